// round 5
// baseline (speedup 1.0000x reference)
#include <cuda_runtime.h>
#include <math.h>

#define NB 4
#define NS 2048
#define ND 512
#define NH 8
#define NDK 64
#define SCL 0.125f
#define NEGBIG (-1e30f)

typedef unsigned long long ull;

// Scratch
__device__ float g_Q[(size_t)NB * NH * NS * NDK];
__device__ float g_K[(size_t)NB * NH * NS * NDK];
__device__ float g_V[(size_t)NB * NH * NS * NDK];
__device__ float g_Ctx[(size_t)NB * NS * ND];
__device__ float g_M[(size_t)NB * NH * NS];
__device__ float g_Z[(size_t)NB * NH * NS];
__device__ float g_madd[(size_t)NB * NS];
__device__ int   g_maskkind;

// ---- packed f32x2 helpers ----
__device__ __forceinline__ ull pk2(float lo, float hi) {
    ull r; asm("mov.b64 %0, {%1, %2};" : "=l"(r) : "f"(lo), "f"(hi)); return r;
}
__device__ __forceinline__ void upk2(ull v, float& lo, float& hi) {
    asm("mov.b64 {%0, %1}, %2;" : "=f"(lo), "=f"(hi) : "l"(v));
}
__device__ __forceinline__ ull ffma2(ull a, ull b, ull c) {
    ull d; asm("fma.rn.f32x2 %0, %1, %2, %3;" : "=l"(d) : "l"(a), "l"(b), "l"(c)); return d;
}
__device__ __forceinline__ ull fmul2(ull a, ull b) {
    ull d; asm("mul.rn.f32x2 %0, %1, %2;" : "=l"(d) : "l"(a), "l"(b)); return d;
}

// swizzled [d][vec] layouts
__device__ __forceinline__ int SW128(int d, int g) {   // row width 128 floats
    return d * 128 + (((g) ^ ((d >> 2) & 7)) << 2);
}
__device__ __forceinline__ int SW64(int d, int g) {    // row width 64 floats
    return d * 64 + (((g) ^ ((d >> 2) & 7)) << 2);
}

// ---------------- mask sniff / convert (validated) ----------------
__global__ void mask_detect(const unsigned char* __restrict__ mraw) {
    __shared__ int s_not01, s_oneOther, s_3fOdd;
    if (threadIdx.x == 0) { s_not01 = 0; s_oneOther = 0; s_3fOdd = 0; }
    __syncthreads();
    int l_not01 = 0, l_oneOther = 0, l_3fOdd = 0;
    for (int i = threadIdx.x; i < NB * NS; i += blockDim.x) {
        const unsigned char v = mraw[i];
        if (v > 1) l_not01++;
        if (v == 1 && (i & 3) != 0) l_oneOther++;
        if (v == 0x3f && (i & 3) == 1) l_3fOdd++;
    }
    atomicAdd(&s_not01, l_not01);
    atomicAdd(&s_oneOther, l_oneOther);
    atomicAdd(&s_3fOdd, l_3fOdd);
    __syncthreads();
    if (threadIdx.x == 0) {
        int kind;
        if (s_not01 > 0)        kind = (s_3fOdd > 0) ? 3 : 2;
        else if (s_oneOther == 0) kind = 1;
        else                    kind = 0;
        g_maskkind = kind;
    }
}

__global__ void mask_convert(const void* __restrict__ mraw) {
    const int i = blockIdx.x * blockDim.x + threadIdx.x;
    if (i >= NB * NS) return;
    const int kind = g_maskkind;
    bool on;
    if (kind == 0)      on = ((const unsigned char*)mraw)[i] != 0;
    else if (kind == 1) on = ((const int*)mraw)[i] != 0;
    else if (kind == 2) on = ((const float*)mraw)[i] != 0.f;
    else                on = ((const unsigned short*)mraw)[i] != 0;
    g_madd[i] = on ? 0.f : -INFINITY;
}

// ---------------------------------------------------------------------------
// Fused QKV projection GEMM: z = blockIdx.z selects (X, W, bias, head-split dst).
// MODE 1 variant (flat) used for the output projection.
// ---------------------------------------------------------------------------
template <int MODE>
__global__ __launch_bounds__(256) void gemm_xwt(const float* __restrict__ X0,
                                                const float* __restrict__ X1,
                                                const float* __restrict__ X2,
                                                const float* __restrict__ W0,
                                                const float* __restrict__ W1,
                                                const float* __restrict__ W2,
                                                const float* __restrict__ b0p,
                                                const float* __restrict__ b1p,
                                                const float* __restrict__ b2p,
                                                float* __restrict__ Y0,
                                                float* __restrict__ Y1,
                                                float* __restrict__ Y2) {
    const int z = blockIdx.z;
    const float* X = (z == 0) ? X0 : (z == 1) ? X1 : X2;
    const float* W = (z == 0) ? W0 : (z == 1) ? W1 : W2;
    const float* bias = (z == 0) ? b0p : (z == 1) ? b1p : b2p;
    float* Y = (z == 0) ? Y0 : (z == 1) ? Y1 : Y2;

    __shared__ float As[16 * 128];
    __shared__ float Bs[16 * 128];
    const int tid = threadIdx.x;
    const int tx = tid & 15, ty = tid >> 4;
    const int m0 = blockIdx.y * 128, n0 = blockIdx.x * 128;
    const int lc = tid & 3, lr = tid >> 2;

    ull acc2[4][8];
#pragma unroll
    for (int rp = 0; rp < 4; rp++)
#pragma unroll
        for (int j = 0; j < 8; j++) acc2[rp][j] = 0ull;

    for (int k0 = 0; k0 < ND; k0 += 16) {
#pragma unroll
        for (int p = 0; p < 2; p++) {
            const int row = lr + 64 * p;
            const int qg = row >> 2, qr = row & 3;
            float4 xa = *(const float4*)&X[(size_t)(m0 + row) * ND + k0 + 4 * lc];
            float4 wb = *(const float4*)&W[(size_t)(n0 + row) * ND + k0 + 4 * lc];
            const int gi = (qg ^ lc) << 2;
            As[(4 * lc + 0) * 128 + gi + qr] = xa.x;
            As[(4 * lc + 1) * 128 + gi + qr] = xa.y;
            As[(4 * lc + 2) * 128 + gi + qr] = xa.z;
            As[(4 * lc + 3) * 128 + gi + qr] = xa.w;
            Bs[(4 * lc + 0) * 128 + gi + qr] = wb.x;
            Bs[(4 * lc + 1) * 128 + gi + qr] = wb.y;
            Bs[(4 * lc + 2) * 128 + gi + qr] = wb.z;
            Bs[(4 * lc + 3) * 128 + gi + qr] = wb.w;
        }
        __syncthreads();
#pragma unroll 8
        for (int kk = 0; kk < 16; kk++) {
            const int sa = SW128(kk, ty), sb = SW128(kk, tx);
            float4 a0 = *(const float4*)&As[sa];
            float4 a1 = *(const float4*)&As[sa + 64];
            float4 b0 = *(const float4*)&Bs[sb];
            float4 b1 = *(const float4*)&Bs[sb + 64];
            ull ap[4] = {pk2(a0.x, a0.y), pk2(a0.z, a0.w),
                         pk2(a1.x, a1.y), pk2(a1.z, a1.w)};
            float bv[8] = {b0.x, b0.y, b0.z, b0.w, b1.x, b1.y, b1.z, b1.w};
#pragma unroll
            for (int j = 0; j < 8; j++) {
                const ull bd = pk2(bv[j], bv[j]);
#pragma unroll
                for (int rp = 0; rp < 4; rp++)
                    acc2[rp][j] = ffma2(ap[rp], bd, acc2[rp][j]);
            }
        }
        __syncthreads();
    }

    float acc[8][8];
#pragma unroll
    for (int rp = 0; rp < 4; rp++)
#pragma unroll
        for (int j = 0; j < 8; j++) upk2(acc2[rp][j], acc[2 * rp][j], acc[2 * rp + 1][j]);

    float4 bA = *(const float4*)&bias[n0 + 4 * tx];
    float4 bB = *(const float4*)&bias[n0 + 64 + 4 * tx];
#pragma unroll
    for (int i = 0; i < 8; i++) {
        const int m = m0 + ((i < 4) ? (4 * ty + i) : (64 + 4 * ty + i - 4));
        float4 vA = make_float4(acc[i][0] + bA.x, acc[i][1] + bA.y,
                                acc[i][2] + bA.z, acc[i][3] + bA.w);
        float4 vB = make_float4(acc[i][4] + bB.x, acc[i][5] + bB.y,
                                acc[i][6] + bB.z, acc[i][7] + bB.w);
        if (MODE == 0) {
            const int b = m >> 11, s = m & (NS - 1);
            const int hA = n0 >> 6, hB = hA + 1;
            *(float4*)&Y[(((size_t)(b * NH + hA)) * NS + s) * NDK + 4 * tx] = vA;
            *(float4*)&Y[(((size_t)(b * NH + hB)) * NS + s) * NDK + 4 * tx] = vB;
        } else {
            *(float4*)&Y[(size_t)m * ND + n0 + 4 * tx] = vA;
            *(float4*)&Y[(size_t)m * ND + n0 + 64 + 4 * tx] = vB;
        }
    }
}

// ---------------------------------------------------------------------------
// Flash attention: 128q x 64k tiles (smem ~102KB -> 2 CTAs/SM).
// ---------------------------------------------------------------------------
__global__ __launch_bounds__(256, 2) void flash_attn(const float* __restrict__ maddg,
                                                     const float* __restrict__ Qg,
                                                     const float* __restrict__ Kg,
                                                     const float* __restrict__ Vg,
                                                     float* __restrict__ Og,
                                                     float* __restrict__ Mg,
                                                     float* __restrict__ Zg) {
    extern __shared__ float sm[];
    float* Qs = sm;                  // 64*128 swizzled [d][q]
    float* Ks = Qs + 64 * 128;       // 64*64 swizzled [d][k]
    float* Vs = Ks + 64 * 64;        // [k][d] 64*68
    float* Ps = Vs + 64 * 68;        // [q][k] 128*68
    float* madd = Ps + 128 * 68;     // 64

    const int tid = threadIdx.x;
    const int tx = tid & 15, ty = tid >> 4;
    const int bh = blockIdx.y;
    const int b = bh >> 3;
    const int h = bh & 7;
    const int q0 = blockIdx.x * 128;
    const float* Q = Qg + (size_t)bh * NS * NDK;
    const float* K = Kg + (size_t)bh * NS * NDK;
    const float* V = Vg + (size_t)bh * NS * NDK;

    const int lc = tid & 15, lr = tid >> 4;
    {   // Q tile -> swizzled transpose [d][128]
#pragma unroll
        for (int p = 0; p < 8; p++) {
            const int row = lr + 16 * p;
            float4 v = *(const float4*)&Q[(size_t)(q0 + row) * NDK + 4 * lc];
            const int gi = ((row >> 2) ^ (lc & 7)) << 2, qr = row & 3;
            Qs[(4 * lc + 0) * 128 + gi + qr] = v.x;
            Qs[(4 * lc + 1) * 128 + gi + qr] = v.y;
            Qs[(4 * lc + 2) * 128 + gi + qr] = v.z;
            Qs[(4 * lc + 3) * 128 + gi + qr] = v.w;
        }
    }

    ull O2[8][2];
#pragma unroll
    for (int i = 0; i < 8; i++) { O2[i][0] = 0ull; O2[i][1] = 0ull; }
    float mI[8], zI[8];
#pragma unroll
    for (int i = 0; i < 8; i++) { mI[i] = -INFINITY; zI[i] = 0.f; }
    int qloc[8], qoff[8];
#pragma unroll
    for (int i = 0; i < 8; i++) {
        qloc[i] = (i < 4) ? (4 * ty + i) : (64 + 4 * ty + i - 4);
        qoff[i] = qloc[i] * 68;
    }
    __syncthreads();

    for (int kt = 0; kt < NS; kt += 64) {
        {   // K (swizzled transpose [d][64]), V (natural [k][68]), mask
#pragma unroll
            for (int p = 0; p < 4; p++) {
                const int row = lr + 16 * p;
                float4 kv = *(const float4*)&K[(size_t)(kt + row) * NDK + 4 * lc];
                float4 vv = *(const float4*)&V[(size_t)(kt + row) * NDK + 4 * lc];
                const int gi = ((row >> 2) ^ (lc & 7)) << 2, qr = row & 3;
                Ks[(4 * lc + 0) * 64 + gi + qr] = kv.x;
                Ks[(4 * lc + 1) * 64 + gi + qr] = kv.y;
                Ks[(4 * lc + 2) * 64 + gi + qr] = kv.z;
                Ks[(4 * lc + 3) * 64 + gi + qr] = kv.w;
                *(float4*)&Vs[row * 68 + 4 * lc] = vv;
            }
            if (tid < 64) madd[tid] = maddg[b * NS + kt + tid];
        }
        __syncthreads();

        // ---- S = Q K^T (128q x 64k, 8x4 micro, packed row-pairs) ----
        ull s2[4][4];
#pragma unroll
        for (int rp = 0; rp < 4; rp++)
#pragma unroll
            for (int j = 0; j < 4; j++) s2[rp][j] = 0ull;
#pragma unroll 8
        for (int dd = 0; dd < 64; dd++) {
            const int sa = SW128(dd, ty);
            float4 a0 = *(const float4*)&Qs[sa];
            float4 a1 = *(const float4*)&Qs[sa + 64];
            float4 b0 = *(const float4*)&Ks[SW64(dd, tx)];
            ull ap[4] = {pk2(a0.x, a0.y), pk2(a0.z, a0.w),
                         pk2(a1.x, a1.y), pk2(a1.z, a1.w)};
            float bv[4] = {b0.x, b0.y, b0.z, b0.w};
#pragma unroll
            for (int j = 0; j < 4; j++) {
                const ull bd = pk2(bv[j], bv[j]);
#pragma unroll
                for (int rp = 0; rp < 4; rp++)
                    s2[rp][j] = ffma2(ap[rp], bd, s2[rp][j]);
            }
        }
        float s[8][4];
#pragma unroll
        for (int rp = 0; rp < 4; rp++)
#pragma unroll
            for (int j = 0; j < 4; j++) upk2(s2[rp][j], s[2 * rp][j], s[2 * rp + 1][j]);

        // ---- online softmax ----
        float mk[4];
        mk[0] = madd[4 * tx + 0]; mk[1] = madd[4 * tx + 1];
        mk[2] = madd[4 * tx + 2]; mk[3] = madd[4 * tx + 3];
#pragma unroll
        for (int i = 0; i < 8; i++) {
            float sc[4];
#pragma unroll
            for (int j = 0; j < 4; j++) sc[j] = s[i][j] * SCL + mk[j];
            float rm = fmaxf(fmaxf(sc[0], sc[1]), fmaxf(sc[2], sc[3]));
#pragma unroll
            for (int off = 8; off > 0; off >>= 1)
                rm = fmaxf(rm, __shfl_xor_sync(0xffffffffu, rm, off));
            const float mn = fmaxf(mI[i], rm);
            const float alpha = (mI[i] <= NEGBIG) ? 0.f : __expf(mI[i] - mn);
            float pv[4], rs = 0.f;
#pragma unroll
            for (int j = 0; j < 4; j++) {
                const float p = (sc[j] <= NEGBIG) ? 0.f : __expf(sc[j] - mn);
                pv[j] = p; rs += p;
            }
#pragma unroll
            for (int off = 8; off > 0; off >>= 1)
                rs += __shfl_xor_sync(0xffffffffu, rs, off);
            zI[i] = zI[i] * alpha + rs;
            mI[i] = mn;
            const ull ad = pk2(alpha, alpha);
            O2[i][0] = fmul2(O2[i][0], ad);
            O2[i][1] = fmul2(O2[i][1], ad);
            *(float4*)&Ps[qoff[i] + 4 * tx] = make_float4(pv[0], pv[1], pv[2], pv[3]);
        }
        __syncthreads();

        // ---- O += P V ----
#pragma unroll 8
        for (int kk = 0; kk < 64; kk++) {
            float4 v4 = *(const float4*)&Vs[kk * 68 + 4 * tx];
            const ull vp0 = pk2(v4.x, v4.y), vp1 = pk2(v4.z, v4.w);
#pragma unroll
            for (int i = 0; i < 8; i++) {
                const float p = Ps[qoff[i] + kk];
                const ull pd = pk2(p, p);
                O2[i][0] = ffma2(pd, vp0, O2[i][0]);
                O2[i][1] = ffma2(pd, vp1, O2[i][1]);
            }
        }
        __syncthreads();
    }

    // epilogue
#pragma unroll
    for (int i = 0; i < 8; i++) {
        const float inv = (zI[i] > 0.f) ? 1.f / zI[i] : 0.f;
        const int qq = q0 + qloc[i];
        float o[4];
        upk2(O2[i][0], o[0], o[1]);
        upk2(O2[i][1], o[2], o[3]);
        float4 o4 = make_float4(o[0] * inv, o[1] * inv, o[2] * inv, o[3] * inv);
        *(float4*)&Og[((size_t)(b * NS + qq)) * ND + h * NDK + 4 * tx] = o4;
        if (tx == 0) {
            Mg[(size_t)bh * NS + qq] = mI[i];
            Zg[(size_t)bh * NS + qq] = zI[i];
        }
    }
}

// ---------------------------------------------------------------------------
// attn.mean over heads: 128q x 64k per block (2 CTAs/SM).
// ---------------------------------------------------------------------------
__global__ __launch_bounds__(256, 2) void attn_mean_k(const float* __restrict__ maddg,
                                                      const float* __restrict__ Qg,
                                                      const float* __restrict__ Kg,
                                                      const float* __restrict__ Mg,
                                                      const float* __restrict__ Zg,
                                                      float* __restrict__ out) {
    extern __shared__ float sm2[];
    float* Qs = sm2;               // 64*128
    float* Ks = Qs + 64 * 128;     // 64*64
    float* madd = Ks + 64 * 64;    // 64

    const int tid = threadIdx.x;
    const int tx = tid & 15, ty = tid >> 4;
    const int b = blockIdx.z;
    const int q0 = blockIdx.y * 128, k0 = blockIdx.x * 64;
    const int lc = tid & 15, lr = tid >> 4;
    if (tid < 64) madd[tid] = maddg[b * NS + k0 + tid];

    int qloc[8];
#pragma unroll
    for (int i = 0; i < 8; i++) qloc[i] = (i < 4) ? (4 * ty + i) : (64 + 4 * ty + i - 4);

    float acc[8][4] = {};
    for (int hh = 0; hh < NH; hh++) {
        __syncthreads();
        const float* Q = Qg + ((size_t)(b * NH + hh)) * NS * NDK;
        const float* K = Kg + ((size_t)(b * NH + hh)) * NS * NDK;
#pragma unroll
        for (int p = 0; p < 8; p++) {
            const int row = lr + 16 * p;
            float4 qv = *(const float4*)&Q[(size_t)(q0 + row) * NDK + 4 * lc];
            const int gi = ((row >> 2) ^ (lc & 7)) << 2, qr = row & 3;
            Qs[(4 * lc + 0) * 128 + gi + qr] = qv.x;
            Qs[(4 * lc + 1) * 128 + gi + qr] = qv.y;
            Qs[(4 * lc + 2) * 128 + gi + qr] = qv.z;
            Qs[(4 * lc + 3) * 128 + gi + qr] = qv.w;
        }
#pragma unroll
        for (int p = 0; p < 4; p++) {
            const int row = lr + 16 * p;
            float4 kv = *(const float4*)&K[(size_t)(k0 + row) * NDK + 4 * lc];
            const int gi = ((row >> 2) ^ (lc & 7)) << 2, qr = row & 3;
            Ks[(4 * lc + 0) * 64 + gi + qr] = kv.x;
            Ks[(4 * lc + 1) * 64 + gi + qr] = kv.y;
            Ks[(4 * lc + 2) * 64 + gi + qr] = kv.z;
            Ks[(4 * lc + 3) * 64 + gi + qr] = kv.w;
        }
        __syncthreads();

        float mrow[8], zinv[8];
#pragma unroll
        for (int i = 0; i < 8; i++) {
            const size_t idx = ((size_t)(b * NH + hh)) * NS + q0 + qloc[i];
            mrow[i] = Mg[idx];
            const float z = Zg[idx];
            zinv[i] = (z > 0.f) ? 1.f / z : 0.f;
        }

        ull s2[4][4];
#pragma unroll
        for (int rp = 0; rp < 4; rp++)
#pragma unroll
            for (int j = 0; j < 4; j++) s2[rp][j] = 0ull;
#pragma unroll 8
        for (int dd = 0; dd < 64; dd++) {
            const int sa = SW128(dd, ty);
            float4 a0 = *(const float4*)&Qs[sa];
            float4 a1 = *(const float4*)&Qs[sa + 64];
            float4 b0 = *(const float4*)&Ks[SW64(dd, tx)];
            ull ap[4] = {pk2(a0.x, a0.y), pk2(a0.z, a0.w),
                         pk2(a1.x, a1.y), pk2(a1.z, a1.w)};
            float bv[4] = {b0.x, b0.y, b0.z, b0.w};
#pragma unroll
            for (int j = 0; j < 4; j++) {
                const ull bd = pk2(bv[j], bv[j]);
#pragma unroll
                for (int rp = 0; rp < 4; rp++)
                    s2[rp][j] = ffma2(ap[rp], bd, s2[rp][j]);
            }
        }
#pragma unroll
        for (int rp = 0; rp < 4; rp++)
#pragma unroll
            for (int j = 0; j < 4; j++) {
                float lo, hi;
                upk2(s2[rp][j], lo, hi);
                const float scLo = lo * SCL + madd[4 * tx + j];
                const float scHi = hi * SCL + madd[4 * tx + j];
                acc[2 * rp][j]     += (scLo <= NEGBIG) ? 0.f : __expf(scLo - mrow[2 * rp]) * zinv[2 * rp];
                acc[2 * rp + 1][j] += (scHi <= NEGBIG) ? 0.f : __expf(scHi - mrow[2 * rp + 1]) * zinv[2 * rp + 1];
            }
    }

#pragma unroll
    for (int i = 0; i < 8; i++) {
        const int qq = q0 + qloc[i];
        float4 oA = make_float4(acc[i][0] * 0.125f, acc[i][1] * 0.125f,
                                acc[i][2] * 0.125f, acc[i][3] * 0.125f);
        *(float4*)&out[((size_t)b * NS + qq) * NS + k0 + 4 * tx] = oA;
    }
}

// ---------------------------------------------------------------------------
extern "C" void kernel_launch(void* const* d_in, const int* in_sizes, int n_in,
                              void* d_out, int out_size) {
    const float* qkv[3] = {0, 0, 0};
    const float* Ws[4] = {0, 0, 0, 0};
    const float* bs[4] = {0, 0, 0, 0};
    const void* maskraw = 0;
    int nqkv = 0, nW = 0, nb = 0;
    for (int i = 0; i < n_in; i++) {
        const int sz = in_sizes[i];
        if (sz == NB * NS * ND) { if (nqkv < 3) qkv[nqkv++] = (const float*)d_in[i]; }
        else if (sz == ND * ND) { if (nW < 4) Ws[nW++] = (const float*)d_in[i]; }
        else if (sz == ND)      { if (nb < 4) bs[nb++] = (const float*)d_in[i]; }
        else if (sz == NB * NS) { maskraw = d_in[i]; }
    }
    float* out = (float*)d_out;

    float *gQ, *gK, *gV, *gC, *gM, *gZ, *gMadd;
    cudaGetSymbolAddress((void**)&gQ, g_Q);
    cudaGetSymbolAddress((void**)&gK, g_K);
    cudaGetSymbolAddress((void**)&gV, g_V);
    cudaGetSymbolAddress((void**)&gC, g_Ctx);
    cudaGetSymbolAddress((void**)&gM, g_M);
    cudaGetSymbolAddress((void**)&gZ, g_Z);
    cudaGetSymbolAddress((void**)&gMadd, g_madd);

    mask_detect<<<1, 256>>>((const unsigned char*)maskraw);
    mask_convert<<<(NB * NS + 255) / 256, 256>>>(maskraw);

    const dim3 blk(256);

    // Fused Q,K,V projections (one launch, 768 CTAs)
    gemm_xwt<0><<<dim3(ND / 128, (NB * NS) / 128, 3), blk>>>(
        qkv[0], qkv[1], qkv[2], Ws[0], Ws[1], Ws[2], bs[0], bs[1], bs[2],
        gQ, gK, gV);

    const size_t FLASH_SMEM =
        (size_t)(64 * 128 + 64 * 64 + 64 * 68 + 128 * 68 + 64) * sizeof(float);
    cudaFuncSetAttribute(flash_attn, cudaFuncAttributeMaxDynamicSharedMemorySize,
                         (int)FLASH_SMEM);
    flash_attn<<<dim3(NS / 128, NB * NH), blk, FLASH_SMEM>>>(gMadd, gQ, gK, gV, gC, gM, gZ);

    // Output projection
    gemm_xwt<1><<<dim3(ND / 128, (NB * NS) / 128, 1), blk>>>(
        gC, gC, gC, Ws[3], Ws[3], Ws[3], bs[3], bs[3], bs[3], out, out, out);

    const size_t MEAN_SMEM = (size_t)(64 * 128 + 64 * 64 + 64) * sizeof(float);
    cudaFuncSetAttribute(attn_mean_k, cudaFuncAttributeMaxDynamicSharedMemorySize,
                         (int)MEAN_SMEM);
    const long long need = (long long)NB * NS * ND + (long long)NB * NS * NS;
    if ((long long)out_size >= need) {
        attn_mean_k<<<dim3(NS / 64, NS / 128, NB), blk, MEAN_SMEM>>>(
            gMadd, gQ, gK, gM, gZ, out + (size_t)NB * NS * ND);
    }
}

// round 6
// speedup vs baseline: 1.7759x; 1.7759x over previous
#include <cuda_runtime.h>
#include <cuda_bf16.h>
#include <math.h>

#define NB 4
#define NS 2048
#define ND 512
#define NH 8
#define NDK 64
#define SCL 0.125f
#define NEGBIG (-1e30f)

typedef unsigned int u32;
typedef __nv_bfloat16 bf16;

// ---------------- scratch (static device allocations) ----------------
__device__ bf16 g_Ah[(size_t)3 * NB * NS * ND];   // split inputs (q,k,v)
__device__ bf16 g_Al[(size_t)3 * NB * NS * ND];
__device__ bf16 g_Wh[(size_t)4 * ND * ND];        // split weights (Wq,Wk,Wv,Wo)
__device__ bf16 g_Wl[(size_t)4 * ND * ND];
__device__ bf16 g_Qh[(size_t)NB * NH * NS * NDK]; // projected, head-split
__device__ bf16 g_Ql[(size_t)NB * NH * NS * NDK];
__device__ bf16 g_Kh[(size_t)NB * NH * NS * NDK];
__device__ bf16 g_Kl[(size_t)NB * NH * NS * NDK];
__device__ bf16 g_Vh[(size_t)NB * NH * NS * NDK];
__device__ bf16 g_Vl[(size_t)NB * NH * NS * NDK];
__device__ bf16 g_Ch[(size_t)NB * NS * ND];       // attention context, split
__device__ bf16 g_Cl[(size_t)NB * NS * ND];
__device__ float g_M[(size_t)NB * NH * NS];
__device__ float g_Z[(size_t)NB * NH * NS];
__device__ float g_madd[(size_t)NB * NS];
__device__ int   g_maskkind;

// ---------------- small helpers ----------------
__device__ __forceinline__ float bfround(float x) {
    return __bfloat162float(__float2bfloat16(x));
}
// pack two f32 -> bf16x2 register; low 16 bits = first arg
__device__ __forceinline__ u32 packbf(float lo_el, float hi_el) {
    u32 r;
    asm("cvt.rn.bf16x2.f32 %0, %1, %2;" : "=r"(r) : "f"(hi_el), "f"(lo_el));
    return r;
}
// D += A*B  (m16n8k16, bf16 in, f32 accum, in-place)
__device__ __forceinline__ void mma_bf16(float d[4], const u32 a[4], u32 b0, u32 b1) {
    asm volatile(
        "mma.sync.aligned.m16n8k16.row.col.f32.bf16.bf16.f32 "
        "{%0,%1,%2,%3}, {%4,%5,%6,%7}, {%8,%9}, {%0,%1,%2,%3};"
        : "+f"(d[0]), "+f"(d[1]), "+f"(d[2]), "+f"(d[3])
        : "r"(a[0]), "r"(a[1]), "r"(a[2]), "r"(a[3]), "r"(b0), "r"(b1));
}

// ---------------- mask sniff / convert (validated R2) ----------------
__global__ void mask_detect(const unsigned char* __restrict__ mraw) {
    __shared__ int s_not01, s_oneOther, s_3fOdd;
    if (threadIdx.x == 0) { s_not01 = 0; s_oneOther = 0; s_3fOdd = 0; }
    __syncthreads();
    int l_not01 = 0, l_oneOther = 0, l_3fOdd = 0;
    for (int i = threadIdx.x; i < NB * NS; i += blockDim.x) {
        const unsigned char v = mraw[i];
        if (v > 1) l_not01++;
        if (v == 1 && (i & 3) != 0) l_oneOther++;
        if (v == 0x3f && (i & 3) == 1) l_3fOdd++;
    }
    atomicAdd(&s_not01, l_not01);
    atomicAdd(&s_oneOther, l_oneOther);
    atomicAdd(&s_3fOdd, l_3fOdd);
    __syncthreads();
    if (threadIdx.x == 0) {
        int kind;
        if (s_not01 > 0)          kind = (s_3fOdd > 0) ? 3 : 2;
        else if (s_oneOther == 0) kind = 1;
        else                      kind = 0;
        g_maskkind = kind;
    }
}

__global__ void mask_convert(const void* __restrict__ mraw) {
    const int i = blockIdx.x * blockDim.x + threadIdx.x;
    if (i >= NB * NS) return;
    const int kind = g_maskkind;
    bool on;
    if (kind == 0)      on = ((const unsigned char*)mraw)[i] != 0;
    else if (kind == 1) on = ((const int*)mraw)[i] != 0;
    else if (kind == 2) on = ((const float*)mraw)[i] != 0.f;
    else                on = ((const unsigned short*)mraw)[i] != 0;
    g_madd[i] = on ? 0.f : -INFINITY;
}

// ---------------- fp32 -> (hi, lo) bf16 split ----------------
__global__ void split_f32(const float* __restrict__ s, bf16* __restrict__ h,
                          bf16* __restrict__ l, int n) {
    const int i = blockIdx.x * blockDim.x + threadIdx.x;
    if (i >= n) return;
    const float x = s[i];
    const bf16 hb = __float2bfloat16(x);
    h[i] = hb;
    l[i] = __float2bfloat16(x - __bfloat162float(hb));
}

// ---------------------------------------------------------------------------
// QKV projections: Y = X @ W^T + b, via split-bf16 mma. Writes head-split
// split-bf16 outputs directly. grid (ND/128, M/128, 3), 256 threads.
// ---------------------------------------------------------------------------
__global__ __launch_bounds__(256) void proj_qkv(const float* __restrict__ b0p,
                                                const float* __restrict__ b1p,
                                                const float* __restrict__ b2p) {
    __shared__ __align__(16) bf16 Xsh[128 * 40], Xsl[128 * 40];
    __shared__ __align__(16) bf16 Wsh[128 * 40], Wsl[128 * 40];

    const int z = blockIdx.z;
    const bf16* Xh = g_Ah + (size_t)z * NB * NS * ND;
    const bf16* Xl = g_Al + (size_t)z * NB * NS * ND;
    const bf16* Wh = g_Wh + (size_t)z * ND * ND;
    const bf16* Wl = g_Wl + (size_t)z * ND * ND;
    const float* bias = (z == 0) ? b0p : (z == 1) ? b1p : b2p;
    bf16* Yh = (z == 0) ? g_Qh : (z == 1) ? g_Kh : g_Vh;
    bf16* Yl = (z == 0) ? g_Ql : (z == 1) ? g_Kl : g_Vl;

    const int tid = threadIdx.x;
    const int w = tid >> 5, lane = tid & 31, g = lane >> 2, t = lane & 3;
    const int m0 = blockIdx.y * 128, n0 = blockIdx.x * 128;
    const int mw = (w >> 1) * 32, nw = (w & 1) * 64;

    float D[2][8][4];
#pragma unroll
    for (int mi = 0; mi < 2; mi++)
#pragma unroll
        for (int nt = 0; nt < 8; nt++)
#pragma unroll
            for (int j = 0; j < 4; j++) D[mi][nt][j] = 0.f;

    const int lrow = tid >> 2, lcol = (tid & 3) * 8;  // 8 bf16 per load

    for (int k0 = 0; k0 < ND; k0 += 32) {
#pragma unroll
        for (int p = 0; p < 2; p++) {
            const int row = lrow + 64 * p;
            *(uint4*)&Xsh[row * 40 + lcol] = *(const uint4*)&Xh[(size_t)(m0 + row) * ND + k0 + lcol];
            *(uint4*)&Xsl[row * 40 + lcol] = *(const uint4*)&Xl[(size_t)(m0 + row) * ND + k0 + lcol];
            *(uint4*)&Wsh[row * 40 + lcol] = *(const uint4*)&Wh[(size_t)(n0 + row) * ND + k0 + lcol];
            *(uint4*)&Wsl[row * 40 + lcol] = *(const uint4*)&Wl[(size_t)(n0 + row) * ND + k0 + lcol];
        }
        __syncthreads();

        const u32* XH = (const u32*)Xsh;
        const u32* XL = (const u32*)Xsl;
        const u32* WH = (const u32*)Wsh;
        const u32* WL = (const u32*)Wsl;
#pragma unroll
        for (int c = 0; c < 2; c++) {
            u32 aH[2][4], aL[2][4];
#pragma unroll
            for (int mi = 0; mi < 2; mi++) {
                const int r0 = (mw + 16 * mi + g) * 20 + 8 * c + t;
                const int r1 = (mw + 16 * mi + g + 8) * 20 + 8 * c + t;
                aH[mi][0] = XH[r0]; aH[mi][1] = XH[r1];
                aH[mi][2] = XH[r0 + 4]; aH[mi][3] = XH[r1 + 4];
                aL[mi][0] = XL[r0]; aL[mi][1] = XL[r1];
                aL[mi][2] = XL[r0 + 4]; aL[mi][3] = XL[r1 + 4];
            }
#pragma unroll
            for (int nt = 0; nt < 8; nt++) {
                const int nb = (nw + 8 * nt + g) * 20 + 8 * c + t;
                const u32 bh0 = WH[nb], bh1 = WH[nb + 4];
                const u32 bl0 = WL[nb], bl1 = WL[nb + 4];
#pragma unroll
                for (int mi = 0; mi < 2; mi++) {
                    mma_bf16(D[mi][nt], aH[mi], bh0, bh1);
                    mma_bf16(D[mi][nt], aH[mi], bl0, bl1);
                    mma_bf16(D[mi][nt], aL[mi], bh0, bh1);
                }
            }
        }
        __syncthreads();
    }

    // epilogue: +bias, split, head-split write
#pragma unroll
    for (int mi = 0; mi < 2; mi++) {
#pragma unroll
        for (int nt = 0; nt < 8; nt++) {
            const int n = n0 + nw + 8 * nt + 2 * t;
            const float bb0 = bias[n], bb1 = bias[n + 1];
            const int h = n >> 6, dk = n & 63;
#pragma unroll
            for (int rr = 0; rr < 2; rr++) {
                const int m = m0 + mw + 16 * mi + g + 8 * rr;
                const float v0 = D[mi][nt][2 * rr + 0] + bb0;
                const float v1 = D[mi][nt][2 * rr + 1] + bb1;
                const int b = m >> 11, s = m & (NS - 1);
                const size_t off = (((size_t)(b * NH + h)) * NS + s) * NDK + dk;
                *(u32*)&Yh[off] = packbf(v0, v1);
                *(u32*)&Yl[off] = packbf(v0 - bfround(v0), v1 - bfround(v1));
            }
        }
    }
}

// ---------------------------------------------------------------------------
// Output projection: out = Ctx @ Wo^T + bo (fp32 out). grid (4, 64).
// ---------------------------------------------------------------------------
__global__ __launch_bounds__(256) void proj_out(const float* __restrict__ bias,
                                                float* __restrict__ out) {
    __shared__ __align__(16) bf16 Xsh[128 * 40], Xsl[128 * 40];
    __shared__ __align__(16) bf16 Wsh[128 * 40], Wsl[128 * 40];

    const bf16* Xh = g_Ch;
    const bf16* Xl = g_Cl;
    const bf16* Wh = g_Wh + (size_t)3 * ND * ND;
    const bf16* Wl = g_Wl + (size_t)3 * ND * ND;

    const int tid = threadIdx.x;
    const int w = tid >> 5, lane = tid & 31, g = lane >> 2, t = lane & 3;
    const int m0 = blockIdx.y * 128, n0 = blockIdx.x * 128;
    const int mw = (w >> 1) * 32, nw = (w & 1) * 64;

    float D[2][8][4];
#pragma unroll
    for (int mi = 0; mi < 2; mi++)
#pragma unroll
        for (int nt = 0; nt < 8; nt++)
#pragma unroll
            for (int j = 0; j < 4; j++) D[mi][nt][j] = 0.f;

    const int lrow = tid >> 2, lcol = (tid & 3) * 8;

    for (int k0 = 0; k0 < ND; k0 += 32) {
#pragma unroll
        for (int p = 0; p < 2; p++) {
            const int row = lrow + 64 * p;
            *(uint4*)&Xsh[row * 40 + lcol] = *(const uint4*)&Xh[(size_t)(m0 + row) * ND + k0 + lcol];
            *(uint4*)&Xsl[row * 40 + lcol] = *(const uint4*)&Xl[(size_t)(m0 + row) * ND + k0 + lcol];
            *(uint4*)&Wsh[row * 40 + lcol] = *(const uint4*)&Wh[(size_t)(n0 + row) * ND + k0 + lcol];
            *(uint4*)&Wsl[row * 40 + lcol] = *(const uint4*)&Wl[(size_t)(n0 + row) * ND + k0 + lcol];
        }
        __syncthreads();

        const u32* XH = (const u32*)Xsh;
        const u32* XL = (const u32*)Xsl;
        const u32* WH = (const u32*)Wsh;
        const u32* WL = (const u32*)Wsl;
#pragma unroll
        for (int c = 0; c < 2; c++) {
            u32 aH[2][4], aL[2][4];
#pragma unroll
            for (int mi = 0; mi < 2; mi++) {
                const int r0 = (mw + 16 * mi + g) * 20 + 8 * c + t;
                const int r1 = (mw + 16 * mi + g + 8) * 20 + 8 * c + t;
                aH[mi][0] = XH[r0]; aH[mi][1] = XH[r1];
                aH[mi][2] = XH[r0 + 4]; aH[mi][3] = XH[r1 + 4];
                aL[mi][0] = XL[r0]; aL[mi][1] = XL[r1];
                aL[mi][2] = XL[r0 + 4]; aL[mi][3] = XL[r1 + 4];
            }
#pragma unroll
            for (int nt = 0; nt < 8; nt++) {
                const int nb = (nw + 8 * nt + g) * 20 + 8 * c + t;
                const u32 bh0 = WH[nb], bh1 = WH[nb + 4];
                const u32 bl0 = WL[nb], bl1 = WL[nb + 4];
#pragma unroll
                for (int mi = 0; mi < 2; mi++) {
                    mma_bf16(D[mi][nt], aH[mi], bh0, bh1);
                    mma_bf16(D[mi][nt], aH[mi], bl0, bl1);
                    mma_bf16(D[mi][nt], aL[mi], bh0, bh1);
                }
            }
        }
        __syncthreads();
    }

#pragma unroll
    for (int mi = 0; mi < 2; mi++) {
#pragma unroll
        for (int nt = 0; nt < 8; nt++) {
            const int n = n0 + nw + 8 * nt + 2 * t;
            const float bb0 = bias[n], bb1 = bias[n + 1];
#pragma unroll
            for (int rr = 0; rr < 2; rr++) {
                const int m = m0 + mw + 16 * mi + g + 8 * rr;
                float2 v = make_float2(D[mi][nt][2 * rr + 0] + bb0,
                                       D[mi][nt][2 * rr + 1] + bb1);
                *(float2*)&out[(size_t)m * ND + n] = v;
            }
        }
    }
}

// ---------------------------------------------------------------------------
// Flash attention: 128q x 64k tiles, warp-owned m16 rows, mma QK^T and PV.
// grid (NS/128, NB*NH), 256 threads.
// ---------------------------------------------------------------------------
__global__ __launch_bounds__(256, 2) void flash_mma() {
    __shared__ __align__(16) bf16 Khs[64 * 72], Kls[64 * 72];
    __shared__ __align__(16) bf16 Vhs[64 * 72], Vls[64 * 72];  // transposed [d][key]
    __shared__ float madds[64];

    const int tid = threadIdx.x;
    const int w = tid >> 5, lane = tid & 31, g = lane >> 2, t = lane & 3;
    const int bh = blockIdx.y;
    const int b = bh >> 3, h = bh & 7;
    const int q0 = blockIdx.x * 128;
    const int qw = q0 + 16 * w;

    const bf16* Qhp = g_Qh + (size_t)bh * NS * NDK;
    const bf16* Qlp = g_Ql + (size_t)bh * NS * NDK;
    const bf16* Khp = g_Kh + (size_t)bh * NS * NDK;
    const bf16* Klp = g_Kl + (size_t)bh * NS * NDK;
    const bf16* Vhp = g_Vh + (size_t)bh * NS * NDK;
    const bf16* Vlp = g_Vl + (size_t)bh * NS * NDK;

    // preload Q fragments (4 k16 chunks over dk=64)
    u32 qH[4][4], qL[4][4];
#pragma unroll
    for (int c = 0; c < 4; c++) {
        const size_t r0 = (size_t)(qw + g) * NDK + 16 * c + 2 * t;
        const size_t r1 = (size_t)(qw + g + 8) * NDK + 16 * c + 2 * t;
        qH[c][0] = *(const u32*)&Qhp[r0]; qH[c][1] = *(const u32*)&Qhp[r1];
        qH[c][2] = *(const u32*)&Qhp[r0 + 8]; qH[c][3] = *(const u32*)&Qhp[r1 + 8];
        qL[c][0] = *(const u32*)&Qlp[r0]; qL[c][1] = *(const u32*)&Qlp[r1];
        qL[c][2] = *(const u32*)&Qlp[r0 + 8]; qL[c][3] = *(const u32*)&Qlp[r1 + 8];
    }

    float O[8][4];
#pragma unroll
    for (int dt = 0; dt < 8; dt++)
#pragma unroll
        for (int j = 0; j < 4; j++) O[dt][j] = 0.f;
    float m0r = -INFINITY, m1r = -INFINITY, z0 = 0.f, z1 = 0.f;

    const int srow = tid >> 3, sseg = tid & 7;  // staging: 32 rows/pass, 16B segs

    for (int kt = 0; kt < NS; kt += 64) {
        // ---- stage K (natural) and V (transposed), mask ----
#pragma unroll
        for (int p = 0; p < 2; p++) {
            const int row = srow + 32 * p;
            const size_t go = (size_t)(kt + row) * NDK + sseg * 8;
            *(uint4*)&Khs[row * 72 + sseg * 8] = *(const uint4*)&Khp[go];
            *(uint4*)&Kls[row * 72 + sseg * 8] = *(const uint4*)&Klp[go];
            uint4 rvh = *(const uint4*)&Vhp[go];
            uint4 rvl = *(const uint4*)&Vlp[go];
            const bf16* th = (const bf16*)&rvh;
            const bf16* tl = (const bf16*)&rvl;
#pragma unroll
            for (int j = 0; j < 8; j++) {
                Vhs[(sseg * 8 + j) * 72 + row] = th[j];
                Vls[(sseg * 8 + j) * 72 + row] = tl[j];
            }
        }
        if (tid < 64) madds[tid] = g_madd[b * NS + kt + tid];
        __syncthreads();

        // ---- S = Q K^T ----
        float S[8][4];
#pragma unroll
        for (int nt = 0; nt < 8; nt++)
#pragma unroll
            for (int j = 0; j < 4; j++) S[nt][j] = 0.f;
        const u32* KH = (const u32*)Khs;
        const u32* KL = (const u32*)Kls;
#pragma unroll
        for (int nt = 0; nt < 8; nt++) {
#pragma unroll
            for (int c = 0; c < 4; c++) {
                const int bi = (8 * nt + g) * 36 + 8 * c + t;
                const u32 bh0 = KH[bi], bh1 = KH[bi + 4];
                const u32 bl0 = KL[bi], bl1 = KL[bi + 4];
                mma_bf16(S[nt], qH[c], bh0, bh1);
                mma_bf16(S[nt], qH[c], bl0, bl1);
                mma_bf16(S[nt], qL[c], bh0, bh1);
            }
        }

        // ---- online softmax (rows g and g+8; reduce over quad t) ----
        float rm0 = -INFINITY, rm1 = -INFINITY;
#pragma unroll
        for (int nt = 0; nt < 8; nt++) {
            const float ma = madds[8 * nt + 2 * t], mb = madds[8 * nt + 2 * t + 1];
            S[nt][0] = S[nt][0] * SCL + ma; S[nt][1] = S[nt][1] * SCL + mb;
            S[nt][2] = S[nt][2] * SCL + ma; S[nt][3] = S[nt][3] * SCL + mb;
            rm0 = fmaxf(rm0, fmaxf(S[nt][0], S[nt][1]));
            rm1 = fmaxf(rm1, fmaxf(S[nt][2], S[nt][3]));
        }
        rm0 = fmaxf(rm0, __shfl_xor_sync(0xffffffffu, rm0, 1));
        rm0 = fmaxf(rm0, __shfl_xor_sync(0xffffffffu, rm0, 2));
        rm1 = fmaxf(rm1, __shfl_xor_sync(0xffffffffu, rm1, 1));
        rm1 = fmaxf(rm1, __shfl_xor_sync(0xffffffffu, rm1, 2));
        const float mn0 = fmaxf(m0r, rm0), mn1 = fmaxf(m1r, rm1);
        const float al0 = (m0r <= NEGBIG) ? 0.f : __expf(m0r - mn0);
        const float al1 = (m1r <= NEGBIG) ? 0.f : __expf(m1r - mn1);
        float rs0 = 0.f, rs1 = 0.f;
#pragma unroll
        for (int nt = 0; nt < 8; nt++) {
            const float p0 = (S[nt][0] <= NEGBIG) ? 0.f : __expf(S[nt][0] - mn0);
            const float p1 = (S[nt][1] <= NEGBIG) ? 0.f : __expf(S[nt][1] - mn0);
            const float p2 = (S[nt][2] <= NEGBIG) ? 0.f : __expf(S[nt][2] - mn1);
            const float p3 = (S[nt][3] <= NEGBIG) ? 0.f : __expf(S[nt][3] - mn1);
            S[nt][0] = p0; S[nt][1] = p1; S[nt][2] = p2; S[nt][3] = p3;
            rs0 += p0 + p1; rs1 += p2 + p3;
        }
        rs0 += __shfl_xor_sync(0xffffffffu, rs0, 1);
        rs0 += __shfl_xor_sync(0xffffffffu, rs0, 2);
        rs1 += __shfl_xor_sync(0xffffffffu, rs1, 1);
        rs1 += __shfl_xor_sync(0xffffffffu, rs1, 2);
        z0 = z0 * al0 + rs0; z1 = z1 * al1 + rs1;
        m0r = mn0; m1r = mn1;
#pragma unroll
        for (int dt = 0; dt < 8; dt++) {
            O[dt][0] *= al0; O[dt][1] *= al0;
            O[dt][2] *= al1; O[dt][3] *= al1;
        }

        // ---- pack P into A-fragments (S n-tiles 2c, 2c+1 -> chunk c) ----
        u32 pH[4][4], pL[4][4];
#pragma unroll
        for (int c = 0; c < 4; c++) {
            const float a0 = S[2 * c][0],     a1 = S[2 * c][1];
            const float a2 = S[2 * c][2],     a3 = S[2 * c][3];
            const float b0 = S[2 * c + 1][0], b1 = S[2 * c + 1][1];
            const float b2 = S[2 * c + 1][2], b3 = S[2 * c + 1][3];
            pH[c][0] = packbf(a0, a1); pH[c][1] = packbf(a2, a3);
            pH[c][2] = packbf(b0, b1); pH[c][3] = packbf(b2, b3);
            pL[c][0] = packbf(a0 - bfround(a0), a1 - bfround(a1));
            pL[c][1] = packbf(a2 - bfround(a2), a3 - bfround(a3));
            pL[c][2] = packbf(b0 - bfround(b0), b1 - bfround(b1));
            pL[c][3] = packbf(b2 - bfround(b2), b3 - bfround(b3));
        }

        // ---- O += P V ----
        const u32* VH = (const u32*)Vhs;
        const u32* VL = (const u32*)Vls;
#pragma unroll
        for (int dt = 0; dt < 8; dt++) {
#pragma unroll
            for (int c = 0; c < 4; c++) {
                const int bi = (8 * dt + g) * 36 + 8 * c + t;
                const u32 vh0 = VH[bi], vh1 = VH[bi + 4];
                const u32 vl0 = VL[bi], vl1 = VL[bi + 4];
                mma_bf16(O[dt], pH[c], vh0, vh1);
                mma_bf16(O[dt], pH[c], vl0, vl1);
                mma_bf16(O[dt], pL[c], vh0, vh1);
            }
        }
        __syncthreads();
    }

    // ---- epilogue: normalize, split-write Ctx, write M/Z ----
    const float inv0 = (z0 > 0.f) ? 1.f / z0 : 0.f;
    const float inv1 = (z1 > 0.f) ? 1.f / z1 : 0.f;
#pragma unroll
    for (int dt = 0; dt < 8; dt++) {
        const int d = 8 * dt + 2 * t;
        const float v0 = O[dt][0] * inv0, v1 = O[dt][1] * inv0;
        const float v2 = O[dt][2] * inv1, v3 = O[dt][3] * inv1;
        const size_t o0 = ((size_t)(b * NS + qw + g)) * ND + h * NDK + d;
        const size_t o1 = ((size_t)(b * NS + qw + g + 8)) * ND + h * NDK + d;
        *(u32*)&g_Ch[o0] = packbf(v0, v1);
        *(u32*)&g_Cl[o0] = packbf(v0 - bfround(v0), v1 - bfround(v1));
        *(u32*)&g_Ch[o1] = packbf(v2, v3);
        *(u32*)&g_Cl[o1] = packbf(v2 - bfround(v2), v3 - bfround(v3));
    }
    if (t == 0) {
        g_M[(size_t)bh * NS + qw + g] = m0r;
        g_M[(size_t)bh * NS + qw + g + 8] = m1r;
        g_Z[(size_t)bh * NS + qw + g] = z0;
        g_Z[(size_t)bh * NS + qw + g + 8] = z1;
    }
}

// ---------------------------------------------------------------------------
// attn.mean over heads: per (b, q-tile 128, k-tile 64), loop 8 heads.
// grid (NS/64, NS/128, NB), 256 threads.
// ---------------------------------------------------------------------------
__global__ __launch_bounds__(256, 2) void mean_mma(float* __restrict__ out) {
    __shared__ __align__(16) bf16 Khs[64 * 72], Kls[64 * 72];
    __shared__ float madds[64];

    const int tid = threadIdx.x;
    const int w = tid >> 5, lane = tid & 31, g = lane >> 2, t = lane & 3;
    const int b = blockIdx.z;
    const int q0 = blockIdx.y * 128, k0 = blockIdx.x * 64;
    const int qw = q0 + 16 * w;
    const int srow = tid >> 3, sseg = tid & 7;

    if (tid < 64) madds[tid] = g_madd[b * NS + k0 + tid];

    float acc[8][4];
#pragma unroll
    for (int nt = 0; nt < 8; nt++)
#pragma unroll
        for (int j = 0; j < 4; j++) acc[nt][j] = 0.f;

    for (int hh = 0; hh < NH; hh++) {
        const size_t bhh = (size_t)(b * NH + hh);
        const bf16* Khp = g_Kh + bhh * NS * NDK;
        const bf16* Klp = g_Kl + bhh * NS * NDK;
        const bf16* Qhp = g_Qh + bhh * NS * NDK;
        const bf16* Qlp = g_Ql + bhh * NS * NDK;

        __syncthreads();
#pragma unroll
        for (int p = 0; p < 2; p++) {
            const int row = srow + 32 * p;
            const size_t go = (size_t)(k0 + row) * NDK + sseg * 8;
            *(uint4*)&Khs[row * 72 + sseg * 8] = *(const uint4*)&Khp[go];
            *(uint4*)&Kls[row * 72 + sseg * 8] = *(const uint4*)&Klp[go];
        }
        __syncthreads();

        // Q fragments for this head (direct gmem)
        u32 qH[4][4], qL[4][4];
#pragma unroll
        for (int c = 0; c < 4; c++) {
            const size_t r0 = (size_t)(qw + g) * NDK + 16 * c + 2 * t;
            const size_t r1 = (size_t)(qw + g + 8) * NDK + 16 * c + 2 * t;
            qH[c][0] = *(const u32*)&Qhp[r0]; qH[c][1] = *(const u32*)&Qhp[r1];
            qH[c][2] = *(const u32*)&Qhp[r0 + 8]; qH[c][3] = *(const u32*)&Qhp[r1 + 8];
            qL[c][0] = *(const u32*)&Qlp[r0]; qL[c][1] = *(const u32*)&Qlp[r1];
            qL[c][2] = *(const u32*)&Qlp[r0 + 8]; qL[c][3] = *(const u32*)&Qlp[r1 + 8];
        }

        float S[8][4];
#pragma unroll
        for (int nt = 0; nt < 8; nt++)
#pragma unroll
            for (int j = 0; j < 4; j++) S[nt][j] = 0.f;
        const u32* KH = (const u32*)Khs;
        const u32* KL = (const u32*)Kls;
#pragma unroll
        for (int nt = 0; nt < 8; nt++) {
#pragma unroll
            for (int c = 0; c < 4; c++) {
                const int bi = (8 * nt + g) * 36 + 8 * c + t;
                const u32 bh0 = KH[bi], bh1 = KH[bi + 4];
                const u32 bl0 = KL[bi], bl1 = KL[bi + 4];
                mma_bf16(S[nt], qH[c], bh0, bh1);
                mma_bf16(S[nt], qH[c], bl0, bl1);
                mma_bf16(S[nt], qL[c], bh0, bh1);
            }
        }

        const float mr0 = g_M[bhh * NS + qw + g];
        const float mr1 = g_M[bhh * NS + qw + g + 8];
        const float zz0 = g_Z[bhh * NS + qw + g];
        const float zz1 = g_Z[bhh * NS + qw + g + 8];
        const float zi0 = (zz0 > 0.f) ? 1.f / zz0 : 0.f;
        const float zi1 = (zz1 > 0.f) ? 1.f / zz1 : 0.f;

#pragma unroll
        for (int nt = 0; nt < 8; nt++) {
            const float ma = madds[8 * nt + 2 * t], mb = madds[8 * nt + 2 * t + 1];
            const float s0 = S[nt][0] * SCL + ma, s1 = S[nt][1] * SCL + mb;
            const float s2 = S[nt][2] * SCL + ma, s3 = S[nt][3] * SCL + mb;
            acc[nt][0] += (s0 <= NEGBIG) ? 0.f : __expf(s0 - mr0) * zi0;
            acc[nt][1] += (s1 <= NEGBIG) ? 0.f : __expf(s1 - mr0) * zi0;
            acc[nt][2] += (s2 <= NEGBIG) ? 0.f : __expf(s2 - mr1) * zi1;
            acc[nt][3] += (s3 <= NEGBIG) ? 0.f : __expf(s3 - mr1) * zi1;
        }
    }

#pragma unroll
    for (int nt = 0; nt < 8; nt++) {
        const int col = k0 + 8 * nt + 2 * t;
        float2 vA = make_float2(acc[nt][0] * 0.125f, acc[nt][1] * 0.125f);
        float2 vB = make_float2(acc[nt][2] * 0.125f, acc[nt][3] * 0.125f);
        *(float2*)&out[((size_t)(b * NS + qw + g)) * NS + col] = vA;
        *(float2*)&out[((size_t)(b * NS + qw + g + 8)) * NS + col] = vB;
    }
}

// ---------------------------------------------------------------------------
extern "C" void kernel_launch(void* const* d_in, const int* in_sizes, int n_in,
                              void* d_out, int out_size) {
    const float* qkv[3] = {0, 0, 0};
    const float* Ws[4] = {0, 0, 0, 0};
    const float* bs[4] = {0, 0, 0, 0};
    const void* maskraw = 0;
    int nqkv = 0, nW = 0, nb = 0;
    for (int i = 0; i < n_in; i++) {
        const int sz = in_sizes[i];
        if (sz == NB * NS * ND) { if (nqkv < 3) qkv[nqkv++] = (const float*)d_in[i]; }
        else if (sz == ND * ND) { if (nW < 4) Ws[nW++] = (const float*)d_in[i]; }
        else if (sz == ND)      { if (nb < 4) bs[nb++] = (const float*)d_in[i]; }
        else if (sz == NB * NS) { maskraw = d_in[i]; }
    }
    float* out = (float*)d_out;

    bf16 *gAh, *gAl, *gWh, *gWl;
    cudaGetSymbolAddress((void**)&gAh, g_Ah);
    cudaGetSymbolAddress((void**)&gAl, g_Al);
    cudaGetSymbolAddress((void**)&gWh, g_Wh);
    cudaGetSymbolAddress((void**)&gWl, g_Wl);

    mask_detect<<<1, 256>>>((const unsigned char*)maskraw);
    mask_convert<<<(NB * NS + 255) / 256, 256>>>(maskraw);

    const int nX = NB * NS * ND;   // 4194304
    const int nWel = ND * ND;      // 262144
    for (int z = 0; z < 3; z++)
        split_f32<<<(nX + 255) / 256, 256>>>(qkv[z], gAh + (size_t)z * nX,
                                             gAl + (size_t)z * nX, nX);
    for (int i = 0; i < 4; i++)
        split_f32<<<(nWel + 255) / 256, 256>>>(Ws[i], gWh + (size_t)i * nWel,
                                               gWl + (size_t)i * nWel, nWel);

    proj_qkv<<<dim3(ND / 128, (NB * NS) / 128, 3), 256>>>(bs[0], bs[1], bs[2]);

    flash_mma<<<dim3(NS / 128, NB * NH), 256>>>();

    proj_out<<<dim3(ND / 128, (NB * NS) / 128), 256>>>(bs[3], out);

    const long long need = (long long)NB * NS * ND + (long long)NB * NS * NS;
    if ((long long)out_size >= need) {
        mean_mma<<<dim3(NS / 64, NS / 128, NB), 256>>>(out + (size_t)NB * NS * ND);
    }
}

// round 8
// speedup vs baseline: 1.8685x; 1.0521x over previous
#include <cuda_runtime.h>
#include <cuda_bf16.h>
#include <math.h>

#define NB 4
#define NS 2048
#define ND 512
#define NH 8
#define NDK 64
#define LOG2E 1.4426950408889634f
#define SCL2 (0.125f * LOG2E)
#define MINIT (-1e30f)

typedef unsigned int u32;
typedef __nv_bfloat16 bf16;

// ---------------- scratch ----------------
__device__ bf16 g_Ah[(size_t)3 * NB * NS * ND];
__device__ bf16 g_Al[(size_t)3 * NB * NS * ND];
__device__ bf16 g_Wh[(size_t)4 * ND * ND];
__device__ bf16 g_Wl[(size_t)4 * ND * ND];
__device__ bf16 g_Qh[(size_t)NB * NH * NS * NDK];
__device__ bf16 g_Ql[(size_t)NB * NH * NS * NDK];
__device__ bf16 g_Kh[(size_t)NB * NH * NS * NDK];
__device__ bf16 g_Kl[(size_t)NB * NH * NS * NDK];
__device__ bf16 g_Vh[(size_t)NB * NH * NS * NDK];
__device__ bf16 g_Vl[(size_t)NB * NH * NS * NDK];
__device__ bf16 g_Ch[(size_t)NB * NS * ND];
__device__ bf16 g_Cl[(size_t)NB * NS * ND];
__device__ float g_M[(size_t)NB * NH * NS];   // row max (log2 domain)
__device__ float g_Z[(size_t)NB * NH * NS];
__device__ float g_madd[(size_t)NB * NS];     // 0 / -inf
__device__ int   g_maskkind;

// ---------------- helpers ----------------
__device__ __forceinline__ float bfround(float x) {
    return __bfloat162float(__float2bfloat16(x));
}
__device__ __forceinline__ u32 packbf(float lo_el, float hi_el) {
    u32 r;
    asm("cvt.rn.bf16x2.f32 %0, %1, %2;" : "=r"(r) : "f"(hi_el), "f"(lo_el));
    return r;
}
__device__ __forceinline__ float ex2f(float x) {
    float y;
    asm("ex2.approx.f32 %0, %1;" : "=f"(y) : "f"(x));
    return y;   // ex2(-inf) = +0, no guards needed
}
__device__ __forceinline__ void mma_bf16(float d[4], const u32 a[4], u32 b0, u32 b1) {
    asm volatile(
        "mma.sync.aligned.m16n8k16.row.col.f32.bf16.bf16.f32 "
        "{%0,%1,%2,%3}, {%4,%5,%6,%7}, {%8,%9}, {%0,%1,%2,%3};"
        : "+f"(d[0]), "+f"(d[1]), "+f"(d[2]), "+f"(d[3])
        : "r"(a[0]), "r"(a[1]), "r"(a[2]), "r"(a[3]), "r"(b0), "r"(b1));
}

// ---------------- mask sniff / convert (validated R2) ----------------
__global__ void mask_detect(const unsigned char* __restrict__ mraw) {
    __shared__ int s_not01, s_oneOther, s_3fOdd;
    if (threadIdx.x == 0) { s_not01 = 0; s_oneOther = 0; s_3fOdd = 0; }
    __syncthreads();
    int l_not01 = 0, l_oneOther = 0, l_3fOdd = 0;
    for (int i = threadIdx.x; i < NB * NS; i += blockDim.x) {
        const unsigned char v = mraw[i];
        if (v > 1) l_not01++;
        if (v == 1 && (i & 3) != 0) l_oneOther++;
        if (v == 0x3f && (i & 3) == 1) l_3fOdd++;
    }
    atomicAdd(&s_not01, l_not01);
    atomicAdd(&s_oneOther, l_oneOther);
    atomicAdd(&s_3fOdd, l_3fOdd);
    __syncthreads();
    if (threadIdx.x == 0) {
        int kind;
        if (s_not01 > 0)          kind = (s_3fOdd > 0) ? 3 : 2;
        else if (s_oneOther == 0) kind = 1;
        else                      kind = 0;
        g_maskkind = kind;
    }
}

__global__ void mask_convert(const void* __restrict__ mraw) {
    const int i = blockIdx.x * blockDim.x + threadIdx.x;
    if (i >= NB * NS) return;
    const int kind = g_maskkind;
    bool on;
    if (kind == 0)      on = ((const unsigned char*)mraw)[i] != 0;
    else if (kind == 1) on = ((const int*)mraw)[i] != 0;
    else if (kind == 2) on = ((const float*)mraw)[i] != 0.f;
    else                on = ((const unsigned short*)mraw)[i] != 0;
    g_madd[i] = on ? 0.f : -INFINITY;
}

// ---------------- fused, vectorized fp32 -> (hi, lo) bf16 splits ----------------
__global__ void split_in(const float* __restrict__ s0, const float* __restrict__ s1,
                         const float* __restrict__ s2) {
    const int z = blockIdx.z;
    const float* s = (z == 0) ? s0 : (z == 1) ? s1 : s2;
    bf16* h = g_Ah + (size_t)z * NB * NS * ND;
    bf16* l = g_Al + (size_t)z * NB * NS * ND;
    const int i = (blockIdx.x * blockDim.x + threadIdx.x) * 4;
    float4 v = *(const float4*)&s[i];
    uint2 hh, ll;
    hh.x = packbf(v.x, v.y);
    hh.y = packbf(v.z, v.w);
    ll.x = packbf(v.x - bfround(v.x), v.y - bfround(v.y));
    ll.y = packbf(v.z - bfround(v.z), v.w - bfround(v.w));
    *(uint2*)&h[i] = hh;
    *(uint2*)&l[i] = ll;
}

__global__ void split_w(const float* __restrict__ s0, const float* __restrict__ s1,
                        const float* __restrict__ s2, const float* __restrict__ s3) {
    const int z = blockIdx.z;
    const float* s = (z == 0) ? s0 : (z == 1) ? s1 : (z == 2) ? s2 : s3;
    bf16* h = g_Wh + (size_t)z * ND * ND;
    bf16* l = g_Wl + (size_t)z * ND * ND;
    const int i = (blockIdx.x * blockDim.x + threadIdx.x) * 4;
    float4 v = *(const float4*)&s[i];
    uint2 hh, ll;
    hh.x = packbf(v.x, v.y);
    hh.y = packbf(v.z, v.w);
    ll.x = packbf(v.x - bfround(v.x), v.y - bfround(v.y));
    ll.y = packbf(v.z - bfround(v.z), v.w - bfround(v.w));
    *(uint2*)&h[i] = hh;
    *(uint2*)&l[i] = ll;
}

// ---------------------------------------------------------------------------
// QKV projections (split-bf16 mma.sync). grid (ND/128, M/128, 3), 256 thr.
// ---------------------------------------------------------------------------
__global__ __launch_bounds__(256) void proj_qkv(const float* __restrict__ b0p,
                                                const float* __restrict__ b1p,
                                                const float* __restrict__ b2p) {
    __shared__ __align__(16) bf16 Xsh[128 * 40], Xsl[128 * 40];
    __shared__ __align__(16) bf16 Wsh[128 * 40], Wsl[128 * 40];

    const int z = blockIdx.z;
    const bf16* Xh = g_Ah + (size_t)z * NB * NS * ND;
    const bf16* Xl = g_Al + (size_t)z * NB * NS * ND;
    const bf16* Wh = g_Wh + (size_t)z * ND * ND;
    const bf16* Wl = g_Wl + (size_t)z * ND * ND;
    const float* bias = (z == 0) ? b0p : (z == 1) ? b1p : b2p;
    bf16* Yh = (z == 0) ? g_Qh : (z == 1) ? g_Kh : g_Vh;
    bf16* Yl = (z == 0) ? g_Ql : (z == 1) ? g_Kl : g_Vl;

    const int tid = threadIdx.x;
    const int w = tid >> 5, lane = tid & 31, g = lane >> 2, t = lane & 3;
    const int m0 = blockIdx.y * 128, n0 = blockIdx.x * 128;
    const int mw = (w >> 1) * 32, nw = (w & 1) * 64;

    float D[2][8][4];
#pragma unroll
    for (int mi = 0; mi < 2; mi++)
#pragma unroll
        for (int nt = 0; nt < 8; nt++)
#pragma unroll
            for (int j = 0; j < 4; j++) D[mi][nt][j] = 0.f;

    const int lrow = tid >> 2, lcol = (tid & 3) * 8;

    for (int k0 = 0; k0 < ND; k0 += 32) {
#pragma unroll
        for (int p = 0; p < 2; p++) {
            const int row = lrow + 64 * p;
            *(uint4*)&Xsh[row * 40 + lcol] = *(const uint4*)&Xh[(size_t)(m0 + row) * ND + k0 + lcol];
            *(uint4*)&Xsl[row * 40 + lcol] = *(const uint4*)&Xl[(size_t)(m0 + row) * ND + k0 + lcol];
            *(uint4*)&Wsh[row * 40 + lcol] = *(const uint4*)&Wh[(size_t)(n0 + row) * ND + k0 + lcol];
            *(uint4*)&Wsl[row * 40 + lcol] = *(const uint4*)&Wl[(size_t)(n0 + row) * ND + k0 + lcol];
        }
        __syncthreads();

        const u32* XH = (const u32*)Xsh;
        const u32* XL = (const u32*)Xsl;
        const u32* WH = (const u32*)Wsh;
        const u32* WL = (const u32*)Wsl;
#pragma unroll
        for (int c = 0; c < 2; c++) {
            u32 aH[2][4], aL[2][4];
#pragma unroll
            for (int mi = 0; mi < 2; mi++) {
                const int r0 = (mw + 16 * mi + g) * 20 + 8 * c + t;
                const int r1 = (mw + 16 * mi + g + 8) * 20 + 8 * c + t;
                aH[mi][0] = XH[r0]; aH[mi][1] = XH[r1];
                aH[mi][2] = XH[r0 + 4]; aH[mi][3] = XH[r1 + 4];
                aL[mi][0] = XL[r0]; aL[mi][1] = XL[r1];
                aL[mi][2] = XL[r0 + 4]; aL[mi][3] = XL[r1 + 4];
            }
#pragma unroll
            for (int nt = 0; nt < 8; nt++) {
                const int nb = (nw + 8 * nt + g) * 20 + 8 * c + t;
                const u32 bh0 = WH[nb], bh1 = WH[nb + 4];
                const u32 bl0 = WL[nb], bl1 = WL[nb + 4];
#pragma unroll
                for (int mi = 0; mi < 2; mi++) {
                    mma_bf16(D[mi][nt], aH[mi], bh0, bh1);
                    mma_bf16(D[mi][nt], aH[mi], bl0, bl1);
                    mma_bf16(D[mi][nt], aL[mi], bh0, bh1);
                }
            }
        }
        __syncthreads();
    }

#pragma unroll
    for (int mi = 0; mi < 2; mi++) {
#pragma unroll
        for (int nt = 0; nt < 8; nt++) {
            const int n = n0 + nw + 8 * nt + 2 * t;
            const float bb0 = bias[n], bb1 = bias[n + 1];
            const int h = n >> 6, dk = n & 63;
#pragma unroll
            for (int rr = 0; rr < 2; rr++) {
                const int m = m0 + mw + 16 * mi + g + 8 * rr;
                const float v0 = D[mi][nt][2 * rr + 0] + bb0;
                const float v1 = D[mi][nt][2 * rr + 1] + bb1;
                const int b = m >> 11, s = m & (NS - 1);
                const size_t off = (((size_t)(b * NH + h)) * NS + s) * NDK + dk;
                *(u32*)&Yh[off] = packbf(v0, v1);
                *(u32*)&Yl[off] = packbf(v0 - bfround(v0), v1 - bfround(v1));
            }
        }
    }
}

// ---------------------------------------------------------------------------
// Output projection
// ---------------------------------------------------------------------------
__global__ __launch_bounds__(256) void proj_out(const float* __restrict__ bias,
                                                float* __restrict__ out) {
    __shared__ __align__(16) bf16 Xsh[128 * 40], Xsl[128 * 40];
    __shared__ __align__(16) bf16 Wsh[128 * 40], Wsl[128 * 40];

    const bf16* Xh = g_Ch;
    const bf16* Xl = g_Cl;
    const bf16* Wh = g_Wh + (size_t)3 * ND * ND;
    const bf16* Wl = g_Wl + (size_t)3 * ND * ND;

    const int tid = threadIdx.x;
    const int w = tid >> 5, lane = tid & 31, g = lane >> 2, t = lane & 3;
    const int m0 = blockIdx.y * 128, n0 = blockIdx.x * 128;
    const int mw = (w >> 1) * 32, nw = (w & 1) * 64;

    float D[2][8][4];
#pragma unroll
    for (int mi = 0; mi < 2; mi++)
#pragma unroll
        for (int nt = 0; nt < 8; nt++)
#pragma unroll
            for (int j = 0; j < 4; j++) D[mi][nt][j] = 0.f;

    const int lrow = tid >> 2, lcol = (tid & 3) * 8;

    for (int k0 = 0; k0 < ND; k0 += 32) {
#pragma unroll
        for (int p = 0; p < 2; p++) {
            const int row = lrow + 64 * p;
            *(uint4*)&Xsh[row * 40 + lcol] = *(const uint4*)&Xh[(size_t)(m0 + row) * ND + k0 + lcol];
            *(uint4*)&Xsl[row * 40 + lcol] = *(const uint4*)&Xl[(size_t)(m0 + row) * ND + k0 + lcol];
            *(uint4*)&Wsh[row * 40 + lcol] = *(const uint4*)&Wh[(size_t)(n0 + row) * ND + k0 + lcol];
            *(uint4*)&Wsl[row * 40 + lcol] = *(const uint4*)&Wl[(size_t)(n0 + row) * ND + k0 + lcol];
        }
        __syncthreads();

        const u32* XH = (const u32*)Xsh;
        const u32* XL = (const u32*)Xsl;
        const u32* WH = (const u32*)Wsh;
        const u32* WL = (const u32*)Wsl;
#pragma unroll
        for (int c = 0; c < 2; c++) {
            u32 aH[2][4], aL[2][4];
#pragma unroll
            for (int mi = 0; mi < 2; mi++) {
                const int r0 = (mw + 16 * mi + g) * 20 + 8 * c + t;
                const int r1 = (mw + 16 * mi + g + 8) * 20 + 8 * c + t;
                aH[mi][0] = XH[r0]; aH[mi][1] = XH[r1];
                aH[mi][2] = XH[r0 + 4]; aH[mi][3] = XH[r1 + 4];
                aL[mi][0] = XL[r0]; aL[mi][1] = XL[r1];
                aL[mi][2] = XL[r0 + 4]; aL[mi][3] = XL[r1 + 4];
            }
#pragma unroll
            for (int nt = 0; nt < 8; nt++) {
                const int nb = (nw + 8 * nt + g) * 20 + 8 * c + t;
                const u32 bh0 = WH[nb], bh1 = WH[nb + 4];
                const u32 bl0 = WL[nb], bl1 = WL[nb + 4];
#pragma unroll
                for (int mi = 0; mi < 2; mi++) {
                    mma_bf16(D[mi][nt], aH[mi], bh0, bh1);
                    mma_bf16(D[mi][nt], aH[mi], bl0, bl1);
                    mma_bf16(D[mi][nt], aL[mi], bh0, bh1);
                }
            }
        }
        __syncthreads();
    }

#pragma unroll
    for (int mi = 0; mi < 2; mi++) {
#pragma unroll
        for (int nt = 0; nt < 8; nt++) {
            const int n = n0 + nw + 8 * nt + 2 * t;
            const float bb0 = bias[n], bb1 = bias[n + 1];
#pragma unroll
            for (int rr = 0; rr < 2; rr++) {
                const int m = m0 + mw + 16 * mi + g + 8 * rr;
                float2 v = make_float2(D[mi][nt][2 * rr + 0] + bb0,
                                       D[mi][nt][2 * rr + 1] + bb1);
                *(float2*)&out[(size_t)m * ND + n] = v;
            }
        }
    }
}

// ---------------------------------------------------------------------------
// Flash attention: 128q x 64k, split-bf16 mma, log2-domain guard-free softmax.
// ---------------------------------------------------------------------------
__global__ __launch_bounds__(256, 2) void flash_mma() {
    __shared__ __align__(16) bf16 Khs[64 * 72], Kls[64 * 72];
    __shared__ __align__(16) bf16 Vhs[64 * 72], Vls[64 * 72];
    __shared__ float madds[64];

    const int tid = threadIdx.x;
    const int w = tid >> 5, lane = tid & 31, g = lane >> 2, t = lane & 3;
    const int bh = blockIdx.y;
    const int b = bh >> 3, h = bh & 7;
    const int q0 = blockIdx.x * 128;
    const int qw = q0 + 16 * w;

    const bf16* Qhp = g_Qh + (size_t)bh * NS * NDK;
    const bf16* Qlp = g_Ql + (size_t)bh * NS * NDK;
    const bf16* Khp = g_Kh + (size_t)bh * NS * NDK;
    const bf16* Klp = g_Kl + (size_t)bh * NS * NDK;
    const bf16* Vhp = g_Vh + (size_t)bh * NS * NDK;
    const bf16* Vlp = g_Vl + (size_t)bh * NS * NDK;

    u32 qH[4][4], qL[4][4];
#pragma unroll
    for (int c = 0; c < 4; c++) {
        const size_t r0 = (size_t)(qw + g) * NDK + 16 * c + 2 * t;
        const size_t r1 = (size_t)(qw + g + 8) * NDK + 16 * c + 2 * t;
        qH[c][0] = *(const u32*)&Qhp[r0]; qH[c][1] = *(const u32*)&Qhp[r1];
        qH[c][2] = *(const u32*)&Qhp[r0 + 8]; qH[c][3] = *(const u32*)&Qhp[r1 + 8];
        qL[c][0] = *(const u32*)&Qlp[r0]; qL[c][1] = *(const u32*)&Qlp[r1];
        qL[c][2] = *(const u32*)&Qlp[r0 + 8]; qL[c][3] = *(const u32*)&Qlp[r1 + 8];
    }

    float O[8][4];
#pragma unroll
    for (int dt = 0; dt < 8; dt++)
#pragma unroll
        for (int j = 0; j < 4; j++) O[dt][j] = 0.f;
    float m0r = MINIT, m1r = MINIT, z0 = 0.f, z1 = 0.f;

    const int srow = tid >> 3, sseg = tid & 7;

    for (int kt = 0; kt < NS; kt += 64) {
#pragma unroll
        for (int p = 0; p < 2; p++) {
            const int row = srow + 32 * p;
            const size_t go = (size_t)(kt + row) * NDK + sseg * 8;
            *(uint4*)&Khs[row * 72 + sseg * 8] = *(const uint4*)&Khp[go];
            *(uint4*)&Kls[row * 72 + sseg * 8] = *(const uint4*)&Klp[go];
            uint4 rvh = *(const uint4*)&Vhp[go];
            uint4 rvl = *(const uint4*)&Vlp[go];
            const bf16* th = (const bf16*)&rvh;
            const bf16* tl = (const bf16*)&rvl;
#pragma unroll
            for (int j = 0; j < 8; j++) {
                Vhs[(sseg * 8 + j) * 72 + row] = th[j];
                Vls[(sseg * 8 + j) * 72 + row] = tl[j];
            }
        }
        if (tid < 64) madds[tid] = g_madd[b * NS + kt + tid];
        __syncthreads();

        float S[8][4];
#pragma unroll
        for (int nt = 0; nt < 8; nt++)
#pragma unroll
            for (int j = 0; j < 4; j++) S[nt][j] = 0.f;
        const u32* KH = (const u32*)Khs;
        const u32* KL = (const u32*)Kls;
#pragma unroll
        for (int nt = 0; nt < 8; nt++) {
#pragma unroll
            for (int c = 0; c < 4; c++) {
                const int bi = (8 * nt + g) * 36 + 8 * c + t;
                const u32 bh0 = KH[bi], bh1 = KH[bi + 4];
                const u32 bl0 = KL[bi], bl1 = KL[bi + 4];
                mma_bf16(S[nt], qH[c], bh0, bh1);
                mma_bf16(S[nt], qH[c], bl0, bl1);
                mma_bf16(S[nt], qL[c], bh0, bh1);
            }
        }

        // ---- log2-domain online softmax, guard-free ----
        float rm0 = MINIT, rm1 = MINIT;
#pragma unroll
        for (int nt = 0; nt < 8; nt++) {
            const float ma = madds[8 * nt + 2 * t], mb = madds[8 * nt + 2 * t + 1];
            S[nt][0] = S[nt][0] * SCL2 + ma; S[nt][1] = S[nt][1] * SCL2 + mb;
            S[nt][2] = S[nt][2] * SCL2 + ma; S[nt][3] = S[nt][3] * SCL2 + mb;
            rm0 = fmaxf(rm0, fmaxf(S[nt][0], S[nt][1]));
            rm1 = fmaxf(rm1, fmaxf(S[nt][2], S[nt][3]));
        }
        rm0 = fmaxf(rm0, __shfl_xor_sync(0xffffffffu, rm0, 1));
        rm0 = fmaxf(rm0, __shfl_xor_sync(0xffffffffu, rm0, 2));
        rm1 = fmaxf(rm1, __shfl_xor_sync(0xffffffffu, rm1, 1));
        rm1 = fmaxf(rm1, __shfl_xor_sync(0xffffffffu, rm1, 2));
        const float mn0 = fmaxf(m0r, rm0), mn1 = fmaxf(m1r, rm1);
        const float al0 = ex2f(m0r - mn0);
        const float al1 = ex2f(m1r - mn1);
        float rs0 = 0.f, rs1 = 0.f;
#pragma unroll
        for (int nt = 0; nt < 8; nt++) {
            const float p0 = ex2f(S[nt][0] - mn0);
            const float p1 = ex2f(S[nt][1] - mn0);
            const float p2 = ex2f(S[nt][2] - mn1);
            const float p3 = ex2f(S[nt][3] - mn1);
            S[nt][0] = p0; S[nt][1] = p1; S[nt][2] = p2; S[nt][3] = p3;
            rs0 += p0 + p1; rs1 += p2 + p3;
        }
        rs0 += __shfl_xor_sync(0xffffffffu, rs0, 1);
        rs0 += __shfl_xor_sync(0xffffffffu, rs0, 2);
        rs1 += __shfl_xor_sync(0xffffffffu, rs1, 1);
        rs1 += __shfl_xor_sync(0xffffffffu, rs1, 2);
        z0 = z0 * al0 + rs0; z1 = z1 * al1 + rs1;
        m0r = mn0; m1r = mn1;
#pragma unroll
        for (int dt = 0; dt < 8; dt++) {
            O[dt][0] *= al0; O[dt][1] *= al0;
            O[dt][2] *= al1; O[dt][3] *= al1;
        }

        u32 pH[4][4], pL[4][4];
#pragma unroll
        for (int c = 0; c < 4; c++) {
            const float a0 = S[2 * c][0],     a1 = S[2 * c][1];
            const float a2 = S[2 * c][2],     a3 = S[2 * c][3];
            const float b0 = S[2 * c + 1][0], b1 = S[2 * c + 1][1];
            const float b2 = S[2 * c + 1][2], b3 = S[2 * c + 1][3];
            pH[c][0] = packbf(a0, a1); pH[c][1] = packbf(a2, a3);
            pH[c][2] = packbf(b0, b1); pH[c][3] = packbf(b2, b3);
            pL[c][0] = packbf(a0 - bfround(a0), a1 - bfround(a1));
            pL[c][1] = packbf(a2 - bfround(a2), a3 - bfround(a3));
            pL[c][2] = packbf(b0 - bfround(b0), b1 - bfround(b1));
            pL[c][3] = packbf(b2 - bfround(b2), b3 - bfround(b3));
        }

        const u32* VH = (const u32*)Vhs;
        const u32* VL = (const u32*)Vls;
#pragma unroll
        for (int dt = 0; dt < 8; dt++) {
#pragma unroll
            for (int c = 0; c < 4; c++) {
                const int bi = (8 * dt + g) * 36 + 8 * c + t;
                const u32 vh0 = VH[bi], vh1 = VH[bi + 4];
                const u32 vl0 = VL[bi], vl1 = VL[bi + 4];
                mma_bf16(O[dt], pH[c], vh0, vh1);
                mma_bf16(O[dt], pH[c], vl0, vl1);
                mma_bf16(O[dt], pL[c], vh0, vh1);
            }
        }
        __syncthreads();
    }

    const float inv0 = (z0 > 0.f) ? 1.f / z0 : 0.f;
    const float inv1 = (z1 > 0.f) ? 1.f / z1 : 0.f;
#pragma unroll
    for (int dt = 0; dt < 8; dt++) {
        const int d = 8 * dt + 2 * t;
        const float v0 = O[dt][0] * inv0, v1 = O[dt][1] * inv0;
        const float v2 = O[dt][2] * inv1, v3 = O[dt][3] * inv1;
        const size_t o0 = ((size_t)(b * NS + qw + g)) * ND + h * NDK + d;
        const size_t o1 = ((size_t)(b * NS + qw + g + 8)) * ND + h * NDK + d;
        *(u32*)&g_Ch[o0] = packbf(v0, v1);
        *(u32*)&g_Cl[o0] = packbf(v0 - bfround(v0), v1 - bfround(v1));
        *(u32*)&g_Ch[o1] = packbf(v2, v3);
        *(u32*)&g_Cl[o1] = packbf(v2 - bfround(v2), v3 - bfround(v3));
    }
    if (t == 0) {
        g_M[(size_t)bh * NS + qw + g] = m0r;
        g_M[(size_t)bh * NS + qw + g + 8] = m1r;
        g_Z[(size_t)bh * NS + qw + g] = z0;
        g_Z[(size_t)bh * NS + qw + g + 8] = z1;
    }
}

// ---------------------------------------------------------------------------
// attn.mean over heads (log2 domain, guard-free)
// ---------------------------------------------------------------------------
__global__ __launch_bounds__(256, 2) void mean_mma(float* __restrict__ out) {
    __shared__ __align__(16) bf16 Khs[64 * 72], Kls[64 * 72];
    __shared__ float madds[64];

    const int tid = threadIdx.x;
    const int w = tid >> 5, lane = tid & 31, g = lane >> 2, t = lane & 3;
    const int b = blockIdx.z;
    const int q0 = blockIdx.y * 128, k0 = blockIdx.x * 64;
    const int qw = q0 + 16 * w;
    const int srow = tid >> 3, sseg = tid & 7;

    if (tid < 64) madds[tid] = g_madd[b * NS + k0 + tid];

    float acc[8][4];
#pragma unroll
    for (int nt = 0; nt < 8; nt++)
#pragma unroll
        for (int j = 0; j < 4; j++) acc[nt][j] = 0.f;

    for (int hh = 0; hh < NH; hh++) {
        const size_t bhh = (size_t)(b * NH + hh);
        const bf16* Khp = g_Kh + bhh * NS * NDK;
        const bf16* Klp = g_Kl + bhh * NS * NDK;
        const bf16* Qhp = g_Qh + bhh * NS * NDK;
        const bf16* Qlp = g_Ql + bhh * NS * NDK;

        __syncthreads();
#pragma unroll
        for (int p = 0; p < 2; p++) {
            const int row = srow + 32 * p;
            const size_t go = (size_t)(k0 + row) * NDK + sseg * 8;
            *(uint4*)&Khs[row * 72 + sseg * 8] = *(const uint4*)&Khp[go];
            *(uint4*)&Kls[row * 72 + sseg * 8] = *(const uint4*)&Klp[go];
        }
        __syncthreads();

        u32 qH[4][4], qL[4][4];
#pragma unroll
        for (int c = 0; c < 4; c++) {
            const size_t r0 = (size_t)(qw + g) * NDK + 16 * c + 2 * t;
            const size_t r1 = (size_t)(qw + g + 8) * NDK + 16 * c + 2 * t;
            qH[c][0] = *(const u32*)&Qhp[r0]; qH[c][1] = *(const u32*)&Qhp[r1];
            qH[c][2] = *(const u32*)&Qhp[r0 + 8]; qH[c][3] = *(const u32*)&Qhp[r1 + 8];
            qL[c][0] = *(const u32*)&Qlp[r0]; qL[c][1] = *(const u32*)&Qlp[r1];
            qL[c][2] = *(const u32*)&Qlp[r0 + 8]; qL[c][3] = *(const u32*)&Qlp[r1 + 8];
        }

        float S[8][4];
#pragma unroll
        for (int nt = 0; nt < 8; nt++)
#pragma unroll
            for (int j = 0; j < 4; j++) S[nt][j] = 0.f;
        const u32* KH = (const u32*)Khs;
        const u32* KL = (const u32*)Kls;
#pragma unroll
        for (int nt = 0; nt < 8; nt++) {
#pragma unroll
            for (int c = 0; c < 4; c++) {
                const int bi = (8 * nt + g) * 36 + 8 * c + t;
                const u32 bh0 = KH[bi], bh1 = KH[bi + 4];
                const u32 bl0 = KL[bi], bl1 = KL[bi + 4];
                mma_bf16(S[nt], qH[c], bh0, bh1);
                mma_bf16(S[nt], qH[c], bl0, bl1);
                mma_bf16(S[nt], qL[c], bh0, bh1);
            }
        }

        const float mr0 = g_M[bhh * NS + qw + g];
        const float mr1 = g_M[bhh * NS + qw + g + 8];
        const float zz0 = g_Z[bhh * NS + qw + g];
        const float zz1 = g_Z[bhh * NS + qw + g + 8];
        const float zi0 = (zz0 > 0.f) ? 1.f / zz0 : 0.f;
        const float zi1 = (zz1 > 0.f) ? 1.f / zz1 : 0.f;

#pragma unroll
        for (int nt = 0; nt < 8; nt++) {
            const float ma = madds[8 * nt + 2 * t], mb = madds[8 * nt + 2 * t + 1];
            const float s0 = S[nt][0] * SCL2 + ma, s1 = S[nt][1] * SCL2 + mb;
            const float s2 = S[nt][2] * SCL2 + ma, s3 = S[nt][3] * SCL2 + mb;
            acc[nt][0] += ex2f(s0 - mr0) * zi0;
            acc[nt][1] += ex2f(s1 - mr0) * zi0;
            acc[nt][2] += ex2f(s2 - mr1) * zi1;
            acc[nt][3] += ex2f(s3 - mr1) * zi1;
        }
    }

#pragma unroll
    for (int nt = 0; nt < 8; nt++) {
        const int col = k0 + 8 * nt + 2 * t;
        float2 vA = make_float2(acc[nt][0] * 0.125f, acc[nt][1] * 0.125f);
        float2 vB = make_float2(acc[nt][2] * 0.125f, acc[nt][3] * 0.125f);
        *(float2*)&out[((size_t)(b * NS + qw + g)) * NS + col] = vA;
        *(float2*)&out[((size_t)(b * NS + qw + g + 8)) * NS + col] = vB;
    }
}

// ---------------------------------------------------------------------------
extern "C" void kernel_launch(void* const* d_in, const int* in_sizes, int n_in,
                              void* d_out, int out_size) {
    const float* qkv[3] = {0, 0, 0};
    const float* Ws[4] = {0, 0, 0, 0};
    const float* bs[4] = {0, 0, 0, 0};
    const void* maskraw = 0;
    int nqkv = 0, nW = 0, nb = 0;
    for (int i = 0; i < n_in; i++) {
        const int sz = in_sizes[i];
        if (sz == NB * NS * ND) { if (nqkv < 3) qkv[nqkv++] = (const float*)d_in[i]; }
        else if (sz == ND * ND) { if (nW < 4) Ws[nW++] = (const float*)d_in[i]; }
        else if (sz == ND)      { if (nb < 4) bs[nb++] = (const float*)d_in[i]; }
        else if (sz == NB * NS) { maskraw = d_in[i]; }
    }
    float* out = (float*)d_out;

    // launch order matters: ncu profiles launch #5 -> flash_mma
    mask_detect<<<1, 256>>>((const unsigned char*)maskraw);                    // 0
    mask_convert<<<(NB * NS + 255) / 256, 256>>>(maskraw);                     // 1

    const int nX = NB * NS * ND;
    const int nWel = ND * ND;
    split_in<<<dim3(nX / 4 / 256, 1, 3), 256>>>(qkv[0], qkv[1], qkv[2]);       // 2
    split_w<<<dim3(nWel / 4 / 256, 1, 4), 256>>>(Ws[0], Ws[1], Ws[2], Ws[3]);  // 3

    proj_qkv<<<dim3(ND / 128, (NB * NS) / 128, 3), 256>>>(bs[0], bs[1], bs[2]); // 4

    flash_mma<<<dim3(NS / 128, NB * NH), 256>>>();                             // 5 <- profiled

    proj_out<<<dim3(ND / 128, (NB * NS) / 128), 256>>>(bs[3], out);            // 6

    const long long need = (long long)NB * NS * ND + (long long)NB * NS * NS;
    if ((long long)out_size >= need) {
        mean_mma<<<dim3(NS / 64, NS / 128, NB), 256>>>(out + (size_t)NB * NS * ND); // 7
    }
}

// round 9
// speedup vs baseline: 2.1325x; 1.1413x over previous
#include <cuda_runtime.h>
#include <cuda_bf16.h>
#include <math.h>

#define NB 4
#define NS 2048
#define ND 512
#define NH 8
#define NDK 64
#define LOG2E 1.4426950408889634f
#define SCL2 (0.125f * LOG2E)
#define MINIT (-1e30f)

typedef unsigned int u32;
typedef __nv_bfloat16 bf16;

// ---------------- scratch ----------------
__device__ bf16 g_Ah[(size_t)3 * NB * NS * ND];
__device__ bf16 g_Al[(size_t)3 * NB * NS * ND];
__device__ bf16 g_Wh[(size_t)4 * ND * ND];
__device__ bf16 g_Wl[(size_t)4 * ND * ND];
__device__ bf16 g_Qh[(size_t)NB * NH * NS * NDK];
__device__ bf16 g_Ql[(size_t)NB * NH * NS * NDK];
__device__ bf16 g_Kh[(size_t)NB * NH * NS * NDK];
__device__ bf16 g_Kl[(size_t)NB * NH * NS * NDK];
__device__ bf16 g_Vh[(size_t)NB * NH * NS * NDK];
__device__ bf16 g_Vl[(size_t)NB * NH * NS * NDK];
__device__ bf16 g_Ch[(size_t)NB * NS * ND];
__device__ bf16 g_Cl[(size_t)NB * NS * ND];
__device__ float g_M[(size_t)NB * NH * NS];   // row max (log2 domain)
__device__ float g_Z[(size_t)NB * NH * NS];
__device__ float g_madd[(size_t)NB * NS];     // 0 / -inf
__device__ int   g_maskkind;
// scaled scores (log2 domain, mask applied): [b][q][h][k]  (537 MB)
__device__ float g_S[(size_t)NB * NS * NH * NS];

// ---------------- helpers ----------------
__device__ __forceinline__ float bfround(float x) {
    return __bfloat162float(__float2bfloat16(x));
}
__device__ __forceinline__ u32 packbf(float lo_el, float hi_el) {
    u32 r;
    asm("cvt.rn.bf16x2.f32 %0, %1, %2;" : "=r"(r) : "f"(hi_el), "f"(lo_el));
    return r;
}
__device__ __forceinline__ float ex2f(float x) {
    float y;
    asm("ex2.approx.f32 %0, %1;" : "=f"(y) : "f"(x));
    return y;   // ex2(-inf) = +0
}
__device__ __forceinline__ void mma_bf16(float d[4], const u32 a[4], u32 b0, u32 b1) {
    asm volatile(
        "mma.sync.aligned.m16n8k16.row.col.f32.bf16.bf16.f32 "
        "{%0,%1,%2,%3}, {%4,%5,%6,%7}, {%8,%9}, {%0,%1,%2,%3};"
        : "+f"(d[0]), "+f"(d[1]), "+f"(d[2]), "+f"(d[3])
        : "r"(a[0]), "r"(a[1]), "r"(a[2]), "r"(a[3]), "r"(b0), "r"(b1));
}

// ---------------- mask sniff / convert (validated R2) ----------------
__global__ void mask_detect(const unsigned char* __restrict__ mraw) {
    __shared__ int s_not01, s_oneOther, s_3fOdd;
    if (threadIdx.x == 0) { s_not01 = 0; s_oneOther = 0; s_3fOdd = 0; }
    __syncthreads();
    int l_not01 = 0, l_oneOther = 0, l_3fOdd = 0;
    for (int i = threadIdx.x; i < NB * NS; i += blockDim.x) {
        const unsigned char v = mraw[i];
        if (v > 1) l_not01++;
        if (v == 1 && (i & 3) != 0) l_oneOther++;
        if (v == 0x3f && (i & 3) == 1) l_3fOdd++;
    }
    atomicAdd(&s_not01, l_not01);
    atomicAdd(&s_oneOther, l_oneOther);
    atomicAdd(&s_3fOdd, l_3fOdd);
    __syncthreads();
    if (threadIdx.x == 0) {
        int kind;
        if (s_not01 > 0)          kind = (s_3fOdd > 0) ? 3 : 2;
        else if (s_oneOther == 0) kind = 1;
        else                      kind = 0;
        g_maskkind = kind;
    }
}

__global__ void mask_convert(const void* __restrict__ mraw) {
    const int i = blockIdx.x * blockDim.x + threadIdx.x;
    if (i >= NB * NS) return;
    const int kind = g_maskkind;
    bool on;
    if (kind == 0)      on = ((const unsigned char*)mraw)[i] != 0;
    else if (kind == 1) on = ((const int*)mraw)[i] != 0;
    else if (kind == 2) on = ((const float*)mraw)[i] != 0.f;
    else                on = ((const unsigned short*)mraw)[i] != 0;
    g_madd[i] = on ? 0.f : -INFINITY;
}

// ---------------- fused, vectorized fp32 -> (hi, lo) bf16 splits ----------------
__global__ void split_in(const float* __restrict__ s0, const float* __restrict__ s1,
                         const float* __restrict__ s2) {
    const int z = blockIdx.z;
    const float* s = (z == 0) ? s0 : (z == 1) ? s1 : s2;
    bf16* h = g_Ah + (size_t)z * NB * NS * ND;
    bf16* l = g_Al + (size_t)z * NB * NS * ND;
    const int i = (blockIdx.x * blockDim.x + threadIdx.x) * 4;
    float4 v = *(const float4*)&s[i];
    uint2 hh, ll;
    hh.x = packbf(v.x, v.y);
    hh.y = packbf(v.z, v.w);
    ll.x = packbf(v.x - bfround(v.x), v.y - bfround(v.y));
    ll.y = packbf(v.z - bfround(v.z), v.w - bfround(v.w));
    *(uint2*)&h[i] = hh;
    *(uint2*)&l[i] = ll;
}

__global__ void split_w(const float* __restrict__ s0, const float* __restrict__ s1,
                        const float* __restrict__ s2, const float* __restrict__ s3) {
    const int z = blockIdx.z;
    const float* s = (z == 0) ? s0 : (z == 1) ? s1 : (z == 2) ? s2 : s3;
    bf16* h = g_Wh + (size_t)z * ND * ND;
    bf16* l = g_Wl + (size_t)z * ND * ND;
    const int i = (blockIdx.x * blockDim.x + threadIdx.x) * 4;
    float4 v = *(const float4*)&s[i];
    uint2 hh, ll;
    hh.x = packbf(v.x, v.y);
    hh.y = packbf(v.z, v.w);
    ll.x = packbf(v.x - bfround(v.x), v.y - bfround(v.y));
    ll.y = packbf(v.z - bfround(v.z), v.w - bfround(v.w));
    *(uint2*)&h[i] = hh;
    *(uint2*)&l[i] = ll;
}

// ---------------------------------------------------------------------------
// QKV projections (split-bf16 mma.sync). grid (ND/128, M/128, 3), 256 thr.
// ---------------------------------------------------------------------------
__global__ __launch_bounds__(256) void proj_qkv(const float* __restrict__ b0p,
                                                const float* __restrict__ b1p,
                                                const float* __restrict__ b2p) {
    __shared__ __align__(16) bf16 Xsh[128 * 40], Xsl[128 * 40];
    __shared__ __align__(16) bf16 Wsh[128 * 40], Wsl[128 * 40];

    const int z = blockIdx.z;
    const bf16* Xh = g_Ah + (size_t)z * NB * NS * ND;
    const bf16* Xl = g_Al + (size_t)z * NB * NS * ND;
    const bf16* Wh = g_Wh + (size_t)z * ND * ND;
    const bf16* Wl = g_Wl + (size_t)z * ND * ND;
    const float* bias = (z == 0) ? b0p : (z == 1) ? b1p : b2p;
    bf16* Yh = (z == 0) ? g_Qh : (z == 1) ? g_Kh : g_Vh;
    bf16* Yl = (z == 0) ? g_Ql : (z == 1) ? g_Kl : g_Vl;

    const int tid = threadIdx.x;
    const int w = tid >> 5, lane = tid & 31, g = lane >> 2, t = lane & 3;
    const int m0 = blockIdx.y * 128, n0 = blockIdx.x * 128;
    const int mw = (w >> 1) * 32, nw = (w & 1) * 64;

    float D[2][8][4];
#pragma unroll
    for (int mi = 0; mi < 2; mi++)
#pragma unroll
        for (int nt = 0; nt < 8; nt++)
#pragma unroll
            for (int j = 0; j < 4; j++) D[mi][nt][j] = 0.f;

    const int lrow = tid >> 2, lcol = (tid & 3) * 8;

    for (int k0 = 0; k0 < ND; k0 += 32) {
#pragma unroll
        for (int p = 0; p < 2; p++) {
            const int row = lrow + 64 * p;
            *(uint4*)&Xsh[row * 40 + lcol] = *(const uint4*)&Xh[(size_t)(m0 + row) * ND + k0 + lcol];
            *(uint4*)&Xsl[row * 40 + lcol] = *(const uint4*)&Xl[(size_t)(m0 + row) * ND + k0 + lcol];
            *(uint4*)&Wsh[row * 40 + lcol] = *(const uint4*)&Wh[(size_t)(n0 + row) * ND + k0 + lcol];
            *(uint4*)&Wsl[row * 40 + lcol] = *(const uint4*)&Wl[(size_t)(n0 + row) * ND + k0 + lcol];
        }
        __syncthreads();

        const u32* XH = (const u32*)Xsh;
        const u32* XL = (const u32*)Xsl;
        const u32* WH = (const u32*)Wsh;
        const u32* WL = (const u32*)Wsl;
#pragma unroll
        for (int c = 0; c < 2; c++) {
            u32 aH[2][4], aL[2][4];
#pragma unroll
            for (int mi = 0; mi < 2; mi++) {
                const int r0 = (mw + 16 * mi + g) * 20 + 8 * c + t;
                const int r1 = (mw + 16 * mi + g + 8) * 20 + 8 * c + t;
                aH[mi][0] = XH[r0]; aH[mi][1] = XH[r1];
                aH[mi][2] = XH[r0 + 4]; aH[mi][3] = XH[r1 + 4];
                aL[mi][0] = XL[r0]; aL[mi][1] = XL[r1];
                aL[mi][2] = XL[r0 + 4]; aL[mi][3] = XL[r1 + 4];
            }
#pragma unroll
            for (int nt = 0; nt < 8; nt++) {
                const int nb = (nw + 8 * nt + g) * 20 + 8 * c + t;
                const u32 bh0 = WH[nb], bh1 = WH[nb + 4];
                const u32 bl0 = WL[nb], bl1 = WL[nb + 4];
#pragma unroll
                for (int mi = 0; mi < 2; mi++) {
                    mma_bf16(D[mi][nt], aH[mi], bh0, bh1);
                    mma_bf16(D[mi][nt], aH[mi], bl0, bl1);
                    mma_bf16(D[mi][nt], aL[mi], bh0, bh1);
                }
            }
        }
        __syncthreads();
    }

#pragma unroll
    for (int mi = 0; mi < 2; mi++) {
#pragma unroll
        for (int nt = 0; nt < 8; nt++) {
            const int n = n0 + nw + 8 * nt + 2 * t;
            const float bb0 = bias[n], bb1 = bias[n + 1];
            const int h = n >> 6, dk = n & 63;
#pragma unroll
            for (int rr = 0; rr < 2; rr++) {
                const int m = m0 + mw + 16 * mi + g + 8 * rr;
                const float v0 = D[mi][nt][2 * rr + 0] + bb0;
                const float v1 = D[mi][nt][2 * rr + 1] + bb1;
                const int b = m >> 11, s = m & (NS - 1);
                const size_t off = (((size_t)(b * NH + h)) * NS + s) * NDK + dk;
                *(u32*)&Yh[off] = packbf(v0, v1);
                *(u32*)&Yl[off] = packbf(v0 - bfround(v0), v1 - bfround(v1));
            }
        }
    }
}

// ---------------------------------------------------------------------------
// Output projection
// ---------------------------------------------------------------------------
__global__ __launch_bounds__(256) void proj_out(const float* __restrict__ bias,
                                                float* __restrict__ out) {
    __shared__ __align__(16) bf16 Xsh[128 * 40], Xsl[128 * 40];
    __shared__ __align__(16) bf16 Wsh[128 * 40], Wsl[128 * 40];

    const bf16* Xh = g_Ch;
    const bf16* Xl = g_Cl;
    const bf16* Wh = g_Wh + (size_t)3 * ND * ND;
    const bf16* Wl = g_Wl + (size_t)3 * ND * ND;

    const int tid = threadIdx.x;
    const int w = tid >> 5, lane = tid & 31, g = lane >> 2, t = lane & 3;
    const int m0 = blockIdx.y * 128, n0 = blockIdx.x * 128;
    const int mw = (w >> 1) * 32, nw = (w & 1) * 64;

    float D[2][8][4];
#pragma unroll
    for (int mi = 0; mi < 2; mi++)
#pragma unroll
        for (int nt = 0; nt < 8; nt++)
#pragma unroll
            for (int j = 0; j < 4; j++) D[mi][nt][j] = 0.f;

    const int lrow = tid >> 2, lcol = (tid & 3) * 8;

    for (int k0 = 0; k0 < ND; k0 += 32) {
#pragma unroll
        for (int p = 0; p < 2; p++) {
            const int row = lrow + 64 * p;
            *(uint4*)&Xsh[row * 40 + lcol] = *(const uint4*)&Xh[(size_t)(m0 + row) * ND + k0 + lcol];
            *(uint4*)&Xsl[row * 40 + lcol] = *(const uint4*)&Xl[(size_t)(m0 + row) * ND + k0 + lcol];
            *(uint4*)&Wsh[row * 40 + lcol] = *(const uint4*)&Wh[(size_t)(n0 + row) * ND + k0 + lcol];
            *(uint4*)&Wsl[row * 40 + lcol] = *(const uint4*)&Wl[(size_t)(n0 + row) * ND + k0 + lcol];
        }
        __syncthreads();

        const u32* XH = (const u32*)Xsh;
        const u32* XL = (const u32*)Xsl;
        const u32* WH = (const u32*)Wsh;
        const u32* WL = (const u32*)Wsl;
#pragma unroll
        for (int c = 0; c < 2; c++) {
            u32 aH[2][4], aL[2][4];
#pragma unroll
            for (int mi = 0; mi < 2; mi++) {
                const int r0 = (mw + 16 * mi + g) * 20 + 8 * c + t;
                const int r1 = (mw + 16 * mi + g + 8) * 20 + 8 * c + t;
                aH[mi][0] = XH[r0]; aH[mi][1] = XH[r1];
                aH[mi][2] = XH[r0 + 4]; aH[mi][3] = XH[r1 + 4];
                aL[mi][0] = XL[r0]; aL[mi][1] = XL[r1];
                aL[mi][2] = XL[r0 + 4]; aL[mi][3] = XL[r1 + 4];
            }
#pragma unroll
            for (int nt = 0; nt < 8; nt++) {
                const int nb = (nw + 8 * nt + g) * 20 + 8 * c + t;
                const u32 bh0 = WH[nb], bh1 = WH[nb + 4];
                const u32 bl0 = WL[nb], bl1 = WL[nb + 4];
#pragma unroll
                for (int mi = 0; mi < 2; mi++) {
                    mma_bf16(D[mi][nt], aH[mi], bh0, bh1);
                    mma_bf16(D[mi][nt], aH[mi], bl0, bl1);
                    mma_bf16(D[mi][nt], aL[mi], bh0, bh1);
                }
            }
        }
        __syncthreads();
    }

#pragma unroll
    for (int mi = 0; mi < 2; mi++) {
#pragma unroll
        for (int nt = 0; nt < 8; nt++) {
            const int n = n0 + nw + 8 * nt + 2 * t;
            const float bb0 = bias[n], bb1 = bias[n + 1];
#pragma unroll
            for (int rr = 0; rr < 2; rr++) {
                const int m = m0 + mw + 16 * mi + g + 8 * rr;
                float2 v = make_float2(D[mi][nt][2 * rr + 0] + bb0,
                                       D[mi][nt][2 * rr + 1] + bb1);
                *(float2*)&out[(size_t)m * ND + n] = v;
            }
        }
    }
}

// ---------------------------------------------------------------------------
// Flash attention: 128q x 64k, split-bf16 mma, log2-domain guard-free softmax,
// AND stores scaled scores to g_S[b][q][h][k] for the mean kernel.
// ---------------------------------------------------------------------------
__global__ __launch_bounds__(256, 2) void flash_mma() {
    __shared__ __align__(16) bf16 Khs[64 * 72], Kls[64 * 72];
    __shared__ __align__(16) bf16 Vhs[64 * 72], Vls[64 * 72];
    __shared__ float madds[64];

    const int tid = threadIdx.x;
    const int w = tid >> 5, lane = tid & 31, g = lane >> 2, t = lane & 3;
    const int bh = blockIdx.y;
    const int b = bh >> 3, h = bh & 7;
    const int q0 = blockIdx.x * 128;
    const int qw = q0 + 16 * w;

    const bf16* Qhp = g_Qh + (size_t)bh * NS * NDK;
    const bf16* Qlp = g_Ql + (size_t)bh * NS * NDK;
    const bf16* Khp = g_Kh + (size_t)bh * NS * NDK;
    const bf16* Klp = g_Kl + (size_t)bh * NS * NDK;
    const bf16* Vhp = g_Vh + (size_t)bh * NS * NDK;
    const bf16* Vlp = g_Vl + (size_t)bh * NS * NDK;

    // S row bases (written every tile)
    float* Srow0 = g_S + ((size_t)(b * NS + qw + g) * NH + h) * NS;
    float* Srow1 = g_S + ((size_t)(b * NS + qw + g + 8) * NH + h) * NS;

    u32 qH[4][4], qL[4][4];
#pragma unroll
    for (int c = 0; c < 4; c++) {
        const size_t r0 = (size_t)(qw + g) * NDK + 16 * c + 2 * t;
        const size_t r1 = (size_t)(qw + g + 8) * NDK + 16 * c + 2 * t;
        qH[c][0] = *(const u32*)&Qhp[r0]; qH[c][1] = *(const u32*)&Qhp[r1];
        qH[c][2] = *(const u32*)&Qhp[r0 + 8]; qH[c][3] = *(const u32*)&Qhp[r1 + 8];
        qL[c][0] = *(const u32*)&Qlp[r0]; qL[c][1] = *(const u32*)&Qlp[r1];
        qL[c][2] = *(const u32*)&Qlp[r0 + 8]; qL[c][3] = *(const u32*)&Qlp[r1 + 8];
    }

    float O[8][4];
#pragma unroll
    for (int dt = 0; dt < 8; dt++)
#pragma unroll
        for (int j = 0; j < 4; j++) O[dt][j] = 0.f;
    float m0r = MINIT, m1r = MINIT, z0 = 0.f, z1 = 0.f;

    const int srow = tid >> 3, sseg = tid & 7;

    for (int kt = 0; kt < NS; kt += 64) {
#pragma unroll
        for (int p = 0; p < 2; p++) {
            const int row = srow + 32 * p;
            const size_t go = (size_t)(kt + row) * NDK + sseg * 8;
            *(uint4*)&Khs[row * 72 + sseg * 8] = *(const uint4*)&Khp[go];
            *(uint4*)&Kls[row * 72 + sseg * 8] = *(const uint4*)&Klp[go];
            uint4 rvh = *(const uint4*)&Vhp[go];
            uint4 rvl = *(const uint4*)&Vlp[go];
            const bf16* th = (const bf16*)&rvh;
            const bf16* tl = (const bf16*)&rvl;
#pragma unroll
            for (int j = 0; j < 8; j++) {
                Vhs[(sseg * 8 + j) * 72 + row] = th[j];
                Vls[(sseg * 8 + j) * 72 + row] = tl[j];
            }
        }
        if (tid < 64) madds[tid] = g_madd[b * NS + kt + tid];
        __syncthreads();

        float S[8][4];
#pragma unroll
        for (int nt = 0; nt < 8; nt++)
#pragma unroll
            for (int j = 0; j < 4; j++) S[nt][j] = 0.f;
        const u32* KH = (const u32*)Khs;
        const u32* KL = (const u32*)Kls;
#pragma unroll
        for (int nt = 0; nt < 8; nt++) {
#pragma unroll
            for (int c = 0; c < 4; c++) {
                const int bi = (8 * nt + g) * 36 + 8 * c + t;
                const u32 bh0 = KH[bi], bh1 = KH[bi + 4];
                const u32 bl0 = KL[bi], bl1 = KL[bi + 4];
                mma_bf16(S[nt], qH[c], bh0, bh1);
                mma_bf16(S[nt], qH[c], bl0, bl1);
                mma_bf16(S[nt], qL[c], bh0, bh1);
            }
        }

        // ---- scale + mask, store scores, log2-domain online softmax ----
        float rm0 = MINIT, rm1 = MINIT;
#pragma unroll
        for (int nt = 0; nt < 8; nt++) {
            const float ma = madds[8 * nt + 2 * t], mb = madds[8 * nt + 2 * t + 1];
            S[nt][0] = S[nt][0] * SCL2 + ma; S[nt][1] = S[nt][1] * SCL2 + mb;
            S[nt][2] = S[nt][2] * SCL2 + ma; S[nt][3] = S[nt][3] * SCL2 + mb;
            const int col = kt + 8 * nt + 2 * t;
            *(float2*)&Srow0[col] = make_float2(S[nt][0], S[nt][1]);
            *(float2*)&Srow1[col] = make_float2(S[nt][2], S[nt][3]);
            rm0 = fmaxf(rm0, fmaxf(S[nt][0], S[nt][1]));
            rm1 = fmaxf(rm1, fmaxf(S[nt][2], S[nt][3]));
        }
        rm0 = fmaxf(rm0, __shfl_xor_sync(0xffffffffu, rm0, 1));
        rm0 = fmaxf(rm0, __shfl_xor_sync(0xffffffffu, rm0, 2));
        rm1 = fmaxf(rm1, __shfl_xor_sync(0xffffffffu, rm1, 1));
        rm1 = fmaxf(rm1, __shfl_xor_sync(0xffffffffu, rm1, 2));
        const float mn0 = fmaxf(m0r, rm0), mn1 = fmaxf(m1r, rm1);
        const float al0 = ex2f(m0r - mn0);
        const float al1 = ex2f(m1r - mn1);
        float rs0 = 0.f, rs1 = 0.f;
#pragma unroll
        for (int nt = 0; nt < 8; nt++) {
            const float p0 = ex2f(S[nt][0] - mn0);
            const float p1 = ex2f(S[nt][1] - mn0);
            const float p2 = ex2f(S[nt][2] - mn1);
            const float p3 = ex2f(S[nt][3] - mn1);
            S[nt][0] = p0; S[nt][1] = p1; S[nt][2] = p2; S[nt][3] = p3;
            rs0 += p0 + p1; rs1 += p2 + p3;
        }
        rs0 += __shfl_xor_sync(0xffffffffu, rs0, 1);
        rs0 += __shfl_xor_sync(0xffffffffu, rs0, 2);
        rs1 += __shfl_xor_sync(0xffffffffu, rs1, 1);
        rs1 += __shfl_xor_sync(0xffffffffu, rs1, 2);
        z0 = z0 * al0 + rs0; z1 = z1 * al1 + rs1;
        m0r = mn0; m1r = mn1;
#pragma unroll
        for (int dt = 0; dt < 8; dt++) {
            O[dt][0] *= al0; O[dt][1] *= al0;
            O[dt][2] *= al1; O[dt][3] *= al1;
        }

        u32 pH[4][4], pL[4][4];
#pragma unroll
        for (int c = 0; c < 4; c++) {
            const float a0 = S[2 * c][0],     a1 = S[2 * c][1];
            const float a2 = S[2 * c][2],     a3 = S[2 * c][3];
            const float b0 = S[2 * c + 1][0], b1 = S[2 * c + 1][1];
            const float b2 = S[2 * c + 1][2], b3 = S[2 * c + 1][3];
            pH[c][0] = packbf(a0, a1); pH[c][1] = packbf(a2, a3);
            pH[c][2] = packbf(b0, b1); pH[c][3] = packbf(b2, b3);
            pL[c][0] = packbf(a0 - bfround(a0), a1 - bfround(a1));
            pL[c][1] = packbf(a2 - bfround(a2), a3 - bfround(a3));
            pL[c][2] = packbf(b0 - bfround(b0), b1 - bfround(b1));
            pL[c][3] = packbf(b2 - bfround(b2), b3 - bfround(b3));
        }

        const u32* VH = (const u32*)Vhs;
        const u32* VL = (const u32*)Vls;
#pragma unroll
        for (int dt = 0; dt < 8; dt++) {
#pragma unroll
            for (int c = 0; c < 4; c++) {
                const int bi = (8 * dt + g) * 36 + 8 * c + t;
                const u32 vh0 = VH[bi], vh1 = VH[bi + 4];
                const u32 vl0 = VL[bi], vl1 = VL[bi + 4];
                mma_bf16(O[dt], pH[c], vh0, vh1);
                mma_bf16(O[dt], pH[c], vl0, vl1);
                mma_bf16(O[dt], pL[c], vh0, vh1);
            }
        }
        __syncthreads();
    }

    const float inv0 = (z0 > 0.f) ? 1.f / z0 : 0.f;
    const float inv1 = (z1 > 0.f) ? 1.f / z1 : 0.f;
#pragma unroll
    for (int dt = 0; dt < 8; dt++) {
        const int d = 8 * dt + 2 * t;
        const float v0 = O[dt][0] * inv0, v1 = O[dt][1] * inv0;
        const float v2 = O[dt][2] * inv1, v3 = O[dt][3] * inv1;
        const size_t o0 = ((size_t)(b * NS + qw + g)) * ND + h * NDK + d;
        const size_t o1 = ((size_t)(b * NS + qw + g + 8)) * ND + h * NDK + d;
        *(u32*)&g_Ch[o0] = packbf(v0, v1);
        *(u32*)&g_Cl[o0] = packbf(v0 - bfround(v0), v1 - bfround(v1));
        *(u32*)&g_Ch[o1] = packbf(v2, v3);
        *(u32*)&g_Cl[o1] = packbf(v2 - bfround(v2), v3 - bfround(v3));
    }
    if (t == 0) {
        g_M[(size_t)bh * NS + qw + g] = m0r;
        g_M[(size_t)bh * NS + qw + g + 8] = m1r;
        g_Z[(size_t)bh * NS + qw + g] = z0;
        g_Z[(size_t)bh * NS + qw + g + 8] = z1;
    }
}

// ---------------------------------------------------------------------------
// attn.mean: pure elementwise from stored scores. Memory-bound.
// grid (NS/1024, NS, NB), 256 threads, 4 k per thread.
// ---------------------------------------------------------------------------
__global__ __launch_bounds__(256) void mean_ew(float* __restrict__ out) {
    const int b = blockIdx.z;
    const int q = blockIdx.y;
    const int k = (blockIdx.x * blockDim.x + threadIdx.x) * 4;

    const float* Sbase = g_S + ((size_t)(b * NS + q) * NH) * NS + k;
    float4 acc = make_float4(0.f, 0.f, 0.f, 0.f);
#pragma unroll
    for (int h = 0; h < NH; h++) {
        const size_t mzidx = ((size_t)(b * NH + h)) * NS + q;
        const float m = g_M[mzidx];
        const float z = g_Z[mzidx];
        const float zi = (z > 0.f) ? 1.f / z : 0.f;
        float4 s = *(const float4*)&Sbase[(size_t)h * NS];
        acc.x += ex2f(s.x - m) * zi;
        acc.y += ex2f(s.y - m) * zi;
        acc.z += ex2f(s.z - m) * zi;
        acc.w += ex2f(s.w - m) * zi;
    }
    acc.x *= 0.125f; acc.y *= 0.125f; acc.z *= 0.125f; acc.w *= 0.125f;
    *(float4*)&out[((size_t)(b * NS + q)) * NS + k] = acc;
}

// ---------------------------------------------------------------------------
extern "C" void kernel_launch(void* const* d_in, const int* in_sizes, int n_in,
                              void* d_out, int out_size) {
    const float* qkv[3] = {0, 0, 0};
    const float* Ws[4] = {0, 0, 0, 0};
    const float* bs[4] = {0, 0, 0, 0};
    const void* maskraw = 0;
    int nqkv = 0, nW = 0, nb = 0;
    for (int i = 0; i < n_in; i++) {
        const int sz = in_sizes[i];
        if (sz == NB * NS * ND) { if (nqkv < 3) qkv[nqkv++] = (const float*)d_in[i]; }
        else if (sz == ND * ND) { if (nW < 4) Ws[nW++] = (const float*)d_in[i]; }
        else if (sz == ND)      { if (nb < 4) bs[nb++] = (const float*)d_in[i]; }
        else if (sz == NB * NS) { maskraw = d_in[i]; }
    }
    float* out = (float*)d_out;

    mask_detect<<<1, 256>>>((const unsigned char*)maskraw);                    // 0
    mask_convert<<<(NB * NS + 255) / 256, 256>>>(maskraw);                     // 1

    const int nX = NB * NS * ND;
    const int nWel = ND * ND;
    split_in<<<dim3(nX / 4 / 256, 1, 3), 256>>>(qkv[0], qkv[1], qkv[2]);       // 2
    split_w<<<dim3(nWel / 4 / 256, 1, 4), 256>>>(Ws[0], Ws[1], Ws[2], Ws[3]);  // 3

    proj_qkv<<<dim3(ND / 128, (NB * NS) / 128, 3), 256>>>(bs[0], bs[1], bs[2]); // 4

    flash_mma<<<dim3(NS / 128, NB * NH), 256>>>();                             // 5 <- profiled

    proj_out<<<dim3(ND / 128, (NB * NS) / 128), 256>>>(bs[3], out);            // 6

    const long long need = (long long)NB * NS * ND + (long long)NB * NS * NS;
    if ((long long)out_size >= need) {
        mean_ew<<<dim3(NS / 1024, NS, NB), 256>>>(out + (size_t)NB * NS * ND); // 7
    }
}

// round 10
// speedup vs baseline: 2.1518x; 1.0091x over previous
#include <cuda_runtime.h>
#include <cuda_bf16.h>
#include <math.h>

#define NB 4
#define NS 2048
#define ND 512
#define NH 8
#define NDK 64
#define LOG2E 1.4426950408889634f
#define SCL2 (0.125f * LOG2E)
#define MINIT (-1e30f)
#define NTILE (NS / 64)

typedef unsigned int u32;
typedef __nv_bfloat16 bf16;

// ---------------- scratch ----------------
__device__ bf16 g_Ah[(size_t)3 * NB * NS * ND];
__device__ bf16 g_Al[(size_t)3 * NB * NS * ND];
__device__ bf16 g_Wh[(size_t)4 * ND * ND];
__device__ bf16 g_Wl[(size_t)4 * ND * ND];
__device__ bf16 g_Qh[(size_t)NB * NH * NS * NDK];
__device__ bf16 g_Ql[(size_t)NB * NH * NS * NDK];
__device__ bf16 g_Kh[(size_t)NB * NH * NS * NDK];
__device__ bf16 g_Kl[(size_t)NB * NH * NS * NDK];
__device__ bf16 g_Vh[(size_t)NB * NH * NS * NDK];
__device__ bf16 g_Vl[(size_t)NB * NH * NS * NDK];
__device__ bf16 g_Ch[(size_t)NB * NS * ND];
__device__ bf16 g_Cl[(size_t)NB * NS * ND];
__device__ float g_M[(size_t)NB * NH * NS];    // final row max (log2 domain)
__device__ float g_Z[(size_t)NB * NH * NS];    // 1/Z (0 for fully-masked)
__device__ float g_Mt[(size_t)NB * NH * NTILE * NS]; // running max at each tile
__device__ float g_madd[(size_t)NB * NS];      // 0 / -inf
__device__ int   g_maskkind;
// tile-local probabilities ex2(s - mn_tile): [b][q][h][k]  (537 MB)
__device__ float g_S[(size_t)NB * NS * NH * NS];

// ---------------- helpers ----------------
__device__ __forceinline__ float bfround(float x) {
    return __bfloat162float(__float2bfloat16(x));
}
__device__ __forceinline__ u32 packbf(float lo_el, float hi_el) {
    u32 r;
    asm("cvt.rn.bf16x2.f32 %0, %1, %2;" : "=r"(r) : "f"(hi_el), "f"(lo_el));
    return r;
}
__device__ __forceinline__ float ex2f(float x) {
    float y;
    asm("ex2.approx.f32 %0, %1;" : "=f"(y) : "f"(x));
    return y;   // ex2(-inf) = +0
}
__device__ __forceinline__ void mma_bf16(float d[4], const u32 a[4], u32 b0, u32 b1) {
    asm volatile(
        "mma.sync.aligned.m16n8k16.row.col.f32.bf16.bf16.f32 "
        "{%0,%1,%2,%3}, {%4,%5,%6,%7}, {%8,%9}, {%0,%1,%2,%3};"
        : "+f"(d[0]), "+f"(d[1]), "+f"(d[2]), "+f"(d[3])
        : "r"(a[0]), "r"(a[1]), "r"(a[2]), "r"(a[3]), "r"(b0), "r"(b1));
}

// ---------------- mask sniff / convert (validated R2) ----------------
__global__ void mask_detect(const unsigned char* __restrict__ mraw) {
    __shared__ int s_not01, s_oneOther, s_3fOdd;
    if (threadIdx.x == 0) { s_not01 = 0; s_oneOther = 0; s_3fOdd = 0; }
    __syncthreads();
    int l_not01 = 0, l_oneOther = 0, l_3fOdd = 0;
    for (int i = threadIdx.x; i < NB * NS; i += blockDim.x) {
        const unsigned char v = mraw[i];
        if (v > 1) l_not01++;
        if (v == 1 && (i & 3) != 0) l_oneOther++;
        if (v == 0x3f && (i & 3) == 1) l_3fOdd++;
    }
    atomicAdd(&s_not01, l_not01);
    atomicAdd(&s_oneOther, l_oneOther);
    atomicAdd(&s_3fOdd, l_3fOdd);
    __syncthreads();
    if (threadIdx.x == 0) {
        int kind;
        if (s_not01 > 0)          kind = (s_3fOdd > 0) ? 3 : 2;
        else if (s_oneOther == 0) kind = 1;
        else                      kind = 0;
        g_maskkind = kind;
    }
}

__global__ void mask_convert(const void* __restrict__ mraw) {
    const int i = blockIdx.x * blockDim.x + threadIdx.x;
    if (i >= NB * NS) return;
    const int kind = g_maskkind;
    bool on;
    if (kind == 0)      on = ((const unsigned char*)mraw)[i] != 0;
    else if (kind == 1) on = ((const int*)mraw)[i] != 0;
    else if (kind == 2) on = ((const float*)mraw)[i] != 0.f;
    else                on = ((const unsigned short*)mraw)[i] != 0;
    g_madd[i] = on ? 0.f : -INFINITY;
}

// ---------------- fused, vectorized fp32 -> (hi, lo) bf16 splits ----------------
__global__ void split_in(const float* __restrict__ s0, const float* __restrict__ s1,
                         const float* __restrict__ s2) {
    const int z = blockIdx.z;
    const float* s = (z == 0) ? s0 : (z == 1) ? s1 : s2;
    bf16* h = g_Ah + (size_t)z * NB * NS * ND;
    bf16* l = g_Al + (size_t)z * NB * NS * ND;
    const int i = (blockIdx.x * blockDim.x + threadIdx.x) * 4;
    float4 v = *(const float4*)&s[i];
    uint2 hh, ll;
    hh.x = packbf(v.x, v.y);
    hh.y = packbf(v.z, v.w);
    ll.x = packbf(v.x - bfround(v.x), v.y - bfround(v.y));
    ll.y = packbf(v.z - bfround(v.z), v.w - bfround(v.w));
    *(uint2*)&h[i] = hh;
    *(uint2*)&l[i] = ll;
}

__global__ void split_w(const float* __restrict__ s0, const float* __restrict__ s1,
                        const float* __restrict__ s2, const float* __restrict__ s3) {
    const int z = blockIdx.z;
    const float* s = (z == 0) ? s0 : (z == 1) ? s1 : (z == 2) ? s2 : s3;
    bf16* h = g_Wh + (size_t)z * ND * ND;
    bf16* l = g_Wl + (size_t)z * ND * ND;
    const int i = (blockIdx.x * blockDim.x + threadIdx.x) * 4;
    float4 v = *(const float4*)&s[i];
    uint2 hh, ll;
    hh.x = packbf(v.x, v.y);
    hh.y = packbf(v.z, v.w);
    ll.x = packbf(v.x - bfround(v.x), v.y - bfround(v.y));
    ll.y = packbf(v.z - bfround(v.z), v.w - bfround(v.w));
    *(uint2*)&h[i] = hh;
    *(uint2*)&l[i] = ll;
}

// ---------------------------------------------------------------------------
// QKV projections (split-bf16 mma.sync). grid (ND/128, M/128, 3), 256 thr.
// ---------------------------------------------------------------------------
__global__ __launch_bounds__(256) void proj_qkv(const float* __restrict__ b0p,
                                                const float* __restrict__ b1p,
                                                const float* __restrict__ b2p) {
    __shared__ __align__(16) bf16 Xsh[128 * 40], Xsl[128 * 40];
    __shared__ __align__(16) bf16 Wsh[128 * 40], Wsl[128 * 40];

    const int z = blockIdx.z;
    const bf16* Xh = g_Ah + (size_t)z * NB * NS * ND;
    const bf16* Xl = g_Al + (size_t)z * NB * NS * ND;
    const bf16* Wh = g_Wh + (size_t)z * ND * ND;
    const bf16* Wl = g_Wl + (size_t)z * ND * ND;
    const float* bias = (z == 0) ? b0p : (z == 1) ? b1p : b2p;
    bf16* Yh = (z == 0) ? g_Qh : (z == 1) ? g_Kh : g_Vh;
    bf16* Yl = (z == 0) ? g_Ql : (z == 1) ? g_Kl : g_Vl;

    const int tid = threadIdx.x;
    const int w = tid >> 5, lane = tid & 31, g = lane >> 2, t = lane & 3;
    const int m0 = blockIdx.y * 128, n0 = blockIdx.x * 128;
    const int mw = (w >> 1) * 32, nw = (w & 1) * 64;

    float D[2][8][4];
#pragma unroll
    for (int mi = 0; mi < 2; mi++)
#pragma unroll
        for (int nt = 0; nt < 8; nt++)
#pragma unroll
            for (int j = 0; j < 4; j++) D[mi][nt][j] = 0.f;

    const int lrow = tid >> 2, lcol = (tid & 3) * 8;

    for (int k0 = 0; k0 < ND; k0 += 32) {
#pragma unroll
        for (int p = 0; p < 2; p++) {
            const int row = lrow + 64 * p;
            *(uint4*)&Xsh[row * 40 + lcol] = *(const uint4*)&Xh[(size_t)(m0 + row) * ND + k0 + lcol];
            *(uint4*)&Xsl[row * 40 + lcol] = *(const uint4*)&Xl[(size_t)(m0 + row) * ND + k0 + lcol];
            *(uint4*)&Wsh[row * 40 + lcol] = *(const uint4*)&Wh[(size_t)(n0 + row) * ND + k0 + lcol];
            *(uint4*)&Wsl[row * 40 + lcol] = *(const uint4*)&Wl[(size_t)(n0 + row) * ND + k0 + lcol];
        }
        __syncthreads();

        const u32* XH = (const u32*)Xsh;
        const u32* XL = (const u32*)Xsl;
        const u32* WH = (const u32*)Wsh;
        const u32* WL = (const u32*)Wsl;
#pragma unroll
        for (int c = 0; c < 2; c++) {
            u32 aH[2][4], aL[2][4];
#pragma unroll
            for (int mi = 0; mi < 2; mi++) {
                const int r0 = (mw + 16 * mi + g) * 20 + 8 * c + t;
                const int r1 = (mw + 16 * mi + g + 8) * 20 + 8 * c + t;
                aH[mi][0] = XH[r0]; aH[mi][1] = XH[r1];
                aH[mi][2] = XH[r0 + 4]; aH[mi][3] = XH[r1 + 4];
                aL[mi][0] = XL[r0]; aL[mi][1] = XL[r1];
                aL[mi][2] = XL[r0 + 4]; aL[mi][3] = XL[r1 + 4];
            }
#pragma unroll
            for (int nt = 0; nt < 8; nt++) {
                const int nb = (nw + 8 * nt + g) * 20 + 8 * c + t;
                const u32 bh0 = WH[nb], bh1 = WH[nb + 4];
                const u32 bl0 = WL[nb], bl1 = WL[nb + 4];
#pragma unroll
                for (int mi = 0; mi < 2; mi++) {
                    mma_bf16(D[mi][nt], aH[mi], bh0, bh1);
                    mma_bf16(D[mi][nt], aH[mi], bl0, bl1);
                    mma_bf16(D[mi][nt], aL[mi], bh0, bh1);
                }
            }
        }
        __syncthreads();
    }

#pragma unroll
    for (int mi = 0; mi < 2; mi++) {
#pragma unroll
        for (int nt = 0; nt < 8; nt++) {
            const int n = n0 + nw + 8 * nt + 2 * t;
            const float bb0 = bias[n], bb1 = bias[n + 1];
            const int h = n >> 6, dk = n & 63;
#pragma unroll
            for (int rr = 0; rr < 2; rr++) {
                const int m = m0 + mw + 16 * mi + g + 8 * rr;
                const float v0 = D[mi][nt][2 * rr + 0] + bb0;
                const float v1 = D[mi][nt][2 * rr + 1] + bb1;
                const int b = m >> 11, s = m & (NS - 1);
                const size_t off = (((size_t)(b * NH + h)) * NS + s) * NDK + dk;
                *(u32*)&Yh[off] = packbf(v0, v1);
                *(u32*)&Yl[off] = packbf(v0 - bfround(v0), v1 - bfround(v1));
            }
        }
    }
}

// ---------------------------------------------------------------------------
// Output projection
// ---------------------------------------------------------------------------
__global__ __launch_bounds__(256) void proj_out(const float* __restrict__ bias,
                                                float* __restrict__ out) {
    __shared__ __align__(16) bf16 Xsh[128 * 40], Xsl[128 * 40];
    __shared__ __align__(16) bf16 Wsh[128 * 40], Wsl[128 * 40];

    const bf16* Xh = g_Ch;
    const bf16* Xl = g_Cl;
    const bf16* Wh = g_Wh + (size_t)3 * ND * ND;
    const bf16* Wl = g_Wl + (size_t)3 * ND * ND;

    const int tid = threadIdx.x;
    const int w = tid >> 5, lane = tid & 31, g = lane >> 2, t = lane & 3;
    const int m0 = blockIdx.y * 128, n0 = blockIdx.x * 128;
    const int mw = (w >> 1) * 32, nw = (w & 1) * 64;

    float D[2][8][4];
#pragma unroll
    for (int mi = 0; mi < 2; mi++)
#pragma unroll
        for (int nt = 0; nt < 8; nt++)
#pragma unroll
            for (int j = 0; j < 4; j++) D[mi][nt][j] = 0.f;

    const int lrow = tid >> 2, lcol = (tid & 3) * 8;

    for (int k0 = 0; k0 < ND; k0 += 32) {
#pragma unroll
        for (int p = 0; p < 2; p++) {
            const int row = lrow + 64 * p;
            *(uint4*)&Xsh[row * 40 + lcol] = *(const uint4*)&Xh[(size_t)(m0 + row) * ND + k0 + lcol];
            *(uint4*)&Xsl[row * 40 + lcol] = *(const uint4*)&Xl[(size_t)(m0 + row) * ND + k0 + lcol];
            *(uint4*)&Wsh[row * 40 + lcol] = *(const uint4*)&Wh[(size_t)(n0 + row) * ND + k0 + lcol];
            *(uint4*)&Wsl[row * 40 + lcol] = *(const uint4*)&Wl[(size_t)(n0 + row) * ND + k0 + lcol];
        }
        __syncthreads();

        const u32* XH = (const u32*)Xsh;
        const u32* XL = (const u32*)Xsl;
        const u32* WH = (const u32*)Wsh;
        const u32* WL = (const u32*)Wsl;
#pragma unroll
        for (int c = 0; c < 2; c++) {
            u32 aH[2][4], aL[2][4];
#pragma unroll
            for (int mi = 0; mi < 2; mi++) {
                const int r0 = (mw + 16 * mi + g) * 20 + 8 * c + t;
                const int r1 = (mw + 16 * mi + g + 8) * 20 + 8 * c + t;
                aH[mi][0] = XH[r0]; aH[mi][1] = XH[r1];
                aH[mi][2] = XH[r0 + 4]; aH[mi][3] = XH[r1 + 4];
                aL[mi][0] = XL[r0]; aL[mi][1] = XL[r1];
                aL[mi][2] = XL[r0 + 4]; aL[mi][3] = XL[r1 + 4];
            }
#pragma unroll
            for (int nt = 0; nt < 8; nt++) {
                const int nb = (nw + 8 * nt + g) * 20 + 8 * c + t;
                const u32 bh0 = WH[nb], bh1 = WH[nb + 4];
                const u32 bl0 = WL[nb], bl1 = WL[nb + 4];
#pragma unroll
                for (int mi = 0; mi < 2; mi++) {
                    mma_bf16(D[mi][nt], aH[mi], bh0, bh1);
                    mma_bf16(D[mi][nt], aH[mi], bl0, bl1);
                    mma_bf16(D[mi][nt], aL[mi], bh0, bh1);
                }
            }
        }
        __syncthreads();
    }

#pragma unroll
    for (int mi = 0; mi < 2; mi++) {
#pragma unroll
        for (int nt = 0; nt < 8; nt++) {
            const int n = n0 + nw + 8 * nt + 2 * t;
            const float bb0 = bias[n], bb1 = bias[n + 1];
#pragma unroll
            for (int rr = 0; rr < 2; rr++) {
                const int m = m0 + mw + 16 * mi + g + 8 * rr;
                float2 v = make_float2(D[mi][nt][2 * rr + 0] + bb0,
                                       D[mi][nt][2 * rr + 1] + bb1);
                *(float2*)&out[(size_t)m * ND + n] = v;
            }
        }
    }
}

// ---------------------------------------------------------------------------
// Flash attention: 128q x 64k, split-bf16 mma, log2-domain guard-free softmax.
// Stores tile-local probabilities p=ex2(s-mn) to g_S, running max to g_Mt,
// and 1/Z to g_Z.
// ---------------------------------------------------------------------------
__global__ __launch_bounds__(256, 2) void flash_mma() {
    __shared__ __align__(16) bf16 Khs[64 * 72], Kls[64 * 72];
    __shared__ __align__(16) bf16 Vhs[64 * 72], Vls[64 * 72];
    __shared__ float madds[64];

    const int tid = threadIdx.x;
    const int w = tid >> 5, lane = tid & 31, g = lane >> 2, t = lane & 3;
    const int bh = blockIdx.y;
    const int b = bh >> 3, h = bh & 7;
    const int q0 = blockIdx.x * 128;
    const int qw = q0 + 16 * w;

    const bf16* Qhp = g_Qh + (size_t)bh * NS * NDK;
    const bf16* Qlp = g_Ql + (size_t)bh * NS * NDK;
    const bf16* Khp = g_Kh + (size_t)bh * NS * NDK;
    const bf16* Klp = g_Kl + (size_t)bh * NS * NDK;
    const bf16* Vhp = g_Vh + (size_t)bh * NS * NDK;
    const bf16* Vlp = g_Vl + (size_t)bh * NS * NDK;

    float* Srow0 = g_S + ((size_t)(b * NS + qw + g) * NH + h) * NS;
    float* Srow1 = g_S + ((size_t)(b * NS + qw + g + 8) * NH + h) * NS;

    u32 qH[4][4], qL[4][4];
#pragma unroll
    for (int c = 0; c < 4; c++) {
        const size_t r0 = (size_t)(qw + g) * NDK + 16 * c + 2 * t;
        const size_t r1 = (size_t)(qw + g + 8) * NDK + 16 * c + 2 * t;
        qH[c][0] = *(const u32*)&Qhp[r0]; qH[c][1] = *(const u32*)&Qhp[r1];
        qH[c][2] = *(const u32*)&Qhp[r0 + 8]; qH[c][3] = *(const u32*)&Qhp[r1 + 8];
        qL[c][0] = *(const u32*)&Qlp[r0]; qL[c][1] = *(const u32*)&Qlp[r1];
        qL[c][2] = *(const u32*)&Qlp[r0 + 8]; qL[c][3] = *(const u32*)&Qlp[r1 + 8];
    }

    float O[8][4];
#pragma unroll
    for (int dt = 0; dt < 8; dt++)
#pragma unroll
        for (int j = 0; j < 4; j++) O[dt][j] = 0.f;
    float m0r = MINIT, m1r = MINIT, z0 = 0.f, z1 = 0.f;

    const int srow = tid >> 3, sseg = tid & 7;

    for (int kt = 0; kt < NS; kt += 64) {
#pragma unroll
        for (int p = 0; p < 2; p++) {
            const int row = srow + 32 * p;
            const size_t go = (size_t)(kt + row) * NDK + sseg * 8;
            *(uint4*)&Khs[row * 72 + sseg * 8] = *(const uint4*)&Khp[go];
            *(uint4*)&Kls[row * 72 + sseg * 8] = *(const uint4*)&Klp[go];
            uint4 rvh = *(const uint4*)&Vhp[go];
            uint4 rvl = *(const uint4*)&Vlp[go];
            const bf16* th = (const bf16*)&rvh;
            const bf16* tl = (const bf16*)&rvl;
#pragma unroll
            for (int j = 0; j < 8; j++) {
                Vhs[(sseg * 8 + j) * 72 + row] = th[j];
                Vls[(sseg * 8 + j) * 72 + row] = tl[j];
            }
        }
        if (tid < 64) madds[tid] = g_madd[b * NS + kt + tid];
        __syncthreads();

        float S[8][4];
#pragma unroll
        for (int nt = 0; nt < 8; nt++)
#pragma unroll
            for (int j = 0; j < 4; j++) S[nt][j] = 0.f;
        const u32* KH = (const u32*)Khs;
        const u32* KL = (const u32*)Kls;
#pragma unroll
        for (int nt = 0; nt < 8; nt++) {
#pragma unroll
            for (int c = 0; c < 4; c++) {
                const int bi = (8 * nt + g) * 36 + 8 * c + t;
                const u32 bh0 = KH[bi], bh1 = KH[bi + 4];
                const u32 bl0 = KL[bi], bl1 = KL[bi + 4];
                mma_bf16(S[nt], qH[c], bh0, bh1);
                mma_bf16(S[nt], qH[c], bl0, bl1);
                mma_bf16(S[nt], qL[c], bh0, bh1);
            }
        }

        // ---- scale + mask, log2-domain online softmax ----
        float rm0 = MINIT, rm1 = MINIT;
#pragma unroll
        for (int nt = 0; nt < 8; nt++) {
            const float ma = madds[8 * nt + 2 * t], mb = madds[8 * nt + 2 * t + 1];
            S[nt][0] = S[nt][0] * SCL2 + ma; S[nt][1] = S[nt][1] * SCL2 + mb;
            S[nt][2] = S[nt][2] * SCL2 + ma; S[nt][3] = S[nt][3] * SCL2 + mb;
            rm0 = fmaxf(rm0, fmaxf(S[nt][0], S[nt][1]));
            rm1 = fmaxf(rm1, fmaxf(S[nt][2], S[nt][3]));
        }
        rm0 = fmaxf(rm0, __shfl_xor_sync(0xffffffffu, rm0, 1));
        rm0 = fmaxf(rm0, __shfl_xor_sync(0xffffffffu, rm0, 2));
        rm1 = fmaxf(rm1, __shfl_xor_sync(0xffffffffu, rm1, 1));
        rm1 = fmaxf(rm1, __shfl_xor_sync(0xffffffffu, rm1, 2));
        const float mn0 = fmaxf(m0r, rm0), mn1 = fmaxf(m1r, rm1);
        const float al0 = ex2f(m0r - mn0);
        const float al1 = ex2f(m1r - mn1);
        // record running max at this tile (for mean correction factors)
        if (t == 0) {
            const size_t mtb = ((size_t)bh * NTILE + (kt >> 6)) * NS;
            g_Mt[mtb + qw + g] = mn0;
            g_Mt[mtb + qw + g + 8] = mn1;
        }
        float rs0 = 0.f, rs1 = 0.f;
#pragma unroll
        for (int nt = 0; nt < 8; nt++) {
            const float p0 = ex2f(S[nt][0] - mn0);
            const float p1 = ex2f(S[nt][1] - mn0);
            const float p2 = ex2f(S[nt][2] - mn1);
            const float p3 = ex2f(S[nt][3] - mn1);
            S[nt][0] = p0; S[nt][1] = p1; S[nt][2] = p2; S[nt][3] = p3;
            const int col = kt + 8 * nt + 2 * t;
            *(float2*)&Srow0[col] = make_float2(p0, p1);
            *(float2*)&Srow1[col] = make_float2(p2, p3);
            rs0 += p0 + p1; rs1 += p2 + p3;
        }
        rs0 += __shfl_xor_sync(0xffffffffu, rs0, 1);
        rs0 += __shfl_xor_sync(0xffffffffu, rs0, 2);
        rs1 += __shfl_xor_sync(0xffffffffu, rs1, 1);
        rs1 += __shfl_xor_sync(0xffffffffu, rs1, 2);
        z0 = z0 * al0 + rs0; z1 = z1 * al1 + rs1;
        m0r = mn0; m1r = mn1;
#pragma unroll
        for (int dt = 0; dt < 8; dt++) {
            O[dt][0] *= al0; O[dt][1] *= al0;
            O[dt][2] *= al1; O[dt][3] *= al1;
        }

        u32 pH[4][4], pL[4][4];
#pragma unroll
        for (int c = 0; c < 4; c++) {
            const float a0 = S[2 * c][0],     a1 = S[2 * c][1];
            const float a2 = S[2 * c][2],     a3 = S[2 * c][3];
            const float b0 = S[2 * c + 1][0], b1 = S[2 * c + 1][1];
            const float b2 = S[2 * c + 1][2], b3 = S[2 * c + 1][3];
            pH[c][0] = packbf(a0, a1); pH[c][1] = packbf(a2, a3);
            pH[c][2] = packbf(b0, b1); pH[c][3] = packbf(b2, b3);
            pL[c][0] = packbf(a0 - bfround(a0), a1 - bfround(a1));
            pL[c][1] = packbf(a2 - bfround(a2), a3 - bfround(a3));
            pL[c][2] = packbf(b0 - bfround(b0), b1 - bfround(b1));
            pL[c][3] = packbf(b2 - bfround(b2), b3 - bfround(b3));
        }

        const u32* VH = (const u32*)Vhs;
        const u32* VL = (const u32*)Vls;
#pragma unroll
        for (int dt = 0; dt < 8; dt++) {
#pragma unroll
            for (int c = 0; c < 4; c++) {
                const int bi = (8 * dt + g) * 36 + 8 * c + t;
                const u32 vh0 = VH[bi], vh1 = VH[bi + 4];
                const u32 vl0 = VL[bi], vl1 = VL[bi + 4];
                mma_bf16(O[dt], pH[c], vh0, vh1);
                mma_bf16(O[dt], pH[c], vl0, vl1);
                mma_bf16(O[dt], pL[c], vh0, vh1);
            }
        }
        __syncthreads();
    }

    const float inv0 = (z0 > 0.f) ? 1.f / z0 : 0.f;
    const float inv1 = (z1 > 0.f) ? 1.f / z1 : 0.f;
#pragma unroll
    for (int dt = 0; dt < 8; dt++) {
        const int d = 8 * dt + 2 * t;
        const float v0 = O[dt][0] * inv0, v1 = O[dt][1] * inv0;
        const float v2 = O[dt][2] * inv1, v3 = O[dt][3] * inv1;
        const size_t o0 = ((size_t)(b * NS + qw + g)) * ND + h * NDK + d;
        const size_t o1 = ((size_t)(b * NS + qw + g + 8)) * ND + h * NDK + d;
        *(u32*)&g_Ch[o0] = packbf(v0, v1);
        *(u32*)&g_Cl[o0] = packbf(v0 - bfround(v0), v1 - bfround(v1));
        *(u32*)&g_Ch[o1] = packbf(v2, v3);
        *(u32*)&g_Cl[o1] = packbf(v2 - bfround(v2), v3 - bfround(v3));
    }
    if (t == 0) {
        g_M[(size_t)bh * NS + qw + g] = m0r;
        g_M[(size_t)bh * NS + qw + g + 8] = m1r;
        g_Z[(size_t)bh * NS + qw + g] = inv0;   // store 1/Z directly
        g_Z[(size_t)bh * NS + qw + g + 8] = inv1;
    }
}

// ---------------------------------------------------------------------------
// attn.mean: p_final = p_stored * ex2(mn_tile - m_final) * (1/Z).
// One ex2 per (h, tile) per thread; DRAM-bound.
// grid (NS/1024, NS, NB), 256 threads, 4 k per thread (single tile each).
// ---------------------------------------------------------------------------
__global__ __launch_bounds__(256) void mean_ew(float* __restrict__ out) {
    const int b = blockIdx.z;
    const int q = blockIdx.y;
    const int k = (blockIdx.x * blockDim.x + threadIdx.x) * 4;
    const int tile = k >> 6;

    const float* Pbase = g_S + ((size_t)(b * NS + q) * NH) * NS + k;
    float4 acc = make_float4(0.f, 0.f, 0.f, 0.f);
#pragma unroll
    for (int h = 0; h < NH; h++) {
        const size_t bh = (size_t)(b * NH + h);
        const float m = g_M[bh * NS + q];
        const float zi = g_Z[bh * NS + q];
        const float mt = g_Mt[(bh * NTILE + tile) * NS + q];
        const float corr = ex2f(mt - m) * zi;
        float4 p = *(const float4*)&Pbase[(size_t)h * NS];
        acc.x += p.x * corr;
        acc.y += p.y * corr;
        acc.z += p.z * corr;
        acc.w += p.w * corr;
    }
    acc.x *= 0.125f; acc.y *= 0.125f; acc.z *= 0.125f; acc.w *= 0.125f;
    *(float4*)&out[((size_t)(b * NS + q)) * NS + k] = acc;
}

// ---------------------------------------------------------------------------
extern "C" void kernel_launch(void* const* d_in, const int* in_sizes, int n_in,
                              void* d_out, int out_size) {
    const float* qkv[3] = {0, 0, 0};
    const float* Ws[4] = {0, 0, 0, 0};
    const float* bs[4] = {0, 0, 0, 0};
    const void* maskraw = 0;
    int nqkv = 0, nW = 0, nb = 0;
    for (int i = 0; i < n_in; i++) {
        const int sz = in_sizes[i];
        if (sz == NB * NS * ND) { if (nqkv < 3) qkv[nqkv++] = (const float*)d_in[i]; }
        else if (sz == ND * ND) { if (nW < 4) Ws[nW++] = (const float*)d_in[i]; }
        else if (sz == ND)      { if (nb < 4) bs[nb++] = (const float*)d_in[i]; }
        else if (sz == NB * NS) { maskraw = d_in[i]; }
    }
    float* out = (float*)d_out;

    mask_detect<<<1, 256>>>((const unsigned char*)maskraw);                    // 0
    mask_convert<<<(NB * NS + 255) / 256, 256>>>(maskraw);                     // 1

    const int nX = NB * NS * ND;
    const int nWel = ND * ND;
    split_in<<<dim3(nX / 4 / 256, 1, 3), 256>>>(qkv[0], qkv[1], qkv[2]);       // 2
    split_w<<<dim3(nWel / 4 / 256, 1, 4), 256>>>(Ws[0], Ws[1], Ws[2], Ws[3]);  // 3

    proj_qkv<<<dim3(ND / 128, (NB * NS) / 128, 3), 256>>>(bs[0], bs[1], bs[2]); // 4

    flash_mma<<<dim3(NS / 128, NB * NH), 256>>>();                             // 5

    proj_out<<<dim3(ND / 128, (NB * NS) / 128), 256>>>(bs[3], out);            // 6

    const long long need = (long long)NB * NS * ND + (long long)NB * NS * NS;
    if ((long long)out_size >= need) {
        mean_ew<<<dim3(NS / 1024, NS, NB), 256>>>(out + (size_t)NB * NS * ND); // 7
    }
}

// round 11
// speedup vs baseline: 2.2464x; 1.0440x over previous
#include <cuda_runtime.h>
#include <cuda_bf16.h>
#include <cuda_fp16.h>
#include <math.h>

#define NB 4
#define NS 2048
#define ND 512
#define NH 8
#define NDK 64
#define LOG2E 1.4426950408889634f
#define SCL2 (0.125f * LOG2E)
#define MINIT (-1e30f)
#define NTILE (NS / 64)

typedef unsigned int u32;
typedef __nv_bfloat16 bf16;

// ---------------- scratch ----------------
__device__ bf16 g_Ah[(size_t)3 * NB * NS * ND];
__device__ bf16 g_Al[(size_t)3 * NB * NS * ND];
__device__ bf16 g_Wh[(size_t)4 * ND * ND];
__device__ bf16 g_Wl[(size_t)4 * ND * ND];
__device__ bf16 g_Qh[(size_t)NB * NH * NS * NDK];
__device__ bf16 g_Ql[(size_t)NB * NH * NS * NDK];
__device__ bf16 g_Kh[(size_t)NB * NH * NS * NDK];
__device__ bf16 g_Kl[(size_t)NB * NH * NS * NDK];
__device__ bf16 g_Vh[(size_t)NB * NH * NS * NDK];
__device__ bf16 g_Vl[(size_t)NB * NH * NS * NDK];
__device__ bf16 g_Ch[(size_t)NB * NS * ND];
__device__ bf16 g_Cl[(size_t)NB * NS * ND];
__device__ float g_M[(size_t)NB * NH * NS];    // final row max (log2 domain)
__device__ float g_Z[(size_t)NB * NH * NS];    // 1/Z (0 for fully-masked)
__device__ float g_Mt[(size_t)NB * NH * NTILE * NS]; // running max at each tile
__device__ float g_madd[(size_t)NB * NS];      // 0 / -inf
__device__ int   g_maskkind;
// tile-local probabilities ex2(s - mn_tile), fp16x2-packed: [b][q][h][k/2] (268 MB)
__device__ u32 g_S[(size_t)NB * NS * NH * NS / 2];

// ---------------- helpers ----------------
__device__ __forceinline__ float bfround(float x) {
    return __bfloat162float(__float2bfloat16(x));
}
__device__ __forceinline__ u32 packbf(float lo_el, float hi_el) {
    u32 r;
    asm("cvt.rn.bf16x2.f32 %0, %1, %2;" : "=r"(r) : "f"(hi_el), "f"(lo_el));
    return r;
}
__device__ __forceinline__ u32 packhf(float lo_el, float hi_el) {
    u32 r;
    asm("cvt.rn.f16x2.f32 %0, %1, %2;" : "=r"(r) : "f"(hi_el), "f"(lo_el));
    return r;
}
__device__ __forceinline__ float2 h2f2(u32 v) {
    __half2 h = *(__half2*)&v;
    return __half22float2(h);
}
__device__ __forceinline__ float ex2f(float x) {
    float y;
    asm("ex2.approx.f32 %0, %1;" : "=f"(y) : "f"(x));
    return y;   // ex2(-inf) = +0
}
__device__ __forceinline__ void mma_bf16(float d[4], const u32 a[4], u32 b0, u32 b1) {
    asm volatile(
        "mma.sync.aligned.m16n8k16.row.col.f32.bf16.bf16.f32 "
        "{%0,%1,%2,%3}, {%4,%5,%6,%7}, {%8,%9}, {%0,%1,%2,%3};"
        : "+f"(d[0]), "+f"(d[1]), "+f"(d[2]), "+f"(d[3])
        : "r"(a[0]), "r"(a[1]), "r"(a[2]), "r"(a[3]), "r"(b0), "r"(b1));
}

// ---------------- mask sniff / convert (validated R2) ----------------
__global__ void mask_detect(const unsigned char* __restrict__ mraw) {
    __shared__ int s_not01, s_oneOther, s_3fOdd;
    if (threadIdx.x == 0) { s_not01 = 0; s_oneOther = 0; s_3fOdd = 0; }
    __syncthreads();
    int l_not01 = 0, l_oneOther = 0, l_3fOdd = 0;
    for (int i = threadIdx.x; i < NB * NS; i += blockDim.x) {
        const unsigned char v = mraw[i];
        if (v > 1) l_not01++;
        if (v == 1 && (i & 3) != 0) l_oneOther++;
        if (v == 0x3f && (i & 3) == 1) l_3fOdd++;
    }
    atomicAdd(&s_not01, l_not01);
    atomicAdd(&s_oneOther, l_oneOther);
    atomicAdd(&s_3fOdd, l_3fOdd);
    __syncthreads();
    if (threadIdx.x == 0) {
        int kind;
        if (s_not01 > 0)          kind = (s_3fOdd > 0) ? 3 : 2;
        else if (s_oneOther == 0) kind = 1;
        else                      kind = 0;
        g_maskkind = kind;
    }
}

__global__ void mask_convert(const void* __restrict__ mraw) {
    const int i = blockIdx.x * blockDim.x + threadIdx.x;
    if (i >= NB * NS) return;
    const int kind = g_maskkind;
    bool on;
    if (kind == 0)      on = ((const unsigned char*)mraw)[i] != 0;
    else if (kind == 1) on = ((const int*)mraw)[i] != 0;
    else if (kind == 2) on = ((const float*)mraw)[i] != 0.f;
    else                on = ((const unsigned short*)mraw)[i] != 0;
    g_madd[i] = on ? 0.f : -INFINITY;
}

// ---------------- fused, vectorized fp32 -> (hi, lo) bf16 splits ----------------
__global__ void split_in(const float* __restrict__ s0, const float* __restrict__ s1,
                         const float* __restrict__ s2) {
    const int z = blockIdx.z;
    const float* s = (z == 0) ? s0 : (z == 1) ? s1 : s2;
    bf16* h = g_Ah + (size_t)z * NB * NS * ND;
    bf16* l = g_Al + (size_t)z * NB * NS * ND;
    const int i = (blockIdx.x * blockDim.x + threadIdx.x) * 4;
    float4 v = *(const float4*)&s[i];
    uint2 hh, ll;
    hh.x = packbf(v.x, v.y);
    hh.y = packbf(v.z, v.w);
    ll.x = packbf(v.x - bfround(v.x), v.y - bfround(v.y));
    ll.y = packbf(v.z - bfround(v.z), v.w - bfround(v.w));
    *(uint2*)&h[i] = hh;
    *(uint2*)&l[i] = ll;
}

__global__ void split_w(const float* __restrict__ s0, const float* __restrict__ s1,
                        const float* __restrict__ s2, const float* __restrict__ s3) {
    const int z = blockIdx.z;
    const float* s = (z == 0) ? s0 : (z == 1) ? s1 : (z == 2) ? s2 : s3;
    bf16* h = g_Wh + (size_t)z * ND * ND;
    bf16* l = g_Wl + (size_t)z * ND * ND;
    const int i = (blockIdx.x * blockDim.x + threadIdx.x) * 4;
    float4 v = *(const float4*)&s[i];
    uint2 hh, ll;
    hh.x = packbf(v.x, v.y);
    hh.y = packbf(v.z, v.w);
    ll.x = packbf(v.x - bfround(v.x), v.y - bfround(v.y));
    ll.y = packbf(v.z - bfround(v.z), v.w - bfround(v.w));
    *(uint2*)&h[i] = hh;
    *(uint2*)&l[i] = ll;
}

// ---------------------------------------------------------------------------
// QKV projections (split-bf16 mma.sync). grid (ND/128, M/128, 3), 256 thr.
// ---------------------------------------------------------------------------
__global__ __launch_bounds__(256) void proj_qkv(const float* __restrict__ b0p,
                                                const float* __restrict__ b1p,
                                                const float* __restrict__ b2p) {
    __shared__ __align__(16) bf16 Xsh[128 * 40], Xsl[128 * 40];
    __shared__ __align__(16) bf16 Wsh[128 * 40], Wsl[128 * 40];

    const int z = blockIdx.z;
    const bf16* Xh = g_Ah + (size_t)z * NB * NS * ND;
    const bf16* Xl = g_Al + (size_t)z * NB * NS * ND;
    const bf16* Wh = g_Wh + (size_t)z * ND * ND;
    const bf16* Wl = g_Wl + (size_t)z * ND * ND;
    const float* bias = (z == 0) ? b0p : (z == 1) ? b1p : b2p;
    bf16* Yh = (z == 0) ? g_Qh : (z == 1) ? g_Kh : g_Vh;
    bf16* Yl = (z == 0) ? g_Ql : (z == 1) ? g_Kl : g_Vl;

    const int tid = threadIdx.x;
    const int w = tid >> 5, lane = tid & 31, g = lane >> 2, t = lane & 3;
    const int m0 = blockIdx.y * 128, n0 = blockIdx.x * 128;
    const int mw = (w >> 1) * 32, nw = (w & 1) * 64;

    float D[2][8][4];
#pragma unroll
    for (int mi = 0; mi < 2; mi++)
#pragma unroll
        for (int nt = 0; nt < 8; nt++)
#pragma unroll
            for (int j = 0; j < 4; j++) D[mi][nt][j] = 0.f;

    const int lrow = tid >> 2, lcol = (tid & 3) * 8;

    for (int k0 = 0; k0 < ND; k0 += 32) {
#pragma unroll
        for (int p = 0; p < 2; p++) {
            const int row = lrow + 64 * p;
            *(uint4*)&Xsh[row * 40 + lcol] = *(const uint4*)&Xh[(size_t)(m0 + row) * ND + k0 + lcol];
            *(uint4*)&Xsl[row * 40 + lcol] = *(const uint4*)&Xl[(size_t)(m0 + row) * ND + k0 + lcol];
            *(uint4*)&Wsh[row * 40 + lcol] = *(const uint4*)&Wh[(size_t)(n0 + row) * ND + k0 + lcol];
            *(uint4*)&Wsl[row * 40 + lcol] = *(const uint4*)&Wl[(size_t)(n0 + row) * ND + k0 + lcol];
        }
        __syncthreads();

        const u32* XH = (const u32*)Xsh;
        const u32* XL = (const u32*)Xsl;
        const u32* WH = (const u32*)Wsh;
        const u32* WL = (const u32*)Wsl;
#pragma unroll
        for (int c = 0; c < 2; c++) {
            u32 aH[2][4], aL[2][4];
#pragma unroll
            for (int mi = 0; mi < 2; mi++) {
                const int r0 = (mw + 16 * mi + g) * 20 + 8 * c + t;
                const int r1 = (mw + 16 * mi + g + 8) * 20 + 8 * c + t;
                aH[mi][0] = XH[r0]; aH[mi][1] = XH[r1];
                aH[mi][2] = XH[r0 + 4]; aH[mi][3] = XH[r1 + 4];
                aL[mi][0] = XL[r0]; aL[mi][1] = XL[r1];
                aL[mi][2] = XL[r0 + 4]; aL[mi][3] = XL[r1 + 4];
            }
#pragma unroll
            for (int nt = 0; nt < 8; nt++) {
                const int nb = (nw + 8 * nt + g) * 20 + 8 * c + t;
                const u32 bh0 = WH[nb], bh1 = WH[nb + 4];
                const u32 bl0 = WL[nb], bl1 = WL[nb + 4];
#pragma unroll
                for (int mi = 0; mi < 2; mi++) {
                    mma_bf16(D[mi][nt], aH[mi], bh0, bh1);
                    mma_bf16(D[mi][nt], aH[mi], bl0, bl1);
                    mma_bf16(D[mi][nt], aL[mi], bh0, bh1);
                }
            }
        }
        __syncthreads();
    }

#pragma unroll
    for (int mi = 0; mi < 2; mi++) {
#pragma unroll
        for (int nt = 0; nt < 8; nt++) {
            const int n = n0 + nw + 8 * nt + 2 * t;
            const float bb0 = bias[n], bb1 = bias[n + 1];
            const int h = n >> 6, dk = n & 63;
#pragma unroll
            for (int rr = 0; rr < 2; rr++) {
                const int m = m0 + mw + 16 * mi + g + 8 * rr;
                const float v0 = D[mi][nt][2 * rr + 0] + bb0;
                const float v1 = D[mi][nt][2 * rr + 1] + bb1;
                const int b = m >> 11, s = m & (NS - 1);
                const size_t off = (((size_t)(b * NH + h)) * NS + s) * NDK + dk;
                *(u32*)&Yh[off] = packbf(v0, v1);
                *(u32*)&Yl[off] = packbf(v0 - bfround(v0), v1 - bfround(v1));
            }
        }
    }
}

// ---------------------------------------------------------------------------
// Output projection
// ---------------------------------------------------------------------------
__global__ __launch_bounds__(256) void proj_out(const float* __restrict__ bias,
                                                float* __restrict__ out) {
    __shared__ __align__(16) bf16 Xsh[128 * 40], Xsl[128 * 40];
    __shared__ __align__(16) bf16 Wsh[128 * 40], Wsl[128 * 40];

    const bf16* Xh = g_Ch;
    const bf16* Xl = g_Cl;
    const bf16* Wh = g_Wh + (size_t)3 * ND * ND;
    const bf16* Wl = g_Wl + (size_t)3 * ND * ND;

    const int tid = threadIdx.x;
    const int w = tid >> 5, lane = tid & 31, g = lane >> 2, t = lane & 3;
    const int m0 = blockIdx.y * 128, n0 = blockIdx.x * 128;
    const int mw = (w >> 1) * 32, nw = (w & 1) * 64;

    float D[2][8][4];
#pragma unroll
    for (int mi = 0; mi < 2; mi++)
#pragma unroll
        for (int nt = 0; nt < 8; nt++)
#pragma unroll
            for (int j = 0; j < 4; j++) D[mi][nt][j] = 0.f;

    const int lrow = tid >> 2, lcol = (tid & 3) * 8;

    for (int k0 = 0; k0 < ND; k0 += 32) {
#pragma unroll
        for (int p = 0; p < 2; p++) {
            const int row = lrow + 64 * p;
            *(uint4*)&Xsh[row * 40 + lcol] = *(const uint4*)&Xh[(size_t)(m0 + row) * ND + k0 + lcol];
            *(uint4*)&Xsl[row * 40 + lcol] = *(const uint4*)&Xl[(size_t)(m0 + row) * ND + k0 + lcol];
            *(uint4*)&Wsh[row * 40 + lcol] = *(const uint4*)&Wh[(size_t)(n0 + row) * ND + k0 + lcol];
            *(uint4*)&Wsl[row * 40 + lcol] = *(const uint4*)&Wl[(size_t)(n0 + row) * ND + k0 + lcol];
        }
        __syncthreads();

        const u32* XH = (const u32*)Xsh;
        const u32* XL = (const u32*)Xsl;
        const u32* WH = (const u32*)Wsh;
        const u32* WL = (const u32*)Wsl;
#pragma unroll
        for (int c = 0; c < 2; c++) {
            u32 aH[2][4], aL[2][4];
#pragma unroll
            for (int mi = 0; mi < 2; mi++) {
                const int r0 = (mw + 16 * mi + g) * 20 + 8 * c + t;
                const int r1 = (mw + 16 * mi + g + 8) * 20 + 8 * c + t;
                aH[mi][0] = XH[r0]; aH[mi][1] = XH[r1];
                aH[mi][2] = XH[r0 + 4]; aH[mi][3] = XH[r1 + 4];
                aL[mi][0] = XL[r0]; aL[mi][1] = XL[r1];
                aL[mi][2] = XL[r0 + 4]; aL[mi][3] = XL[r1 + 4];
            }
#pragma unroll
            for (int nt = 0; nt < 8; nt++) {
                const int nb = (nw + 8 * nt + g) * 20 + 8 * c + t;
                const u32 bh0 = WH[nb], bh1 = WH[nb + 4];
                const u32 bl0 = WL[nb], bl1 = WL[nb + 4];
#pragma unroll
                for (int mi = 0; mi < 2; mi++) {
                    mma_bf16(D[mi][nt], aH[mi], bh0, bh1);
                    mma_bf16(D[mi][nt], aH[mi], bl0, bl1);
                    mma_bf16(D[mi][nt], aL[mi], bh0, bh1);
                }
            }
        }
        __syncthreads();
    }

#pragma unroll
    for (int mi = 0; mi < 2; mi++) {
#pragma unroll
        for (int nt = 0; nt < 8; nt++) {
            const int n = n0 + nw + 8 * nt + 2 * t;
            const float bb0 = bias[n], bb1 = bias[n + 1];
#pragma unroll
            for (int rr = 0; rr < 2; rr++) {
                const int m = m0 + mw + 16 * mi + g + 8 * rr;
                float2 v = make_float2(D[mi][nt][2 * rr + 0] + bb0,
                                       D[mi][nt][2 * rr + 1] + bb1);
                *(float2*)&out[(size_t)m * ND + n] = v;
            }
        }
    }
}

// ---------------------------------------------------------------------------
// Flash attention: 128q x 64k, split-bf16 mma, log2-domain guard-free softmax.
// Stores tile-local probabilities (fp16x2) to g_S, running max to g_Mt, 1/Z to g_Z.
// ---------------------------------------------------------------------------
__global__ __launch_bounds__(256, 2) void flash_mma() {
    __shared__ __align__(16) bf16 Khs[64 * 72], Kls[64 * 72];
    __shared__ __align__(16) bf16 Vhs[64 * 72], Vls[64 * 72];
    __shared__ float madds[64];

    const int tid = threadIdx.x;
    const int w = tid >> 5, lane = tid & 31, g = lane >> 2, t = lane & 3;
    const int bh = blockIdx.y;
    const int b = bh >> 3, h = bh & 7;
    const int q0 = blockIdx.x * 128;
    const int qw = q0 + 16 * w;

    const bf16* Qhp = g_Qh + (size_t)bh * NS * NDK;
    const bf16* Qlp = g_Ql + (size_t)bh * NS * NDK;
    const bf16* Khp = g_Kh + (size_t)bh * NS * NDK;
    const bf16* Klp = g_Kl + (size_t)bh * NS * NDK;
    const bf16* Vhp = g_Vh + (size_t)bh * NS * NDK;
    const bf16* Vlp = g_Vl + (size_t)bh * NS * NDK;

    u32* Srow0 = g_S + (((size_t)(b * NS + qw + g) * NH + h) * NS >> 1);
    u32* Srow1 = g_S + (((size_t)(b * NS + qw + g + 8) * NH + h) * NS >> 1);

    u32 qH[4][4], qL[4][4];
#pragma unroll
    for (int c = 0; c < 4; c++) {
        const size_t r0 = (size_t)(qw + g) * NDK + 16 * c + 2 * t;
        const size_t r1 = (size_t)(qw + g + 8) * NDK + 16 * c + 2 * t;
        qH[c][0] = *(const u32*)&Qhp[r0]; qH[c][1] = *(const u32*)&Qhp[r1];
        qH[c][2] = *(const u32*)&Qhp[r0 + 8]; qH[c][3] = *(const u32*)&Qhp[r1 + 8];
        qL[c][0] = *(const u32*)&Qlp[r0]; qL[c][1] = *(const u32*)&Qlp[r1];
        qL[c][2] = *(const u32*)&Qlp[r0 + 8]; qL[c][3] = *(const u32*)&Qlp[r1 + 8];
    }

    float O[8][4];
#pragma unroll
    for (int dt = 0; dt < 8; dt++)
#pragma unroll
        for (int j = 0; j < 4; j++) O[dt][j] = 0.f;
    float m0r = MINIT, m1r = MINIT, z0 = 0.f, z1 = 0.f;

    const int srow = tid >> 3, sseg = tid & 7;

    for (int kt = 0; kt < NS; kt += 64) {
#pragma unroll
        for (int p = 0; p < 2; p++) {
            const int row = srow + 32 * p;
            const size_t go = (size_t)(kt + row) * NDK + sseg * 8;
            *(uint4*)&Khs[row * 72 + sseg * 8] = *(const uint4*)&Khp[go];
            *(uint4*)&Kls[row * 72 + sseg * 8] = *(const uint4*)&Klp[go];
            uint4 rvh = *(const uint4*)&Vhp[go];
            uint4 rvl = *(const uint4*)&Vlp[go];
            const bf16* th = (const bf16*)&rvh;
            const bf16* tl = (const bf16*)&rvl;
#pragma unroll
            for (int j = 0; j < 8; j++) {
                Vhs[(sseg * 8 + j) * 72 + row] = th[j];
                Vls[(sseg * 8 + j) * 72 + row] = tl[j];
            }
        }
        if (tid < 64) madds[tid] = g_madd[b * NS + kt + tid];
        __syncthreads();

        float S[8][4];
#pragma unroll
        for (int nt = 0; nt < 8; nt++)
#pragma unroll
            for (int j = 0; j < 4; j++) S[nt][j] = 0.f;
        const u32* KH = (const u32*)Khs;
        const u32* KL = (const u32*)Kls;
#pragma unroll
        for (int nt = 0; nt < 8; nt++) {
#pragma unroll
            for (int c = 0; c < 4; c++) {
                const int bi = (8 * nt + g) * 36 + 8 * c + t;
                const u32 bh0 = KH[bi], bh1 = KH[bi + 4];
                const u32 bl0 = KL[bi], bl1 = KL[bi + 4];
                mma_bf16(S[nt], qH[c], bh0, bh1);
                mma_bf16(S[nt], qH[c], bl0, bl1);
                mma_bf16(S[nt], qL[c], bh0, bh1);
            }
        }

        // ---- scale + mask, log2-domain online softmax ----
        float rm0 = MINIT, rm1 = MINIT;
#pragma unroll
        for (int nt = 0; nt < 8; nt++) {
            const float ma = madds[8 * nt + 2 * t], mb = madds[8 * nt + 2 * t + 1];
            S[nt][0] = S[nt][0] * SCL2 + ma; S[nt][1] = S[nt][1] * SCL2 + mb;
            S[nt][2] = S[nt][2] * SCL2 + ma; S[nt][3] = S[nt][3] * SCL2 + mb;
            rm0 = fmaxf(rm0, fmaxf(S[nt][0], S[nt][1]));
            rm1 = fmaxf(rm1, fmaxf(S[nt][2], S[nt][3]));
        }
        rm0 = fmaxf(rm0, __shfl_xor_sync(0xffffffffu, rm0, 1));
        rm0 = fmaxf(rm0, __shfl_xor_sync(0xffffffffu, rm0, 2));
        rm1 = fmaxf(rm1, __shfl_xor_sync(0xffffffffu, rm1, 1));
        rm1 = fmaxf(rm1, __shfl_xor_sync(0xffffffffu, rm1, 2));
        const float mn0 = fmaxf(m0r, rm0), mn1 = fmaxf(m1r, rm1);
        const float al0 = ex2f(m0r - mn0);
        const float al1 = ex2f(m1r - mn1);
        if (t == 0) {
            const size_t mtb = ((size_t)bh * NTILE + (kt >> 6)) * NS;
            g_Mt[mtb + qw + g] = mn0;
            g_Mt[mtb + qw + g + 8] = mn1;
        }
        float rs0 = 0.f, rs1 = 0.f;
#pragma unroll
        for (int nt = 0; nt < 8; nt++) {
            const float p0 = ex2f(S[nt][0] - mn0);
            const float p1 = ex2f(S[nt][1] - mn0);
            const float p2 = ex2f(S[nt][2] - mn1);
            const float p3 = ex2f(S[nt][3] - mn1);
            S[nt][0] = p0; S[nt][1] = p1; S[nt][2] = p2; S[nt][3] = p3;
            const int col2 = (kt + 8 * nt + 2 * t) >> 1;
            Srow0[col2] = packhf(p0, p1);
            Srow1[col2] = packhf(p2, p3);
            rs0 += p0 + p1; rs1 += p2 + p3;
        }
        rs0 += __shfl_xor_sync(0xffffffffu, rs0, 1);
        rs0 += __shfl_xor_sync(0xffffffffu, rs0, 2);
        rs1 += __shfl_xor_sync(0xffffffffu, rs1, 1);
        rs1 += __shfl_xor_sync(0xffffffffu, rs1, 2);
        z0 = z0 * al0 + rs0; z1 = z1 * al1 + rs1;
        m0r = mn0; m1r = mn1;
#pragma unroll
        for (int dt = 0; dt < 8; dt++) {
            O[dt][0] *= al0; O[dt][1] *= al0;
            O[dt][2] *= al1; O[dt][3] *= al1;
        }

        u32 pH[4][4], pL[4][4];
#pragma unroll
        for (int c = 0; c < 4; c++) {
            const float a0 = S[2 * c][0],     a1 = S[2 * c][1];
            const float a2 = S[2 * c][2],     a3 = S[2 * c][3];
            const float b0 = S[2 * c + 1][0], b1 = S[2 * c + 1][1];
            const float b2 = S[2 * c + 1][2], b3 = S[2 * c + 1][3];
            pH[c][0] = packbf(a0, a1); pH[c][1] = packbf(a2, a3);
            pH[c][2] = packbf(b0, b1); pH[c][3] = packbf(b2, b3);
            pL[c][0] = packbf(a0 - bfround(a0), a1 - bfround(a1));
            pL[c][1] = packbf(a2 - bfround(a2), a3 - bfround(a3));
            pL[c][2] = packbf(b0 - bfround(b0), b1 - bfround(b1));
            pL[c][3] = packbf(b2 - bfround(b2), b3 - bfround(b3));
        }

        const u32* VH = (const u32*)Vhs;
        const u32* VL = (const u32*)Vls;
#pragma unroll
        for (int dt = 0; dt < 8; dt++) {
#pragma unroll
            for (int c = 0; c < 4; c++) {
                const int bi = (8 * dt + g) * 36 + 8 * c + t;
                const u32 vh0 = VH[bi], vh1 = VH[bi + 4];
                const u32 vl0 = VL[bi], vl1 = VL[bi + 4];
                mma_bf16(O[dt], pH[c], vh0, vh1);
                mma_bf16(O[dt], pH[c], vl0, vl1);
                mma_bf16(O[dt], pL[c], vh0, vh1);
            }
        }
        __syncthreads();
    }

    const float inv0 = (z0 > 0.f) ? 1.f / z0 : 0.f;
    const float inv1 = (z1 > 0.f) ? 1.f / z1 : 0.f;
#pragma unroll
    for (int dt = 0; dt < 8; dt++) {
        const int d = 8 * dt + 2 * t;
        const float v0 = O[dt][0] * inv0, v1 = O[dt][1] * inv0;
        const float v2 = O[dt][2] * inv1, v3 = O[dt][3] * inv1;
        const size_t o0 = ((size_t)(b * NS + qw + g)) * ND + h * NDK + d;
        const size_t o1 = ((size_t)(b * NS + qw + g + 8)) * ND + h * NDK + d;
        *(u32*)&g_Ch[o0] = packbf(v0, v1);
        *(u32*)&g_Cl[o0] = packbf(v0 - bfround(v0), v1 - bfround(v1));
        *(u32*)&g_Ch[o1] = packbf(v2, v3);
        *(u32*)&g_Cl[o1] = packbf(v2 - bfround(v2), v3 - bfround(v3));
    }
    if (t == 0) {
        g_M[(size_t)bh * NS + qw + g] = m0r;
        g_M[(size_t)bh * NS + qw + g + 8] = m1r;
        g_Z[(size_t)bh * NS + qw + g] = inv0;
        g_Z[(size_t)bh * NS + qw + g + 8] = inv1;
    }
}

// ---------------------------------------------------------------------------
// attn.mean: out = (1/8) Σ_h p_fp16 * ex2(mn_tile - m_final) * (1/Z).
// 8 k per thread (one uint4 of fp16x2); DRAM-bound.
// grid (1, NS, NB), 256 threads.
// ---------------------------------------------------------------------------
__global__ __launch_bounds__(256) void mean_ew(float* __restrict__ out) {
    const int b = blockIdx.z;
    const int q = blockIdx.y;
    const int k = threadIdx.x * 8;
    const int tile = k >> 6;

    const u32* Pbase = g_S + (((size_t)(b * NS + q) * NH) * NS + k >> 1);
    float acc[8];
#pragma unroll
    for (int j = 0; j < 8; j++) acc[j] = 0.f;

#pragma unroll
    for (int h = 0; h < NH; h++) {
        const size_t bh = (size_t)(b * NH + h);
        const float m = g_M[bh * NS + q];
        const float zi = g_Z[bh * NS + q];
        const float mt = g_Mt[(bh * NTILE + tile) * NS + q];
        const float corr = ex2f(mt - m) * zi;
        uint4 pv = *(const uint4*)&Pbase[(size_t)h * (NS >> 1)];
        float2 p0 = h2f2(pv.x), p1 = h2f2(pv.y), p2 = h2f2(pv.z), p3 = h2f2(pv.w);
        acc[0] += p0.x * corr; acc[1] += p0.y * corr;
        acc[2] += p1.x * corr; acc[3] += p1.y * corr;
        acc[4] += p2.x * corr; acc[5] += p2.y * corr;
        acc[6] += p3.x * corr; acc[7] += p3.y * corr;
    }
    float4 oA = make_float4(acc[0] * 0.125f, acc[1] * 0.125f, acc[2] * 0.125f, acc[3] * 0.125f);
    float4 oB = make_float4(acc[4] * 0.125f, acc[5] * 0.125f, acc[6] * 0.125f, acc[7] * 0.125f);
    float* orow = &out[((size_t)(b * NS + q)) * NS + k];
    *(float4*)&orow[0] = oA;
    *(float4*)&orow[4] = oB;
}

// ---------------------------------------------------------------------------
extern "C" void kernel_launch(void* const* d_in, const int* in_sizes, int n_in,
                              void* d_out, int out_size) {
    const float* qkv[3] = {0, 0, 0};
    const float* Ws[4] = {0, 0, 0, 0};
    const float* bs[4] = {0, 0, 0, 0};
    const void* maskraw = 0;
    int nqkv = 0, nW = 0, nb = 0;
    for (int i = 0; i < n_in; i++) {
        const int sz = in_sizes[i];
        if (sz == NB * NS * ND) { if (nqkv < 3) qkv[nqkv++] = (const float*)d_in[i]; }
        else if (sz == ND * ND) { if (nW < 4) Ws[nW++] = (const float*)d_in[i]; }
        else if (sz == ND)      { if (nb < 4) bs[nb++] = (const float*)d_in[i]; }
        else if (sz == NB * NS) { maskraw = d_in[i]; }
    }
    float* out = (float*)d_out;

    mask_detect<<<1, 256>>>((const unsigned char*)maskraw);                    // 0
    mask_convert<<<(NB * NS + 255) / 256, 256>>>(maskraw);                     // 1

    const int nX = NB * NS * ND;
    const int nWel = ND * ND;
    split_in<<<dim3(nX / 4 / 256, 1, 3), 256>>>(qkv[0], qkv[1], qkv[2]);       // 2
    split_w<<<dim3(nWel / 4 / 256, 1, 4), 256>>>(Ws[0], Ws[1], Ws[2], Ws[3]);  // 3

    proj_qkv<<<dim3(ND / 128, (NB * NS) / 128, 3), 256>>>(bs[0], bs[1], bs[2]); // 4

    flash_mma<<<dim3(NS / 128, NB * NH), 256>>>();                             // 5

    proj_out<<<dim3(ND / 128, (NB * NS) / 128), 256>>>(bs[3], out);            // 6

    const long long need = (long long)NB * NS * ND + (long long)NB * NS * NS;
    if ((long long)out_size >= need) {
        mean_ew<<<dim3(1, NS, NB), 256>>>(out + (size_t)NB * NS * ND);         // 7
    }
}

// round 12
// speedup vs baseline: 2.7587x; 1.2280x over previous
#include <cuda_runtime.h>
#include <cuda_bf16.h>
#include <cuda_fp16.h>
#include <math.h>

#define NB 4
#define NS 2048
#define ND 512
#define NH 8
#define NDK 64
#define LOG2E 1.4426950408889634f
#define SCL2 (0.125f * LOG2E)
#define MINIT (-1e30f)
#define NTILE (NS / 64)

typedef unsigned int u32;
typedef __nv_bfloat16 bf16;

// ---------------- scratch ----------------
__device__ bf16 g_Ah[(size_t)3 * NB * NS * ND];
__device__ bf16 g_Al[(size_t)3 * NB * NS * ND];
__device__ bf16 g_Wh[(size_t)4 * ND * ND];
__device__ bf16 g_Wl[(size_t)4 * ND * ND];
__device__ bf16 g_Qh[(size_t)NB * NH * NS * NDK];
__device__ bf16 g_Ql[(size_t)NB * NH * NS * NDK];
__device__ bf16 g_Kh[(size_t)NB * NH * NS * NDK];
__device__ bf16 g_Kl[(size_t)NB * NH * NS * NDK];
__device__ bf16 g_Vh[(size_t)NB * NH * NS * NDK];
__device__ bf16 g_Vl[(size_t)NB * NH * NS * NDK];
__device__ bf16 g_Ch[(size_t)NB * NS * ND];
__device__ bf16 g_Cl[(size_t)NB * NS * ND];
__device__ float g_M[(size_t)NB * NH * NS];    // final row max (log2 domain)
__device__ float g_Z[(size_t)NB * NH * NS];    // 1/Z (0 for fully-masked)
__device__ float g_Mt[(size_t)NB * NH * NTILE * NS]; // running max at each tile
__device__ float g_madd[(size_t)NB * NS];      // 0 / -inf
__device__ int   g_maskkind;
// tile-local probabilities ex2(s - mn_tile), fp16x2-packed: [b][q][h][k/2] (268 MB)
__device__ u32 g_S[(size_t)NB * NS * NH * NS / 2];

// ---------------- helpers ----------------
__device__ __forceinline__ float bfround(float x) {
    return __bfloat162float(__float2bfloat16(x));
}
__device__ __forceinline__ u32 packbf(float lo_el, float hi_el) {
    u32 r;
    asm("cvt.rn.bf16x2.f32 %0, %1, %2;" : "=r"(r) : "f"(hi_el), "f"(lo_el));
    return r;
}
__device__ __forceinline__ u32 packhf(float lo_el, float hi_el) {
    u32 r;
    asm("cvt.rn.f16x2.f32 %0, %1, %2;" : "=r"(r) : "f"(hi_el), "f"(lo_el));
    return r;
}
__device__ __forceinline__ float2 h2f2(u32 v) {
    __half2 h = *(__half2*)&v;
    return __half22float2(h);
}
__device__ __forceinline__ float ex2f(float x) {
    float y;
    asm("ex2.approx.f32 %0, %1;" : "=f"(y) : "f"(x));
    return y;
}
__device__ __forceinline__ void mma_bf16(float d[4], const u32 a[4], u32 b0, u32 b1) {
    asm volatile(
        "mma.sync.aligned.m16n8k16.row.col.f32.bf16.bf16.f32 "
        "{%0,%1,%2,%3}, {%4,%5,%6,%7}, {%8,%9}, {%0,%1,%2,%3};"
        : "+f"(d[0]), "+f"(d[1]), "+f"(d[2]), "+f"(d[3])
        : "r"(a[0]), "r"(a[1]), "r"(a[2]), "r"(a[3]), "r"(b0), "r"(b1));
}
__device__ __forceinline__ u32 smem_u32p(const void* p) {
    u32 a;
    asm("{ .reg .u64 t; cvta.to.shared.u64 t, %1; cvt.u32.u64 %0, t; }" : "=r"(a) : "l"(p));
    return a;
}
__device__ __forceinline__ void ldsm_x4(u32* r, u32 a) {
    asm volatile("ldmatrix.sync.aligned.m8n8.x4.shared.b16 {%0,%1,%2,%3}, [%4];"
                 : "=r"(r[0]), "=r"(r[1]), "=r"(r[2]), "=r"(r[3]) : "r"(a));
}
__device__ __forceinline__ void ldsm_x4_t(u32* r, u32 a) {
    asm volatile("ldmatrix.sync.aligned.m8n8.x4.trans.shared.b16 {%0,%1,%2,%3}, [%4];"
                 : "=r"(r[0]), "=r"(r[1]), "=r"(r[2]), "=r"(r[3]) : "r"(a));
}

// ---------------- mask sniff / convert (validated R2) ----------------
__global__ void mask_detect(const unsigned char* __restrict__ mraw) {
    __shared__ int s_not01, s_oneOther, s_3fOdd;
    if (threadIdx.x == 0) { s_not01 = 0; s_oneOther = 0; s_3fOdd = 0; }
    __syncthreads();
    int l_not01 = 0, l_oneOther = 0, l_3fOdd = 0;
    for (int i = threadIdx.x; i < NB * NS; i += blockDim.x) {
        const unsigned char v = mraw[i];
        if (v > 1) l_not01++;
        if (v == 1 && (i & 3) != 0) l_oneOther++;
        if (v == 0x3f && (i & 3) == 1) l_3fOdd++;
    }
    atomicAdd(&s_not01, l_not01);
    atomicAdd(&s_oneOther, l_oneOther);
    atomicAdd(&s_3fOdd, l_3fOdd);
    __syncthreads();
    if (threadIdx.x == 0) {
        int kind;
        if (s_not01 > 0)          kind = (s_3fOdd > 0) ? 3 : 2;
        else if (s_oneOther == 0) kind = 1;
        else                      kind = 0;
        g_maskkind = kind;
    }
}

__global__ void mask_convert(const void* __restrict__ mraw) {
    const int i = blockIdx.x * blockDim.x + threadIdx.x;
    if (i >= NB * NS) return;
    const int kind = g_maskkind;
    bool on;
    if (kind == 0)      on = ((const unsigned char*)mraw)[i] != 0;
    else if (kind == 1) on = ((const int*)mraw)[i] != 0;
    else if (kind == 2) on = ((const float*)mraw)[i] != 0.f;
    else                on = ((const unsigned short*)mraw)[i] != 0;
    g_madd[i] = on ? 0.f : -INFINITY;
}

// ---------------- fused, vectorized fp32 -> (hi, lo) bf16 splits ----------------
__global__ void split_in(const float* __restrict__ s0, const float* __restrict__ s1,
                         const float* __restrict__ s2) {
    const int z = blockIdx.z;
    const float* s = (z == 0) ? s0 : (z == 1) ? s1 : s2;
    bf16* h = g_Ah + (size_t)z * NB * NS * ND;
    bf16* l = g_Al + (size_t)z * NB * NS * ND;
    const int i = (blockIdx.x * blockDim.x + threadIdx.x) * 4;
    float4 v = *(const float4*)&s[i];
    uint2 hh, ll;
    hh.x = packbf(v.x, v.y);
    hh.y = packbf(v.z, v.w);
    ll.x = packbf(v.x - bfround(v.x), v.y - bfround(v.y));
    ll.y = packbf(v.z - bfround(v.z), v.w - bfround(v.w));
    *(uint2*)&h[i] = hh;
    *(uint2*)&l[i] = ll;
}

__global__ void split_w(const float* __restrict__ s0, const float* __restrict__ s1,
                        const float* __restrict__ s2, const float* __restrict__ s3) {
    const int z = blockIdx.z;
    const float* s = (z == 0) ? s0 : (z == 1) ? s1 : (z == 2) ? s2 : s3;
    bf16* h = g_Wh + (size_t)z * ND * ND;
    bf16* l = g_Wl + (size_t)z * ND * ND;
    const int i = (blockIdx.x * blockDim.x + threadIdx.x) * 4;
    float4 v = *(const float4*)&s[i];
    uint2 hh, ll;
    hh.x = packbf(v.x, v.y);
    hh.y = packbf(v.z, v.w);
    ll.x = packbf(v.x - bfround(v.x), v.y - bfround(v.y));
    ll.y = packbf(v.z - bfround(v.z), v.w - bfround(v.w));
    *(uint2*)&h[i] = hh;
    *(uint2*)&l[i] = ll;
}

// ---------------------------------------------------------------------------
// QKV projections (split-bf16 mma.sync). grid (ND/128, M/128, 3), 256 thr.
// ---------------------------------------------------------------------------
__global__ __launch_bounds__(256) void proj_qkv(const float* __restrict__ b0p,
                                                const float* __restrict__ b1p,
                                                const float* __restrict__ b2p) {
    __shared__ __align__(16) bf16 Xsh[128 * 40], Xsl[128 * 40];
    __shared__ __align__(16) bf16 Wsh[128 * 40], Wsl[128 * 40];

    const int z = blockIdx.z;
    const bf16* Xh = g_Ah + (size_t)z * NB * NS * ND;
    const bf16* Xl = g_Al + (size_t)z * NB * NS * ND;
    const bf16* Wh = g_Wh + (size_t)z * ND * ND;
    const bf16* Wl = g_Wl + (size_t)z * ND * ND;
    const float* bias = (z == 0) ? b0p : (z == 1) ? b1p : b2p;
    bf16* Yh = (z == 0) ? g_Qh : (z == 1) ? g_Kh : g_Vh;
    bf16* Yl = (z == 0) ? g_Ql : (z == 1) ? g_Kl : g_Vl;

    const int tid = threadIdx.x;
    const int w = tid >> 5, lane = tid & 31, g = lane >> 2, t = lane & 3;
    const int m0 = blockIdx.y * 128, n0 = blockIdx.x * 128;
    const int mw = (w >> 1) * 32, nw = (w & 1) * 64;

    float D[2][8][4];
#pragma unroll
    for (int mi = 0; mi < 2; mi++)
#pragma unroll
        for (int nt = 0; nt < 8; nt++)
#pragma unroll
            for (int j = 0; j < 4; j++) D[mi][nt][j] = 0.f;

    const int lrow = tid >> 2, lcol = (tid & 3) * 8;

    for (int k0 = 0; k0 < ND; k0 += 32) {
#pragma unroll
        for (int p = 0; p < 2; p++) {
            const int row = lrow + 64 * p;
            *(uint4*)&Xsh[row * 40 + lcol] = *(const uint4*)&Xh[(size_t)(m0 + row) * ND + k0 + lcol];
            *(uint4*)&Xsl[row * 40 + lcol] = *(const uint4*)&Xl[(size_t)(m0 + row) * ND + k0 + lcol];
            *(uint4*)&Wsh[row * 40 + lcol] = *(const uint4*)&Wh[(size_t)(n0 + row) * ND + k0 + lcol];
            *(uint4*)&Wsl[row * 40 + lcol] = *(const uint4*)&Wl[(size_t)(n0 + row) * ND + k0 + lcol];
        }
        __syncthreads();

        const u32* XH = (const u32*)Xsh;
        const u32* XL = (const u32*)Xsl;
        const u32* WH = (const u32*)Wsh;
        const u32* WL = (const u32*)Wsl;
#pragma unroll
        for (int c = 0; c < 2; c++) {
            u32 aH[2][4], aL[2][4];
#pragma unroll
            for (int mi = 0; mi < 2; mi++) {
                const int r0 = (mw + 16 * mi + g) * 20 + 8 * c + t;
                const int r1 = (mw + 16 * mi + g + 8) * 20 + 8 * c + t;
                aH[mi][0] = XH[r0]; aH[mi][1] = XH[r1];
                aH[mi][2] = XH[r0 + 4]; aH[mi][3] = XH[r1 + 4];
                aL[mi][0] = XL[r0]; aL[mi][1] = XL[r1];
                aL[mi][2] = XL[r0 + 4]; aL[mi][3] = XL[r1 + 4];
            }
#pragma unroll
            for (int nt = 0; nt < 8; nt++) {
                const int nb = (nw + 8 * nt + g) * 20 + 8 * c + t;
                const u32 bh0 = WH[nb], bh1 = WH[nb + 4];
                const u32 bl0 = WL[nb], bl1 = WL[nb + 4];
#pragma unroll
                for (int mi = 0; mi < 2; mi++) {
                    mma_bf16(D[mi][nt], aH[mi], bh0, bh1);
                    mma_bf16(D[mi][nt], aH[mi], bl0, bl1);
                    mma_bf16(D[mi][nt], aL[mi], bh0, bh1);
                }
            }
        }
        __syncthreads();
    }

#pragma unroll
    for (int mi = 0; mi < 2; mi++) {
#pragma unroll
        for (int nt = 0; nt < 8; nt++) {
            const int n = n0 + nw + 8 * nt + 2 * t;
            const float bb0 = bias[n], bb1 = bias[n + 1];
            const int h = n >> 6, dk = n & 63;
#pragma unroll
            for (int rr = 0; rr < 2; rr++) {
                const int m = m0 + mw + 16 * mi + g + 8 * rr;
                const float v0 = D[mi][nt][2 * rr + 0] + bb0;
                const float v1 = D[mi][nt][2 * rr + 1] + bb1;
                const int b = m >> 11, s = m & (NS - 1);
                const size_t off = (((size_t)(b * NH + h)) * NS + s) * NDK + dk;
                *(u32*)&Yh[off] = packbf(v0, v1);
                *(u32*)&Yl[off] = packbf(v0 - bfround(v0), v1 - bfround(v1));
            }
        }
    }
}

// ---------------------------------------------------------------------------
// Output projection
// ---------------------------------------------------------------------------
__global__ __launch_bounds__(256) void proj_out(const float* __restrict__ bias,
                                                float* __restrict__ out) {
    __shared__ __align__(16) bf16 Xsh[128 * 40], Xsl[128 * 40];
    __shared__ __align__(16) bf16 Wsh[128 * 40], Wsl[128 * 40];

    const bf16* Xh = g_Ch;
    const bf16* Xl = g_Cl;
    const bf16* Wh = g_Wh + (size_t)3 * ND * ND;
    const bf16* Wl = g_Wl + (size_t)3 * ND * ND;

    const int tid = threadIdx.x;
    const int w = tid >> 5, lane = tid & 31, g = lane >> 2, t = lane & 3;
    const int m0 = blockIdx.y * 128, n0 = blockIdx.x * 128;
    const int mw = (w >> 1) * 32, nw = (w & 1) * 64;

    float D[2][8][4];
#pragma unroll
    for (int mi = 0; mi < 2; mi++)
#pragma unroll
        for (int nt = 0; nt < 8; nt++)
#pragma unroll
            for (int j = 0; j < 4; j++) D[mi][nt][j] = 0.f;

    const int lrow = tid >> 2, lcol = (tid & 3) * 8;

    for (int k0 = 0; k0 < ND; k0 += 32) {
#pragma unroll
        for (int p = 0; p < 2; p++) {
            const int row = lrow + 64 * p;
            *(uint4*)&Xsh[row * 40 + lcol] = *(const uint4*)&Xh[(size_t)(m0 + row) * ND + k0 + lcol];
            *(uint4*)&Xsl[row * 40 + lcol] = *(const uint4*)&Xl[(size_t)(m0 + row) * ND + k0 + lcol];
            *(uint4*)&Wsh[row * 40 + lcol] = *(const uint4*)&Wh[(size_t)(n0 + row) * ND + k0 + lcol];
            *(uint4*)&Wsl[row * 40 + lcol] = *(const uint4*)&Wl[(size_t)(n0 + row) * ND + k0 + lcol];
        }
        __syncthreads();

        const u32* XH = (const u32*)Xsh;
        const u32* XL = (const u32*)Xsl;
        const u32* WH = (const u32*)Wsh;
        const u32* WL = (const u32*)Wsl;
#pragma unroll
        for (int c = 0; c < 2; c++) {
            u32 aH[2][4], aL[2][4];
#pragma unroll
            for (int mi = 0; mi < 2; mi++) {
                const int r0 = (mw + 16 * mi + g) * 20 + 8 * c + t;
                const int r1 = (mw + 16 * mi + g + 8) * 20 + 8 * c + t;
                aH[mi][0] = XH[r0]; aH[mi][1] = XH[r1];
                aH[mi][2] = XH[r0 + 4]; aH[mi][3] = XH[r1 + 4];
                aL[mi][0] = XL[r0]; aL[mi][1] = XL[r1];
                aL[mi][2] = XL[r0 + 4]; aL[mi][3] = XL[r1 + 4];
            }
#pragma unroll
            for (int nt = 0; nt < 8; nt++) {
                const int nb = (nw + 8 * nt + g) * 20 + 8 * c + t;
                const u32 bh0 = WH[nb], bh1 = WH[nb + 4];
                const u32 bl0 = WL[nb], bl1 = WL[nb + 4];
#pragma unroll
                for (int mi = 0; mi < 2; mi++) {
                    mma_bf16(D[mi][nt], aH[mi], bh0, bh1);
                    mma_bf16(D[mi][nt], aH[mi], bl0, bl1);
                    mma_bf16(D[mi][nt], aL[mi], bh0, bh1);
                }
            }
        }
        __syncthreads();
    }

#pragma unroll
    for (int mi = 0; mi < 2; mi++) {
#pragma unroll
        for (int nt = 0; nt < 8; nt++) {
            const int n = n0 + nw + 8 * nt + 2 * t;
            const float bb0 = bias[n], bb1 = bias[n + 1];
#pragma unroll
            for (int rr = 0; rr < 2; rr++) {
                const int m = m0 + mw + 16 * mi + g + 8 * rr;
                float2 v = make_float2(D[mi][nt][2 * rr + 0] + bb0,
                                       D[mi][nt][2 * rr + 1] + bb1);
                *(float2*)&out[(size_t)m * ND + n] = v;
            }
        }
    }
}

// ---------------------------------------------------------------------------
// Flash attention: 128q x 64k, split-bf16 mma, log2-domain guard-free softmax.
// K and V both staged NATURAL [k][72]; fragments loaded via ldmatrix
// (non-trans for K, .trans for V — eliminates the bank-conflicted transpose).
// ---------------------------------------------------------------------------
__global__ __launch_bounds__(256, 2) void flash_mma() {
    __shared__ __align__(16) bf16 Khs[64 * 72], Kls[64 * 72];
    __shared__ __align__(16) bf16 Vhs[64 * 72], Vls[64 * 72];
    __shared__ float madds[64];

    const int tid = threadIdx.x;
    const int w = tid >> 5, lane = tid & 31, g = lane >> 2, t = lane & 3;
    const int bh = blockIdx.y;
    const int b = bh >> 3, h = bh & 7;
    const int q0 = blockIdx.x * 128;
    const int qw = q0 + 16 * w;

    const bf16* Qhp = g_Qh + (size_t)bh * NS * NDK;
    const bf16* Qlp = g_Ql + (size_t)bh * NS * NDK;
    const bf16* Khp = g_Kh + (size_t)bh * NS * NDK;
    const bf16* Klp = g_Kl + (size_t)bh * NS * NDK;
    const bf16* Vhp = g_Vh + (size_t)bh * NS * NDK;
    const bf16* Vlp = g_Vl + (size_t)bh * NS * NDK;

    u32* Srow0 = g_S + (((size_t)(b * NS + qw + g) * NH + h) * NS >> 1);
    u32* Srow1 = g_S + (((size_t)(b * NS + qw + g + 8) * NH + h) * NS >> 1);

    // ldmatrix per-lane byte offsets (row stride = 72 bf16 = 144 B)
    // K (non-trans): lane l -> row (l&7), col 8*(l>>3) bf16
    const u32 kb_h = smem_u32p(Khs), kb_l = smem_u32p(Kls);
    const u32 vb_h = smem_u32p(Vhs), vb_l = smem_u32p(Vls);
    const u32 aoffK = ((lane & 7) * 72 + 8 * (lane >> 3)) * 2;
    // V (.trans): lane l -> row (l&7) + 8*((l>>3)&1), col 8*(l>>4) bf16
    const u32 aoffV = (((lane & 7) + 8 * ((lane >> 3) & 1)) * 72 + 8 * (lane >> 4)) * 2;

    u32 qH[4][4], qL[4][4];
#pragma unroll
    for (int c = 0; c < 4; c++) {
        const size_t r0 = (size_t)(qw + g) * NDK + 16 * c + 2 * t;
        const size_t r1 = (size_t)(qw + g + 8) * NDK + 16 * c + 2 * t;
        qH[c][0] = *(const u32*)&Qhp[r0]; qH[c][1] = *(const u32*)&Qhp[r1];
        qH[c][2] = *(const u32*)&Qhp[r0 + 8]; qH[c][3] = *(const u32*)&Qhp[r1 + 8];
        qL[c][0] = *(const u32*)&Qlp[r0]; qL[c][1] = *(const u32*)&Qlp[r1];
        qL[c][2] = *(const u32*)&Qlp[r0 + 8]; qL[c][3] = *(const u32*)&Qlp[r1 + 8];
    }

    float O[8][4];
#pragma unroll
    for (int dt = 0; dt < 8; dt++)
#pragma unroll
        for (int j = 0; j < 4; j++) O[dt][j] = 0.f;
    float m0r = MINIT, m1r = MINIT, z0 = 0.f, z1 = 0.f;

    const int srow = tid >> 3, sseg = tid & 7;

    for (int kt = 0; kt < NS; kt += 64) {
        // ---- stage K and V natural [k][72] (vectorized, conflict-free) ----
#pragma unroll
        for (int p = 0; p < 2; p++) {
            const int row = srow + 32 * p;
            const size_t go = (size_t)(kt + row) * NDK + sseg * 8;
            *(uint4*)&Khs[row * 72 + sseg * 8] = *(const uint4*)&Khp[go];
            *(uint4*)&Kls[row * 72 + sseg * 8] = *(const uint4*)&Klp[go];
            *(uint4*)&Vhs[row * 72 + sseg * 8] = *(const uint4*)&Vhp[go];
            *(uint4*)&Vls[row * 72 + sseg * 8] = *(const uint4*)&Vlp[go];
        }
        if (tid < 64) madds[tid] = g_madd[b * NS + kt + tid];
        __syncthreads();

        // ---- S = Q K^T (K fragments via ldmatrix.x4) ----
        float S[8][4];
#pragma unroll
        for (int nt = 0; nt < 8; nt++)
#pragma unroll
            for (int j = 0; j < 4; j++) S[nt][j] = 0.f;
#pragma unroll
        for (int nt = 0; nt < 8; nt++) {
#pragma unroll
            for (int cc = 0; cc < 2; cc++) {
                const u32 off = aoffK + (u32)(8 * nt * 72 + 32 * cc) * 2;
                u32 fH[4], fL[4];
                ldsm_x4(fH, kb_h + off);
                ldsm_x4(fL, kb_l + off);
                mma_bf16(S[nt], qH[2 * cc],     fH[0], fH[1]);
                mma_bf16(S[nt], qH[2 * cc],     fL[0], fL[1]);
                mma_bf16(S[nt], qL[2 * cc],     fH[0], fH[1]);
                mma_bf16(S[nt], qH[2 * cc + 1], fH[2], fH[3]);
                mma_bf16(S[nt], qH[2 * cc + 1], fL[2], fL[3]);
                mma_bf16(S[nt], qL[2 * cc + 1], fH[2], fH[3]);
            }
        }

        // ---- scale + mask, log2-domain online softmax ----
        float rm0 = MINIT, rm1 = MINIT;
#pragma unroll
        for (int nt = 0; nt < 8; nt++) {
            const float ma = madds[8 * nt + 2 * t], mb = madds[8 * nt + 2 * t + 1];
            S[nt][0] = S[nt][0] * SCL2 + ma; S[nt][1] = S[nt][1] * SCL2 + mb;
            S[nt][2] = S[nt][2] * SCL2 + ma; S[nt][3] = S[nt][3] * SCL2 + mb;
            rm0 = fmaxf(rm0, fmaxf(S[nt][0], S[nt][1]));
            rm1 = fmaxf(rm1, fmaxf(S[nt][2], S[nt][3]));
        }
        rm0 = fmaxf(rm0, __shfl_xor_sync(0xffffffffu, rm0, 1));
        rm0 = fmaxf(rm0, __shfl_xor_sync(0xffffffffu, rm0, 2));
        rm1 = fmaxf(rm1, __shfl_xor_sync(0xffffffffu, rm1, 1));
        rm1 = fmaxf(rm1, __shfl_xor_sync(0xffffffffu, rm1, 2));
        const float mn0 = fmaxf(m0r, rm0), mn1 = fmaxf(m1r, rm1);
        const float al0 = ex2f(m0r - mn0);
        const float al1 = ex2f(m1r - mn1);
        if (t == 0) {
            const size_t mtb = ((size_t)bh * NTILE + (kt >> 6)) * NS;
            g_Mt[mtb + qw + g] = mn0;
            g_Mt[mtb + qw + g + 8] = mn1;
        }
        float rs0 = 0.f, rs1 = 0.f;
#pragma unroll
        for (int nt = 0; nt < 8; nt++) {
            const float p0 = ex2f(S[nt][0] - mn0);
            const float p1 = ex2f(S[nt][1] - mn0);
            const float p2 = ex2f(S[nt][2] - mn1);
            const float p3 = ex2f(S[nt][3] - mn1);
            S[nt][0] = p0; S[nt][1] = p1; S[nt][2] = p2; S[nt][3] = p3;
            const int col2 = (kt + 8 * nt + 2 * t) >> 1;
            Srow0[col2] = packhf(p0, p1);
            Srow1[col2] = packhf(p2, p3);
            rs0 += p0 + p1; rs1 += p2 + p3;
        }
        rs0 += __shfl_xor_sync(0xffffffffu, rs0, 1);
        rs0 += __shfl_xor_sync(0xffffffffu, rs0, 2);
        rs1 += __shfl_xor_sync(0xffffffffu, rs1, 1);
        rs1 += __shfl_xor_sync(0xffffffffu, rs1, 2);
        z0 = z0 * al0 + rs0; z1 = z1 * al1 + rs1;
        m0r = mn0; m1r = mn1;
#pragma unroll
        for (int dt = 0; dt < 8; dt++) {
            O[dt][0] *= al0; O[dt][1] *= al0;
            O[dt][2] *= al1; O[dt][3] *= al1;
        }

        u32 pH[4][4], pL[4][4];
#pragma unroll
        for (int c = 0; c < 4; c++) {
            const float a0 = S[2 * c][0],     a1 = S[2 * c][1];
            const float a2 = S[2 * c][2],     a3 = S[2 * c][3];
            const float b0 = S[2 * c + 1][0], b1 = S[2 * c + 1][1];
            const float b2 = S[2 * c + 1][2], b3 = S[2 * c + 1][3];
            pH[c][0] = packbf(a0, a1); pH[c][1] = packbf(a2, a3);
            pH[c][2] = packbf(b0, b1); pH[c][3] = packbf(b2, b3);
            pL[c][0] = packbf(a0 - bfround(a0), a1 - bfround(a1));
            pL[c][1] = packbf(a2 - bfround(a2), a3 - bfround(a3));
            pL[c][2] = packbf(b0 - bfround(b0), b1 - bfround(b1));
            pL[c][3] = packbf(b2 - bfround(b2), b3 - bfround(b3));
        }

        // ---- O += P V (V fragments via ldmatrix.x4.trans) ----
#pragma unroll
        for (int c = 0; c < 4; c++) {
#pragma unroll
            for (int dd = 0; dd < 4; dd++) {
                const u32 off = aoffV + (u32)(16 * c * 72 + 16 * dd) * 2;
                u32 vH[4], vL[4];
                ldsm_x4_t(vH, vb_h + off);
                ldsm_x4_t(vL, vb_l + off);
                mma_bf16(O[2 * dd],     pH[c], vH[0], vH[1]);
                mma_bf16(O[2 * dd],     pH[c], vL[0], vL[1]);
                mma_bf16(O[2 * dd],     pL[c], vH[0], vH[1]);
                mma_bf16(O[2 * dd + 1], pH[c], vH[2], vH[3]);
                mma_bf16(O[2 * dd + 1], pH[c], vL[2], vL[3]);
                mma_bf16(O[2 * dd + 1], pL[c], vH[2], vH[3]);
            }
        }
        __syncthreads();
    }

    const float inv0 = (z0 > 0.f) ? 1.f / z0 : 0.f;
    const float inv1 = (z1 > 0.f) ? 1.f / z1 : 0.f;
#pragma unroll
    for (int dt = 0; dt < 8; dt++) {
        const int d = 8 * dt + 2 * t;
        const float v0 = O[dt][0] * inv0, v1 = O[dt][1] * inv0;
        const float v2 = O[dt][2] * inv1, v3 = O[dt][3] * inv1;
        const size_t o0 = ((size_t)(b * NS + qw + g)) * ND + h * NDK + d;
        const size_t o1 = ((size_t)(b * NS + qw + g + 8)) * ND + h * NDK + d;
        *(u32*)&g_Ch[o0] = packbf(v0, v1);
        *(u32*)&g_Cl[o0] = packbf(v0 - bfround(v0), v1 - bfround(v1));
        *(u32*)&g_Ch[o1] = packbf(v2, v3);
        *(u32*)&g_Cl[o1] = packbf(v2 - bfround(v2), v3 - bfround(v3));
    }
    if (t == 0) {
        g_M[(size_t)bh * NS + qw + g] = m0r;
        g_M[(size_t)bh * NS + qw + g + 8] = m1r;
        g_Z[(size_t)bh * NS + qw + g] = inv0;
        g_Z[(size_t)bh * NS + qw + g + 8] = inv1;
    }
}

// ---------------------------------------------------------------------------
// attn.mean: out = (1/8) Σ_h p_fp16 * ex2(mn_tile - m_final) * (1/Z).
// ---------------------------------------------------------------------------
__global__ __launch_bounds__(256) void mean_ew(float* __restrict__ out) {
    const int b = blockIdx.z;
    const int q = blockIdx.y;
    const int k = threadIdx.x * 8;
    const int tile = k >> 6;

    const u32* Pbase = g_S + (((size_t)(b * NS + q) * NH) * NS + k >> 1);
    float acc[8];
#pragma unroll
    for (int j = 0; j < 8; j++) acc[j] = 0.f;

#pragma unroll
    for (int h = 0; h < NH; h++) {
        const size_t bh = (size_t)(b * NH + h);
        const float m = g_M[bh * NS + q];
        const float zi = g_Z[bh * NS + q];
        const float mt = g_Mt[(bh * NTILE + tile) * NS + q];
        const float corr = ex2f(mt - m) * zi;
        uint4 pv = *(const uint4*)&Pbase[(size_t)h * (NS >> 1)];
        float2 p0 = h2f2(pv.x), p1 = h2f2(pv.y), p2 = h2f2(pv.z), p3 = h2f2(pv.w);
        acc[0] += p0.x * corr; acc[1] += p0.y * corr;
        acc[2] += p1.x * corr; acc[3] += p1.y * corr;
        acc[4] += p2.x * corr; acc[5] += p2.y * corr;
        acc[6] += p3.x * corr; acc[7] += p3.y * corr;
    }
    float4 oA = make_float4(acc[0] * 0.125f, acc[1] * 0.125f, acc[2] * 0.125f, acc[3] * 0.125f);
    float4 oB = make_float4(acc[4] * 0.125f, acc[5] * 0.125f, acc[6] * 0.125f, acc[7] * 0.125f);
    float* orow = &out[((size_t)(b * NS + q)) * NS + k];
    *(float4*)&orow[0] = oA;
    *(float4*)&orow[4] = oB;
}

// ---------------------------------------------------------------------------
extern "C" void kernel_launch(void* const* d_in, const int* in_sizes, int n_in,
                              void* d_out, int out_size) {
    const float* qkv[3] = {0, 0, 0};
    const float* Ws[4] = {0, 0, 0, 0};
    const float* bs[4] = {0, 0, 0, 0};
    const void* maskraw = 0;
    int nqkv = 0, nW = 0, nb = 0;
    for (int i = 0; i < n_in; i++) {
        const int sz = in_sizes[i];
        if (sz == NB * NS * ND) { if (nqkv < 3) qkv[nqkv++] = (const float*)d_in[i]; }
        else if (sz == ND * ND) { if (nW < 4) Ws[nW++] = (const float*)d_in[i]; }
        else if (sz == ND)      { if (nb < 4) bs[nb++] = (const float*)d_in[i]; }
        else if (sz == NB * NS) { maskraw = d_in[i]; }
    }
    float* out = (float*)d_out;

    mask_detect<<<1, 256>>>((const unsigned char*)maskraw);                    // 0
    mask_convert<<<(NB * NS + 255) / 256, 256>>>(maskraw);                     // 1

    const int nX = NB * NS * ND;
    const int nWel = ND * ND;
    split_in<<<dim3(nX / 4 / 256, 1, 3), 256>>>(qkv[0], qkv[1], qkv[2]);       // 2
    split_w<<<dim3(nWel / 4 / 256, 1, 4), 256>>>(Ws[0], Ws[1], Ws[2], Ws[3]);  // 3

    proj_qkv<<<dim3(ND / 128, (NB * NS) / 128, 3), 256>>>(bs[0], bs[1], bs[2]); // 4

    flash_mma<<<dim3(NS / 128, NB * NH), 256>>>();                             // 5

    proj_out<<<dim3(ND / 128, (NB * NS) / 128), 256>>>(bs[3], out);            // 6

    const long long need = (long long)NB * NS * ND + (long long)NB * NS * NS;
    if ((long long)out_size >= need) {
        mean_ew<<<dim3(1, NS, NB), 256>>>(out + (size_t)NB * NS * ND);         // 7
    }
}